// round 7
// baseline (speedup 1.0000x reference)
#include <cuda_runtime.h>
#include <cuda_fp16.h>
#include <cstdint>
#include <math.h>

#define S_DIM 256
#define I_DIM 256
#define CS    256
#define NH    8
#define HD    32
#define M_ROWS 65536
#define MBLOCKS 512
#define QSCALE 0.2550349f   /* log2(e) / sqrt(32) */

// ---------------------------------------------------------------------------
// Scratch (device globals). A-operands plain fp16; B-operands split hi/lo.
// ---------------------------------------------------------------------------
__device__ __align__(16) __half g_x   [M_ROWS * CS];
__device__ __align__(16) __half g_gv  [M_ROWS * CS];
__device__ __align__(16) __half g_q   [M_ROWS * CS];
__device__ __align__(16) __half g_k_hi[M_ROWS * CS];
__device__ __align__(16) __half g_k_lo[M_ROWS * CS];
__device__ __align__(16) __half g_v_hi[M_ROWS * CS];
__device__ __align__(16) __half g_v_lo[M_ROWS * CS];
__device__ __align__(16) __half g_wt_hi[5 * CS * CS];   // [w][k][n]
__device__ __align__(16) __half g_wt_lo[5 * CS * CS];
__device__ float g_g[M_ROWS * CS];

// ---------------------------------------------------------------------------
// Helpers
// ---------------------------------------------------------------------------
__device__ __forceinline__ uint32_t smem_u32(const void* p) {
    uint32_t a;
    asm("{ .reg .u64 t; cvta.to.shared.u64 t, %1; cvt.u32.u64 %0, t; }" : "=r"(a) : "l"(p));
    return a;
}
__device__ __forceinline__ void cpa16(uint32_t dst, const void* src) {
    asm volatile("{ .reg .u64 g; cvta.to.global.u64 g, %1;"
                 "  cp.async.cg.shared.global [%0], [g], 16; }"
                 :: "r"(dst), "l"(src) : "memory");
}
__device__ __forceinline__ void cpa_commit() {
    asm volatile("cp.async.commit_group;" ::: "memory");
}
template <int N>
__device__ __forceinline__ void cpa_wait() {
    asm volatile("cp.async.wait_group %0;" :: "n"(N) : "memory");
}
__device__ __forceinline__ void ldsm4(uint32_t* r, uint32_t addr) {
    asm volatile("ldmatrix.sync.aligned.m8n8.x4.shared.b16 {%0,%1,%2,%3}, [%4];"
                 : "=r"(r[0]), "=r"(r[1]), "=r"(r[2]), "=r"(r[3]) : "r"(addr));
}
__device__ __forceinline__ void ldsm4t(uint32_t* r, uint32_t addr) {
    asm volatile("ldmatrix.sync.aligned.m8n8.x4.trans.shared.b16 {%0,%1,%2,%3}, [%4];"
                 : "=r"(r[0]), "=r"(r[1]), "=r"(r[2]), "=r"(r[3]) : "r"(addr));
}
__device__ __forceinline__ void mma_f16(float* c, const uint32_t* a, const uint32_t* b) {
    asm volatile("mma.sync.aligned.m16n8k16.row.col.f32.f16.f16.f32 "
                 "{%0,%1,%2,%3}, {%4,%5,%6,%7}, {%8,%9}, {%0,%1,%2,%3};"
                 : "+f"(c[0]), "+f"(c[1]), "+f"(c[2]), "+f"(c[3])
                 : "r"(a[0]), "r"(a[1]), "r"(a[2]), "r"(a[3]), "r"(b[0]), "r"(b[1]));
}
__device__ __forceinline__ uint32_t h2pack(float a, float b) {
    __half2 t = __floats2half2_rn(a, b);
    return *reinterpret_cast<uint32_t*>(&t);
}
__device__ __forceinline__ void split2h(float a, float b, uint32_t& hi, uint32_t& lo) {
    __half2 t = __floats2half2_rn(a, b);
    hi = *reinterpret_cast<uint32_t*>(&t);
    __half2 t2 = __floats2half2_rn(a - __low2float(t), b - __high2float(t));
    lo = *reinterpret_cast<uint32_t*>(&t2);
}
__device__ __forceinline__ float ex2f(float x) {
    float r;
    asm("ex2.approx.f32 %0, %1;" : "=f"(r) : "f"(x));
    return r;
}

// ---------------------------------------------------------------------------
// Kernel 1: LayerNorm -> plain fp16
// ---------------------------------------------------------------------------
__global__ void __launch_bounds__(256) ln_kernel(const float* __restrict__ msa,
                                                 const float* __restrict__ gamma,
                                                 const float* __restrict__ beta)
{
    __shared__ float p1[8], p2[8];
    const int tid = threadIdx.x;
    const int r = tid >> 6;
    const int t = tid & 63;
    const int row = blockIdx.x * 4 + r;

    const float4 v = *(const float4*)(msa + (size_t)row * CS + t * 4);
    float s1 = v.x + v.y + v.z + v.w;
    float s2 = v.x * v.x + v.y * v.y + v.z * v.z + v.w * v.w;
    #pragma unroll
    for (int o = 16; o > 0; o >>= 1) {
        s1 += __shfl_xor_sync(0xFFFFFFFFu, s1, o);
        s2 += __shfl_xor_sync(0xFFFFFFFFu, s2, o);
    }
    if ((tid & 31) == 0) { p1[tid >> 5] = s1; p2[tid >> 5] = s2; }
    __syncthreads();
    const float a = p1[2 * r] + p1[2 * r + 1];
    const float b = p2[2 * r] + p2[2 * r + 1];
    const float mu = a * (1.0f / CS);
    const float var = b * (1.0f / CS) - mu * mu;
    const float rstd = rsqrtf(var + 1e-5f);

    const float4 gm = *(const float4*)(gamma + t * 4);
    const float4 bt = *(const float4*)(beta + t * 4);
    const float y0 = (v.x - mu) * rstd * gm.x + bt.x;
    const float y1 = (v.y - mu) * rstd * gm.y + bt.y;
    const float y2 = (v.z - mu) * rstd * gm.z + bt.z;
    const float y3 = (v.w - mu) * rstd * gm.w + bt.w;

    *(uint2*)(g_x + (size_t)row * CS + t * 4) = make_uint2(h2pack(y0, y1), h2pack(y2, y3));
}

// ---------------------------------------------------------------------------
// Kernel 2: weight split to fp16 hi/lo
// ---------------------------------------------------------------------------
__global__ void __launch_bounds__(256) wprep_kernel(const float* __restrict__ Wq,
                                                    const float* __restrict__ Wk,
                                                    const float* __restrict__ Wv,
                                                    const float* __restrict__ Wg,
                                                    const float* __restrict__ Wo)
{
    const int idx = blockIdx.x * 256 + threadIdx.x;
    const int w = idx >> 16;
    const int e = idx & 65535;
    const float* W = (w == 0) ? Wq : (w == 1) ? Wk : (w == 2) ? Wv : (w == 3) ? Wg : Wo;
    const float val = W[e];
    const __half h = __float2half_rn(val);
    g_wt_hi[idx] = h;
    g_wt_lo[idx] = __float2half_rn(val - __half2float(h));
}

// ---------------------------------------------------------------------------
// HMMA GEMM: C[128,256] = A[128,256] @ W[256,256].
// 256 threads / 8 warps, warp tile 64x64 (2m x 4n warp grid), BK=16, 3-stage.
// mode: 0 = QSCALE + fp16 single, 1 = fp16 split hi/lo,
//       2 = sigmoid(x+bias) fp32, 3 = x+bias fp32
// ---------------------------------------------------------------------------
#define GB_OFF  6144u
#define GB_TERM 8448u
#define GSTAGE  23040u
#define GEMM_SMEM (3 * 23040)

__device__ __forceinline__ void gemm_load_stage(uint32_t st, int ks, int tid, int mblk,
                                                const __half* __restrict__ aP,
                                                const __half* __restrict__ bH,
                                                const __half* __restrict__ bL)
{
    // A: 128 rows x 32B = 256 chunks, 1 per thread
    const int ar = tid >> 1, ac = tid & 1;
    cpa16(st + (uint32_t)(ar * 48 + ac * 16),
          aP + (size_t)(mblk * 128 + ar) * CS + ks * 16 + ac * 8);
    // B hi/lo: 16 rows x 512B = 512 chunks each, 2 per thread per term
    #pragma unroll
    for (int j = 0; j < 2; j++) {
        const int u = tid + 256 * j;
        const int row = u >> 5, col = u & 31;
        const uint32_t d = st + GB_OFF + (uint32_t)(row * 528 + col * 16);
        const size_t s = (size_t)(ks * 16 + row) * CS + col * 8;
        cpa16(d, bH + s);
        cpa16(d + GB_TERM, bL + s);
    }
}

__device__ __forceinline__ void gemm_body(const __half* __restrict__ aP,
                                          const __half* __restrict__ bH,
                                          const __half* __restrict__ bL,
                                          const float* __restrict__ bias,
                                          float* __restrict__ Cf,
                                          __half* __restrict__ Chi,
                                          __half* __restrict__ Clo,
                                          int mode, int mblk)
{
    extern __shared__ unsigned char smem[];
    const uint32_t sb = smem_u32(smem);
    const int tid = threadIdx.x;
    const int lane = tid & 31;
    const int wid = tid >> 5;
    const int wm = wid >> 2;        // 0..1 -> m tile of 64
    const int wn = wid & 3;         // 0..3 -> n tile of 64

    float acc[2][8][4];             // [mf pair handled as 4 via 2x2]? -> use [4][8] flattened below
    // acc layout: acc4[mf][nf][4] with mf 0..3, nf 0..7
    float acc4[4][8][4];
    #pragma unroll
    for (int i = 0; i < 4; i++)
        #pragma unroll
        for (int j = 0; j < 8; j++)
            #pragma unroll
            for (int q = 0; q < 4; q++) acc4[i][j][q] = 0.f;
    (void)acc;

    gemm_load_stage(sb,          0, tid, mblk, aP, bH, bL);
    cpa_commit();
    gemm_load_stage(sb + GSTAGE, 1, tid, mblk, aP, bH, bL);
    cpa_commit();

    const uint32_t aRowSel = (uint32_t)((wm * 64 + (lane & 15)) * 48 + (lane >> 4) * 16);
    const uint32_t bColSel = (uint32_t)((lane & 15) * 528 + (wn * 64 + (lane >> 4) * 8) * 2);

    for (int ks = 0; ks < 16; ks++) {
        if (ks < 15) cpa_wait<1>(); else cpa_wait<0>();
        __syncthreads();
        if (ks + 2 < 16) {
            gemm_load_stage(sb + (uint32_t)((ks + 2) % 3) * GSTAGE, ks + 2, tid, mblk, aP, bH, bL);
            cpa_commit();
        }
        const uint32_t st = sb + (uint32_t)(ks % 3) * GSTAGE;

        uint32_t Af[4][4], Bh[8][2], Bl[8][2];
        #pragma unroll
        for (int mf = 0; mf < 4; mf++)
            ldsm4(Af[mf], st + aRowSel + (uint32_t)(mf * 16 * 48));
        const uint32_t bBase = st + GB_OFF + bColSel;
        #pragma unroll
        for (int g = 0; g < 4; g++) {
            uint32_t r[4];
            ldsm4t(r, bBase + (uint32_t)(g * 32));
            Bh[2 * g][0] = r[0]; Bh[2 * g][1] = r[1];
            Bh[2 * g + 1][0] = r[2]; Bh[2 * g + 1][1] = r[3];
            ldsm4t(r, bBase + GB_TERM + (uint32_t)(g * 32));
            Bl[2 * g][0] = r[0]; Bl[2 * g][1] = r[1];
            Bl[2 * g + 1][0] = r[2]; Bl[2 * g + 1][1] = r[3];
        }
        #pragma unroll
        for (int mf = 0; mf < 4; mf++)
            #pragma unroll
            for (int nf = 0; nf < 8; nf++)
                mma_f16(acc4[mf][nf], Af[mf], Bh[nf]);
        #pragma unroll
        for (int mf = 0; mf < 4; mf++)
            #pragma unroll
            for (int nf = 0; nf < 8; nf++)
                mma_f16(acc4[mf][nf], Af[mf], Bl[nf]);
    }

    // ---- epilogue ----
    const int r0 = mblk * 128 + wm * 64 + (lane >> 2);
    const int c0 = wn * 64 + (lane & 3) * 2;
    #pragma unroll
    for (int mf = 0; mf < 4; mf++) {
        #pragma unroll
        for (int nf = 0; nf < 8; nf++) {
            const int n = c0 + nf * 8;
            const int m = r0 + mf * 16;
            float v0 = acc4[mf][nf][0], v1 = acc4[mf][nf][1];
            float v2 = acc4[mf][nf][2], v3 = acc4[mf][nf][3];
            if (mode == 0) {
                *(uint32_t*)(Chi + (size_t)m * CS + n)       = h2pack(v0 * QSCALE, v1 * QSCALE);
                *(uint32_t*)(Chi + (size_t)(m + 8) * CS + n) = h2pack(v2 * QSCALE, v3 * QSCALE);
            } else if (mode == 1) {
                uint32_t h0, l0, h1, l1;
                split2h(v0, v1, h0, l0);
                split2h(v2, v3, h1, l1);
                *(uint32_t*)(Chi + (size_t)m * CS + n)       = h0;
                *(uint32_t*)(Clo + (size_t)m * CS + n)       = l0;
                *(uint32_t*)(Chi + (size_t)(m + 8) * CS + n) = h1;
                *(uint32_t*)(Clo + (size_t)(m + 8) * CS + n) = l1;
            } else if (mode == 2) {
                const float b0 = __ldg(bias + n), b1 = __ldg(bias + n + 1);
                v0 = 1.f / (1.f + __expf(-(v0 + b0)));
                v1 = 1.f / (1.f + __expf(-(v1 + b1)));
                v2 = 1.f / (1.f + __expf(-(v2 + b0)));
                v3 = 1.f / (1.f + __expf(-(v3 + b1)));
                *(float2*)(Cf + (size_t)m * CS + n)       = make_float2(v0, v1);
                *(float2*)(Cf + (size_t)(m + 8) * CS + n) = make_float2(v2, v3);
            } else {
                const float b0 = __ldg(bias + n), b1 = __ldg(bias + n + 1);
                *(float2*)(Cf + (size_t)m * CS + n)       = make_float2(v0 + b0, v1 + b1);
                *(float2*)(Cf + (size_t)(m + 8) * CS + n) = make_float2(v2 + b0, v3 + b1);
            }
        }
    }
}

__global__ void __launch_bounds__(256, 1) gemm_proj(const float* __restrict__ bg)
{
    const int w = blockIdx.y;
    const __half* bh = g_wt_hi + (size_t)w * 65536;
    const __half* bl = g_wt_lo + (size_t)w * 65536;
    if (w == 0)
        gemm_body(g_x, bh, bl, nullptr, nullptr, g_q, nullptr, 0, blockIdx.x);
    else if (w == 1)
        gemm_body(g_x, bh, bl, nullptr, nullptr, g_k_hi, g_k_lo, 1, blockIdx.x);
    else if (w == 2)
        gemm_body(g_x, bh, bl, nullptr, nullptr, g_v_hi, g_v_lo, 1, blockIdx.x);
    else
        gemm_body(g_x, bh, bl, bg, g_g, nullptr, nullptr, 2, blockIdx.x);
}

__global__ void __launch_bounds__(256, 1) gemm_outp(const float* __restrict__ bo,
                                                    float* __restrict__ out)
{
    gemm_body(g_gv, g_wt_hi + (size_t)4 * 65536, g_wt_lo + (size_t)4 * 65536,
              bo, out, nullptr, nullptr, 3, blockIdx.x);
}

// ---------------------------------------------------------------------------
// Kernel 3: tensor-core column attention.
// Block = (i, head-pair). 512 thr = 16 warps: wh = head (2), wq = q-group (8),
// each warp owns 32 queries (2 m-frags) over all 256 keys (kt loop).
// K/V fragments feed 2 m-frags -> half the ldsm bytes per unit work.
// smem: Q 2 heads x 20480 + 3 stages x 40960 (Kh,Kl,Vh,Vl x 2 heads @64x80B).
// ---------------------------------------------------------------------------
#define AQ_SZ   20480u
#define AST_OFF 40960u
#define AST_SZ  40960u
#define ATTN_SMEM (40960 + 3 * 40960)

__device__ __forceinline__ void load_kv_stage(uint32_t stbase, int i, int hp, int t0, int tid)
{
    #pragma unroll
    for (int j = 0; j < 4; j++) {
        const int u = tid + 512 * j;
        const int sub = u >> 8;             // arr*2 + hsel
        const int rem = u & 255;
        const int row = rem >> 2;
        const int c = rem & 3;
        const int arr = sub >> 1;
        const int hsel = sub & 1;
        const __half* base = (arr == 0) ? g_k_hi : (arr == 1) ? g_k_lo
                           : (arr == 2) ? g_v_hi : g_v_lo;
        const __half* src = base + ((size_t)(t0 + row) * I_DIM + i) * CS
                            + (2 * hp + hsel) * HD + c * 8;
        cpa16(stbase + (uint32_t)(sub * 5120 + row * 80 + c * 16), src);
    }
}

__global__ void __launch_bounds__(512, 1) attn_kernel()
{
    extern __shared__ unsigned char sm[];
    const uint32_t sb = smem_u32(sm);
    const int i = blockIdx.x;
    const int hp = blockIdx.y;          // head pair
    const int tid = threadIdx.x;
    const int lane = tid & 31;
    const int wid = tid >> 5;
    const int wh = wid >> 3;            // head within pair
    const int wq = wid & 7;             // q-group (32 queries)
    const int h = 2 * hp + wh;

    // Q load: 2 heads x 256 rows x 4 chunks = 2048 chunks, 4/thread
    #pragma unroll
    for (int j = 0; j < 4; j++) {
        const int u = tid + 512 * j;
        const int hsel = u >> 10;
        const int rem = u & 1023;
        const int row = rem >> 2, c = rem & 3;
        cpa16(sb + (uint32_t)(hsel * AQ_SZ + row * 80 + c * 16),
              g_q + ((size_t)row * I_DIM + i) * CS + (2 * hp + hsel) * HD + c * 8);
    }
    cpa_commit();
    load_kv_stage(sb + AST_OFF, i, hp, 0, tid);
    cpa_commit();
    load_kv_stage(sb + AST_OFF + AST_SZ, i, hp, 64, tid);
    cpa_commit();

    cpa_wait<2>();
    __syncthreads();

    // Q fragments: 2 m-frags x 2 k-halves
    uint32_t qf[2][2][4];
    {
        const uint32_t qb = sb + (uint32_t)wh * AQ_SZ;
        #pragma unroll
        for (int mf = 0; mf < 2; mf++) {
            const uint32_t qrow = (uint32_t)((wq * 32 + mf * 16 + (lane & 15)) * 80
                                             + (lane >> 4) * 16);
            ldsm4(qf[mf][0], qb + qrow);
            ldsm4(qf[mf][1], qb + qrow + 32u);
        }
    }

    float o[2][4][4];
    #pragma unroll
    for (int mf = 0; mf < 2; mf++)
        #pragma unroll
        for (int nf = 0; nf < 4; nf++)
            #pragma unroll
            for (int q = 0; q < 4; q++) o[mf][nf][q] = 0.f;
    float lsum[2][2] = {{0.f, 0.f}, {0.f, 0.f}};

    const uint32_t kaddr = (uint32_t)((((lane >> 4) * 8) + (lane & 7)) * 80 + ((lane >> 3) & 1) * 16);
    const uint32_t vaddr = (uint32_t)(((((lane >> 3) & 1) * 8) + (lane & 7)) * 80 + (lane >> 4) * 16);

    for (int kt = 0; kt < 4; kt++) {
        if (kt < 3) cpa_wait<1>(); else cpa_wait<0>();
        __syncthreads();
        if (kt + 2 < 4) {
            load_kv_stage(sb + AST_OFF + (uint32_t)((kt + 2) % 3) * AST_SZ, i, hp, (kt + 2) * 64, tid);
            cpa_commit();
        }
        const uint32_t st = sb + AST_OFF + (uint32_t)(kt % 3) * AST_SZ;
        const uint32_t khb = st + (uint32_t)(wh)     * 5120u;
        const uint32_t klb = st + (uint32_t)(2 + wh) * 5120u;
        const uint32_t vhb = st + (uint32_t)(4 + wh) * 5120u;
        const uint32_t vlb = st + (uint32_t)(6 + wh) * 5120u;

        // 4 chunks of 16 keys
        #pragma unroll
        for (int ch = 0; ch < 4; ch++) {
            const uint32_t roff = (uint32_t)(ch * 16 * 80);

            float s[2][2][4];   // [nt][mf][4]
            #pragma unroll
            for (int nt = 0; nt < 2; nt++)
                #pragma unroll
                for (int mf = 0; mf < 2; mf++)
                    #pragma unroll
                    for (int q = 0; q < 4; q++) s[nt][mf][q] = 0.f;

            #pragma unroll
            for (int ks = 0; ks < 2; ks++) {
                uint32_t bh[2][2], bl[2][2], r[4];
                ldsm4(r, khb + roff + kaddr + (uint32_t)(ks * 32));
                bh[0][0] = r[0]; bh[0][1] = r[1]; bh[1][0] = r[2]; bh[1][1] = r[3];
                ldsm4(r, klb + roff + kaddr + (uint32_t)(ks * 32));
                bl[0][0] = r[0]; bl[0][1] = r[1]; bl[1][0] = r[2]; bl[1][1] = r[3];
                #pragma unroll
                for (int nt = 0; nt < 2; nt++)
                    #pragma unroll
                    for (int mf = 0; mf < 2; mf++) {
                        mma_f16(s[nt][mf], qf[mf][ks], bh[nt]);
                        mma_f16(s[nt][mf], qf[mf][ks], bl[nt]);
                    }
            }

            // V fragments for this 16-key chunk (n = 32 dims)
            uint32_t vhf[4][2], vlf[4][2];
            #pragma unroll
            for (int np2 = 0; np2 < 2; np2++) {
                uint32_t r[4];
                ldsm4t(r, vhb + roff + vaddr + (uint32_t)(np2 * 32));
                vhf[2 * np2][0] = r[0]; vhf[2 * np2][1] = r[1];
                vhf[2 * np2 + 1][0] = r[2]; vhf[2 * np2 + 1][1] = r[3];
                ldsm4t(r, vlb + roff + vaddr + (uint32_t)(np2 * 32));
                vlf[2 * np2][0] = r[0]; vlf[2 * np2][1] = r[1];
                vlf[2 * np2 + 1][0] = r[2]; vlf[2 * np2 + 1][1] = r[3];
            }

            // exp + lsum + pack P + PV per m-frag
            #pragma unroll
            for (int mf = 0; mf < 2; mf++) {
                float* sa = s[0][mf];
                float* sc = s[1][mf];
                sa[0] = ex2f(sa[0]); sa[1] = ex2f(sa[1]);
                sa[2] = ex2f(sa[2]); sa[3] = ex2f(sa[3]);
                sc[0] = ex2f(sc[0]); sc[1] = ex2f(sc[1]);
                sc[2] = ex2f(sc[2]); sc[3] = ex2f(sc[3]);
                lsum[mf][0] += sa[0] + sa[1] + sc[0] + sc[1];
                lsum[mf][1] += sa[2] + sa[3] + sc[2] + sc[3];
                uint32_t pA[4];
                pA[0] = h2pack(sa[0], sa[1]);
                pA[1] = h2pack(sa[2], sa[3]);
                pA[2] = h2pack(sc[0], sc[1]);
                pA[3] = h2pack(sc[2], sc[3]);
                #pragma unroll
                for (int nf = 0; nf < 4; nf++) {
                    mma_f16(o[mf][nf], pA, vhf[nf]);
                    mma_f16(o[mf][nf], pA, vlf[nf]);
                }
            }
        }
    }

    // ---- epilogue: quad-reduce lsum, normalize, gate, fp16 store ----
    #pragma unroll
    for (int mf = 0; mf < 2; mf++) {
        float l0 = lsum[mf][0], l1 = lsum[mf][1];
        l0 += __shfl_xor_sync(0xFFFFFFFFu, l0, 1);
        l0 += __shfl_xor_sync(0xFFFFFFFFu, l0, 2);
        l1 += __shfl_xor_sync(0xFFFFFFFFu, l1, 1);
        l1 += __shfl_xor_sync(0xFFFFFFFFu, l1, 2);
        const float inv0 = 1.f / l0;
        const float inv1 = 1.f / l1;

        const int row = wq * 32 + mf * 16 + (lane >> 2);
        const size_t M0 = ((size_t)row * I_DIM + i) * CS + h * HD;
        const size_t M1 = ((size_t)(row + 8) * I_DIM + i) * CS + h * HD;
        #pragma unroll
        for (int nf = 0; nf < 4; nf++) {
            const int col = nf * 8 + (lane & 3) * 2;
            const float2 g0 = *(const float2*)(g_g + M0 + col);
            const float2 g1 = *(const float2*)(g_g + M1 + col);
            *(uint32_t*)(g_gv + M0 + col) =
                h2pack(o[mf][nf][0] * inv0 * g0.x, o[mf][nf][1] * inv0 * g0.y);
            *(uint32_t*)(g_gv + M1 + col) =
                h2pack(o[mf][nf][2] * inv1 * g1.x, o[mf][nf][3] * inv1 * g1.y);
        }
    }
}

// ---------------------------------------------------------------------------
// Launch
// ---------------------------------------------------------------------------
extern "C" void kernel_launch(void* const* d_in, const int* in_sizes, int n_in,
                              void* d_out, int out_size)
{
    const float* msa   = (const float*)d_in[0];
    const float* gamma = (const float*)d_in[1];
    const float* beta  = (const float*)d_in[2];
    const float* Wq    = (const float*)d_in[3];
    const float* Wk    = (const float*)d_in[4];
    const float* Wv    = (const float*)d_in[5];
    const float* Wg    = (const float*)d_in[6];
    const float* bg    = (const float*)d_in[7];
    const float* Wo    = (const float*)d_in[8];
    const float* bo    = (const float*)d_in[9];
    float* out = (float*)d_out;

    cudaFuncSetAttribute(gemm_proj, cudaFuncAttributeMaxDynamicSharedMemorySize, GEMM_SMEM);
    cudaFuncSetAttribute(gemm_outp, cudaFuncAttributeMaxDynamicSharedMemorySize, GEMM_SMEM);
    cudaFuncSetAttribute(attn_kernel, cudaFuncAttributeMaxDynamicSharedMemorySize, ATTN_SMEM);

    ln_kernel<<<M_ROWS / 4, 256>>>(msa, gamma, beta);
    wprep_kernel<<<5 * 65536 / 256, 256>>>(Wq, Wk, Wv, Wg, Wo);

    gemm_proj<<<dim3(MBLOCKS, 4), 256, GEMM_SMEM>>>(bg);

    attn_kernel<<<dim3(I_DIM, NH / 2), 512, ATTN_SMEM>>>();

    gemm_outp<<<MBLOCKS, 256, GEMM_SMEM>>>(bo, out);
}

// round 8
// speedup vs baseline: 1.2856x; 1.2856x over previous
#include <cuda_runtime.h>
#include <cuda_fp16.h>
#include <cstdint>
#include <math.h>

#define S_DIM 256
#define I_DIM 256
#define CS    256
#define NH    8
#define HD    32
#define M_ROWS 65536
#define MBLOCKS 512
#define QSCALE 0.2550349f   /* log2(e) / sqrt(32) */

// ---------------------------------------------------------------------------
// Scratch (device globals). A-operands plain fp16; B-operands split hi/lo.
// ---------------------------------------------------------------------------
__device__ __align__(16) __half g_x   [M_ROWS * CS];
__device__ __align__(16) __half g_gv  [M_ROWS * CS];
__device__ __align__(16) __half g_q   [M_ROWS * CS];
__device__ __align__(16) __half g_k_hi[M_ROWS * CS];
__device__ __align__(16) __half g_k_lo[M_ROWS * CS];
__device__ __align__(16) __half g_v_hi[M_ROWS * CS];
__device__ __align__(16) __half g_v_lo[M_ROWS * CS];
__device__ __align__(16) __half g_wt_hi[5 * CS * CS];   // [w][k][n]
__device__ __align__(16) __half g_wt_lo[5 * CS * CS];
__device__ float g_g[M_ROWS * CS];

// ---------------------------------------------------------------------------
// Helpers
// ---------------------------------------------------------------------------
__device__ __forceinline__ uint32_t smem_u32(const void* p) {
    uint32_t a;
    asm("{ .reg .u64 t; cvta.to.shared.u64 t, %1; cvt.u32.u64 %0, t; }" : "=r"(a) : "l"(p));
    return a;
}
__device__ __forceinline__ void cpa16(uint32_t dst, const void* src) {
    asm volatile("{ .reg .u64 g; cvta.to.global.u64 g, %1;"
                 "  cp.async.cg.shared.global [%0], [g], 16; }"
                 :: "r"(dst), "l"(src) : "memory");
}
__device__ __forceinline__ void cpa_commit() {
    asm volatile("cp.async.commit_group;" ::: "memory");
}
template <int N>
__device__ __forceinline__ void cpa_wait() {
    asm volatile("cp.async.wait_group %0;" :: "n"(N) : "memory");
}
__device__ __forceinline__ void ldsm4(uint32_t* r, uint32_t addr) {
    asm volatile("ldmatrix.sync.aligned.m8n8.x4.shared.b16 {%0,%1,%2,%3}, [%4];"
                 : "=r"(r[0]), "=r"(r[1]), "=r"(r[2]), "=r"(r[3]) : "r"(addr));
}
__device__ __forceinline__ void ldsm4t(uint32_t* r, uint32_t addr) {
    asm volatile("ldmatrix.sync.aligned.m8n8.x4.trans.shared.b16 {%0,%1,%2,%3}, [%4];"
                 : "=r"(r[0]), "=r"(r[1]), "=r"(r[2]), "=r"(r[3]) : "r"(addr));
}
__device__ __forceinline__ void mma_f16(float* c, const uint32_t* a, const uint32_t* b) {
    asm volatile("mma.sync.aligned.m16n8k16.row.col.f32.f16.f16.f32 "
                 "{%0,%1,%2,%3}, {%4,%5,%6,%7}, {%8,%9}, {%0,%1,%2,%3};"
                 : "+f"(c[0]), "+f"(c[1]), "+f"(c[2]), "+f"(c[3])
                 : "r"(a[0]), "r"(a[1]), "r"(a[2]), "r"(a[3]), "r"(b[0]), "r"(b[1]));
}
__device__ __forceinline__ uint32_t h2pack(float a, float b) {
    __half2 t = __floats2half2_rn(a, b);
    return *reinterpret_cast<uint32_t*>(&t);
}
__device__ __forceinline__ void split2h(float a, float b, uint32_t& hi, uint32_t& lo) {
    __half2 t = __floats2half2_rn(a, b);
    hi = *reinterpret_cast<uint32_t*>(&t);
    __half2 t2 = __floats2half2_rn(a - __low2float(t), b - __high2float(t));
    lo = *reinterpret_cast<uint32_t*>(&t2);
}
__device__ __forceinline__ float ex2f(float x) {
    float r;
    asm("ex2.approx.f32 %0, %1;" : "=f"(r) : "f"(x));
    return r;
}

// ---------------------------------------------------------------------------
// Kernel 1: LayerNorm -> plain fp16
// ---------------------------------------------------------------------------
__global__ void __launch_bounds__(256) ln_kernel(const float* __restrict__ msa,
                                                 const float* __restrict__ gamma,
                                                 const float* __restrict__ beta)
{
    __shared__ float p1[8], p2[8];
    const int tid = threadIdx.x;
    const int r = tid >> 6;
    const int t = tid & 63;
    const int row = blockIdx.x * 4 + r;

    const float4 v = *(const float4*)(msa + (size_t)row * CS + t * 4);
    float s1 = v.x + v.y + v.z + v.w;
    float s2 = v.x * v.x + v.y * v.y + v.z * v.z + v.w * v.w;
    #pragma unroll
    for (int o = 16; o > 0; o >>= 1) {
        s1 += __shfl_xor_sync(0xFFFFFFFFu, s1, o);
        s2 += __shfl_xor_sync(0xFFFFFFFFu, s2, o);
    }
    if ((tid & 31) == 0) { p1[tid >> 5] = s1; p2[tid >> 5] = s2; }
    __syncthreads();
    const float a = p1[2 * r] + p1[2 * r + 1];
    const float b = p2[2 * r] + p2[2 * r + 1];
    const float mu = a * (1.0f / CS);
    const float var = b * (1.0f / CS) - mu * mu;
    const float rstd = rsqrtf(var + 1e-5f);

    const float4 gm = *(const float4*)(gamma + t * 4);
    const float4 bt = *(const float4*)(beta + t * 4);
    const float y0 = (v.x - mu) * rstd * gm.x + bt.x;
    const float y1 = (v.y - mu) * rstd * gm.y + bt.y;
    const float y2 = (v.z - mu) * rstd * gm.z + bt.z;
    const float y3 = (v.w - mu) * rstd * gm.w + bt.w;

    *(uint2*)(g_x + (size_t)row * CS + t * 4) = make_uint2(h2pack(y0, y1), h2pack(y2, y3));
}

// ---------------------------------------------------------------------------
// Kernel 2: weight split to fp16 hi/lo
// ---------------------------------------------------------------------------
__global__ void __launch_bounds__(256) wprep_kernel(const float* __restrict__ Wq,
                                                    const float* __restrict__ Wk,
                                                    const float* __restrict__ Wv,
                                                    const float* __restrict__ Wg,
                                                    const float* __restrict__ Wo)
{
    const int idx = blockIdx.x * 256 + threadIdx.x;
    const int w = idx >> 16;
    const int e = idx & 65535;
    const float* W = (w == 0) ? Wq : (w == 1) ? Wk : (w == 2) ? Wv : (w == 3) ? Wg : Wo;
    const float val = W[e];
    const __half h = __float2half_rn(val);
    g_wt_hi[idx] = h;
    g_wt_lo[idx] = __float2half_rn(val - __half2float(h));
}

// ---------------------------------------------------------------------------
// HMMA GEMM (round-5 proven config): C[128,256] = A[128,256] @ W[256,256].
// 512 threads / 16 warps (2m x 8n), warp tile 64x32, BK=16, 3-stage cp.async.
// mode: 0 = QSCALE + fp16 single, 1 = fp16 split hi/lo,
//       2 = sigmoid(x+bias) fp32, 3 = x+bias fp32
// ---------------------------------------------------------------------------
#define GB_OFF  6144u
#define GB_TERM 8448u
#define GSTAGE  23040u
#define GEMM_SMEM (3 * 23040)

__device__ __forceinline__ void gemm_load_stage(uint32_t st, int ks, int tid, int mblk,
                                                const __half* __restrict__ aP,
                                                const __half* __restrict__ bH,
                                                const __half* __restrict__ bL)
{
    // B hi/lo: 16 rows x 512B = 512 chunks each, 1 per thread per term
    const int row = tid >> 5, col = tid & 31;
    const uint32_t bdst = st + GB_OFF + (uint32_t)(row * 528 + col * 16);
    const size_t bsrc = (size_t)(ks * 16 + row) * CS + col * 8;
    cpa16(bdst, bH + bsrc);
    cpa16(bdst + GB_TERM, bL + bsrc);
    if (tid < 256) {
        const int ar = tid >> 1, ac = tid & 1;
        cpa16(st + (uint32_t)(ar * 48 + ac * 16),
              aP + (size_t)(mblk * 128 + ar) * CS + ks * 16 + ac * 8);
    }
}

__device__ __forceinline__ void gemm_body(const __half* __restrict__ aP,
                                          const __half* __restrict__ bH,
                                          const __half* __restrict__ bL,
                                          const float* __restrict__ bias,
                                          float* __restrict__ Cf,
                                          __half* __restrict__ Chi,
                                          __half* __restrict__ Clo,
                                          int mode, int mblk)
{
    extern __shared__ unsigned char smem[];
    const uint32_t sb = smem_u32(smem);
    const int tid = threadIdx.x;
    const int lane = tid & 31;
    const int wid = tid >> 5;
    const int wm = wid >> 3;
    const int wn = wid & 7;

    float acc[4][4][4];
    #pragma unroll
    for (int i = 0; i < 4; i++)
        #pragma unroll
        for (int j = 0; j < 4; j++)
            #pragma unroll
            for (int q = 0; q < 4; q++) acc[i][j][q] = 0.f;

    gemm_load_stage(sb,          0, tid, mblk, aP, bH, bL);
    cpa_commit();
    gemm_load_stage(sb + GSTAGE, 1, tid, mblk, aP, bH, bL);
    cpa_commit();

    const uint32_t aRowSel = (uint32_t)((wm * 64 + (lane & 15)) * 48 + (lane >> 4) * 16);
    const uint32_t bColSel = (uint32_t)((lane & 15) * 528 + (wn * 32 + (lane >> 4) * 8) * 2);

    for (int ks = 0; ks < 16; ks++) {
        if (ks < 15) cpa_wait<1>(); else cpa_wait<0>();
        __syncthreads();
        if (ks + 2 < 16) {
            gemm_load_stage(sb + (uint32_t)((ks + 2) % 3) * GSTAGE, ks + 2, tid, mblk, aP, bH, bL);
            cpa_commit();
        }
        const uint32_t st = sb + (uint32_t)(ks % 3) * GSTAGE;

        uint32_t Af[4][4], Bh[4][2], Bl[4][2];
        #pragma unroll
        for (int mf = 0; mf < 4; mf++)
            ldsm4(Af[mf], st + aRowSel + (uint32_t)(mf * 16 * 48));
        const uint32_t bBase = st + GB_OFF + bColSel;
        #pragma unroll
        for (int g = 0; g < 2; g++) {
            uint32_t r[4];
            ldsm4t(r, bBase + (uint32_t)(g * 32));
            Bh[2 * g][0] = r[0]; Bh[2 * g][1] = r[1];
            Bh[2 * g + 1][0] = r[2]; Bh[2 * g + 1][1] = r[3];
            ldsm4t(r, bBase + GB_TERM + (uint32_t)(g * 32));
            Bl[2 * g][0] = r[0]; Bl[2 * g][1] = r[1];
            Bl[2 * g + 1][0] = r[2]; Bl[2 * g + 1][1] = r[3];
        }
        #pragma unroll
        for (int mf = 0; mf < 4; mf++)
            #pragma unroll
            for (int nf = 0; nf < 4; nf++)
                mma_f16(acc[mf][nf], Af[mf], Bh[nf]);
        #pragma unroll
        for (int mf = 0; mf < 4; mf++)
            #pragma unroll
            for (int nf = 0; nf < 4; nf++)
                mma_f16(acc[mf][nf], Af[mf], Bl[nf]);
    }

    // ---- epilogue ----
    const int r0 = mblk * 128 + wm * 64 + (lane >> 2);
    const int c0 = wn * 32 + (lane & 3) * 2;
    #pragma unroll
    for (int mf = 0; mf < 4; mf++) {
        #pragma unroll
        for (int nf = 0; nf < 4; nf++) {
            const int n = c0 + nf * 8;
            const int m = r0 + mf * 16;
            float v0 = acc[mf][nf][0], v1 = acc[mf][nf][1];
            float v2 = acc[mf][nf][2], v3 = acc[mf][nf][3];
            if (mode == 0) {
                *(uint32_t*)(Chi + (size_t)m * CS + n)       = h2pack(v0 * QSCALE, v1 * QSCALE);
                *(uint32_t*)(Chi + (size_t)(m + 8) * CS + n) = h2pack(v2 * QSCALE, v3 * QSCALE);
            } else if (mode == 1) {
                uint32_t h0, l0, h1, l1;
                split2h(v0, v1, h0, l0);
                split2h(v2, v3, h1, l1);
                *(uint32_t*)(Chi + (size_t)m * CS + n)       = h0;
                *(uint32_t*)(Clo + (size_t)m * CS + n)       = l0;
                *(uint32_t*)(Chi + (size_t)(m + 8) * CS + n) = h1;
                *(uint32_t*)(Clo + (size_t)(m + 8) * CS + n) = l1;
            } else if (mode == 2) {
                const float b0 = __ldg(bias + n), b1 = __ldg(bias + n + 1);
                v0 = 1.f / (1.f + __expf(-(v0 + b0)));
                v1 = 1.f / (1.f + __expf(-(v1 + b1)));
                v2 = 1.f / (1.f + __expf(-(v2 + b0)));
                v3 = 1.f / (1.f + __expf(-(v3 + b1)));
                *(float2*)(Cf + (size_t)m * CS + n)       = make_float2(v0, v1);
                *(float2*)(Cf + (size_t)(m + 8) * CS + n) = make_float2(v2, v3);
            } else {
                const float b0 = __ldg(bias + n), b1 = __ldg(bias + n + 1);
                *(float2*)(Cf + (size_t)m * CS + n)       = make_float2(v0 + b0, v1 + b1);
                *(float2*)(Cf + (size_t)(m + 8) * CS + n) = make_float2(v2 + b0, v3 + b1);
            }
        }
    }
}

__global__ void __launch_bounds__(512, 1) gemm_proj(const float* __restrict__ bg)
{
    const int w = blockIdx.y;
    const __half* bh = g_wt_hi + (size_t)w * 65536;
    const __half* bl = g_wt_lo + (size_t)w * 65536;
    if (w == 0)
        gemm_body(g_x, bh, bl, nullptr, nullptr, g_q, nullptr, 0, blockIdx.x);
    else if (w == 1)
        gemm_body(g_x, bh, bl, nullptr, nullptr, g_k_hi, g_k_lo, 1, blockIdx.x);
    else if (w == 2)
        gemm_body(g_x, bh, bl, nullptr, nullptr, g_v_hi, g_v_lo, 1, blockIdx.x);
    else
        gemm_body(g_x, bh, bl, bg, g_g, nullptr, nullptr, 2, blockIdx.x);
}

__global__ void __launch_bounds__(512, 1) gemm_outp(const float* __restrict__ bo,
                                                    float* __restrict__ out)
{
    gemm_body(g_gv, g_wt_hi + (size_t)4 * 65536, g_wt_lo + (size_t)4 * 65536,
              bo, out, nullptr, nullptr, 3, blockIdx.x);
}

// ---------------------------------------------------------------------------
// Kernel 3: tensor-core column attention.
// Block = one (i, h). 256 thr = 8 warps, each warp owns 32 queries (2 m-frags)
// over all 256 keys. smem 80KB -> 2 CTAs/SM for latency hiding.
// ---------------------------------------------------------------------------
#define AQ_SZ   20480u
#define AST_OFF 20480u
#define AST_SZ  20480u
#define ATTN_SMEM (20480 + 3 * 20480)

__device__ __forceinline__ void load_kv_stage(uint32_t stbase, int i, int h, int t0, int tid)
{
    #pragma unroll
    for (int j = 0; j < 4; j++) {
        const int u = tid + 256 * j;
        const int arr = u >> 8;             // 0:Kh 1:Kl 2:Vh 3:Vl
        const int rem = u & 255;
        const int row = rem >> 2;
        const int c = rem & 3;
        const __half* base = (arr == 0) ? g_k_hi : (arr == 1) ? g_k_lo
                           : (arr == 2) ? g_v_hi : g_v_lo;
        const __half* src = base + ((size_t)(t0 + row) * I_DIM + i) * CS + h * HD + c * 8;
        cpa16(stbase + (uint32_t)(arr * 5120 + row * 80 + c * 16), src);
    }
}

__global__ void __launch_bounds__(256, 2) attn_kernel()
{
    extern __shared__ unsigned char sm[];
    const uint32_t sb = smem_u32(sm);
    const int i = blockIdx.x;
    const int h = blockIdx.y;
    const int tid = threadIdx.x;
    const int lane = tid & 31;
    const int wq = tid >> 5;            // q-group (32 queries)

    // Q load: 256 rows x 4 chunks = 1024 chunks, 4/thread
    #pragma unroll
    for (int j = 0; j < 4; j++) {
        const int u = tid + 256 * j;
        const int row = u >> 2, c = u & 3;
        cpa16(sb + (uint32_t)(row * 80 + c * 16),
              g_q + ((size_t)row * I_DIM + i) * CS + h * HD + c * 8);
    }
    cpa_commit();
    load_kv_stage(sb + AST_OFF, i, h, 0, tid);
    cpa_commit();
    load_kv_stage(sb + AST_OFF + AST_SZ, i, h, 64, tid);
    cpa_commit();

    cpa_wait<2>();
    __syncthreads();

    // Q fragments: 2 m-frags x 2 k-halves
    uint32_t qf[2][2][4];
    #pragma unroll
    for (int mf = 0; mf < 2; mf++) {
        const uint32_t qrow = (uint32_t)((wq * 32 + mf * 16 + (lane & 15)) * 80
                                         + (lane >> 4) * 16);
        ldsm4(qf[mf][0], sb + qrow);
        ldsm4(qf[mf][1], sb + qrow + 32u);
    }

    float o[2][4][4];
    #pragma unroll
    for (int mf = 0; mf < 2; mf++)
        #pragma unroll
        for (int nf = 0; nf < 4; nf++)
            #pragma unroll
            for (int q = 0; q < 4; q++) o[mf][nf][q] = 0.f;
    float lsum[2][2] = {{0.f, 0.f}, {0.f, 0.f}};

    const uint32_t kaddr = (uint32_t)((((lane >> 4) * 8) + (lane & 7)) * 80 + ((lane >> 3) & 1) * 16);
    const uint32_t vaddr = (uint32_t)(((((lane >> 3) & 1) * 8) + (lane & 7)) * 80 + (lane >> 4) * 16);

    for (int kt = 0; kt < 4; kt++) {
        if (kt < 3) cpa_wait<1>(); else cpa_wait<0>();
        __syncthreads();
        if (kt + 2 < 4) {
            load_kv_stage(sb + AST_OFF + (uint32_t)((kt + 2) % 3) * AST_SZ, i, h, (kt + 2) * 64, tid);
            cpa_commit();
        }
        const uint32_t st = sb + AST_OFF + (uint32_t)(kt % 3) * AST_SZ;

        // 4 chunks of 16 keys
        #pragma unroll
        for (int ch = 0; ch < 4; ch++) {
            const uint32_t roff = (uint32_t)(ch * 16 * 80);

            float s[2][2][4];   // [nt][mf][4]
            #pragma unroll
            for (int nt = 0; nt < 2; nt++)
                #pragma unroll
                for (int mf = 0; mf < 2; mf++)
                    #pragma unroll
                    for (int q = 0; q < 4; q++) s[nt][mf][q] = 0.f;

            #pragma unroll
            for (int ks = 0; ks < 2; ks++) {
                uint32_t bh[2][2], bl[2][2], r[4];
                ldsm4(r, st + roff + kaddr + (uint32_t)(ks * 32));
                bh[0][0] = r[0]; bh[0][1] = r[1]; bh[1][0] = r[2]; bh[1][1] = r[3];
                ldsm4(r, st + 5120u + roff + kaddr + (uint32_t)(ks * 32));
                bl[0][0] = r[0]; bl[0][1] = r[1]; bl[1][0] = r[2]; bl[1][1] = r[3];
                #pragma unroll
                for (int nt = 0; nt < 2; nt++)
                    #pragma unroll
                    for (int mf = 0; mf < 2; mf++) {
                        mma_f16(s[nt][mf], qf[mf][ks], bh[nt]);
                        mma_f16(s[nt][mf], qf[mf][ks], bl[nt]);
                    }
            }

            // V fragments for this 16-key chunk (n = 32 dims)
            uint32_t vhf[4][2], vlf[4][2];
            #pragma unroll
            for (int np2 = 0; np2 < 2; np2++) {
                uint32_t r[4];
                ldsm4t(r, st + 10240u + roff + vaddr + (uint32_t)(np2 * 32));
                vhf[2 * np2][0] = r[0]; vhf[2 * np2][1] = r[1];
                vhf[2 * np2 + 1][0] = r[2]; vhf[2 * np2 + 1][1] = r[3];
                ldsm4t(r, st + 15360u + roff + vaddr + (uint32_t)(np2 * 32));
                vlf[2 * np2][0] = r[0]; vlf[2 * np2][1] = r[1];
                vlf[2 * np2 + 1][0] = r[2]; vlf[2 * np2 + 1][1] = r[3];
            }

            // exp + lsum + pack P + PV per m-frag
            #pragma unroll
            for (int mf = 0; mf < 2; mf++) {
                float* sa = s[0][mf];
                float* sc = s[1][mf];
                sa[0] = ex2f(sa[0]); sa[1] = ex2f(sa[1]);
                sa[2] = ex2f(sa[2]); sa[3] = ex2f(sa[3]);
                sc[0] = ex2f(sc[0]); sc[1] = ex2f(sc[1]);
                sc[2] = ex2f(sc[2]); sc[3] = ex2f(sc[3]);
                lsum[mf][0] += sa[0] + sa[1] + sc[0] + sc[1];
                lsum[mf][1] += sa[2] + sa[3] + sc[2] + sc[3];
                uint32_t pA[4];
                pA[0] = h2pack(sa[0], sa[1]);
                pA[1] = h2pack(sa[2], sa[3]);
                pA[2] = h2pack(sc[0], sc[1]);
                pA[3] = h2pack(sc[2], sc[3]);
                #pragma unroll
                for (int nf = 0; nf < 4; nf++) {
                    mma_f16(o[mf][nf], pA, vhf[nf]);
                    mma_f16(o[mf][nf], pA, vlf[nf]);
                }
            }
        }
    }

    // ---- epilogue: quad-reduce lsum, normalize, gate, fp16 store ----
    #pragma unroll
    for (int mf = 0; mf < 2; mf++) {
        float l0 = lsum[mf][0], l1 = lsum[mf][1];
        l0 += __shfl_xor_sync(0xFFFFFFFFu, l0, 1);
        l0 += __shfl_xor_sync(0xFFFFFFFFu, l0, 2);
        l1 += __shfl_xor_sync(0xFFFFFFFFu, l1, 1);
        l1 += __shfl_xor_sync(0xFFFFFFFFu, l1, 2);
        const float inv0 = 1.f / l0;
        const float inv1 = 1.f / l1;

        const int row = wq * 32 + mf * 16 + (lane >> 2);
        const size_t M0 = ((size_t)row * I_DIM + i) * CS + h * HD;
        const size_t M1 = ((size_t)(row + 8) * I_DIM + i) * CS + h * HD;
        #pragma unroll
        for (int nf = 0; nf < 4; nf++) {
            const int col = nf * 8 + (lane & 3) * 2;
            const float2 g0 = *(const float2*)(g_g + M0 + col);
            const float2 g1 = *(const float2*)(g_g + M1 + col);
            *(uint32_t*)(g_gv + M0 + col) =
                h2pack(o[mf][nf][0] * inv0 * g0.x, o[mf][nf][1] * inv0 * g0.y);
            *(uint32_t*)(g_gv + M1 + col) =
                h2pack(o[mf][nf][2] * inv1 * g1.x, o[mf][nf][3] * inv1 * g1.y);
        }
    }
}

// ---------------------------------------------------------------------------
// Launch
// ---------------------------------------------------------------------------
extern "C" void kernel_launch(void* const* d_in, const int* in_sizes, int n_in,
                              void* d_out, int out_size)
{
    const float* msa   = (const float*)d_in[0];
    const float* gamma = (const float*)d_in[1];
    const float* beta  = (const float*)d_in[2];
    const float* Wq    = (const float*)d_in[3];
    const float* Wk    = (const float*)d_in[4];
    const float* Wv    = (const float*)d_in[5];
    const float* Wg    = (const float*)d_in[6];
    const float* bg    = (const float*)d_in[7];
    const float* Wo    = (const float*)d_in[8];
    const float* bo    = (const float*)d_in[9];
    float* out = (float*)d_out;

    cudaFuncSetAttribute(gemm_proj, cudaFuncAttributeMaxDynamicSharedMemorySize, GEMM_SMEM);
    cudaFuncSetAttribute(gemm_outp, cudaFuncAttributeMaxDynamicSharedMemorySize, GEMM_SMEM);
    cudaFuncSetAttribute(attn_kernel, cudaFuncAttributeMaxDynamicSharedMemorySize, ATTN_SMEM);

    ln_kernel<<<M_ROWS / 4, 256>>>(msa, gamma, beta);
    wprep_kernel<<<5 * 65536 / 256, 256>>>(Wq, Wk, Wv, Wg, Wo);

    gemm_proj<<<dim3(MBLOCKS, 4), 512, GEMM_SMEM>>>(bg);

    attn_kernel<<<dim3(I_DIM, NH), 256, ATTN_SMEM>>>();

    gemm_outp<<<MBLOCKS, 512, GEMM_SMEM>>>(bo, out);
}

// round 9
// speedup vs baseline: 1.3678x; 1.0639x over previous
#include <cuda_runtime.h>
#include <cuda_fp16.h>
#include <cstdint>
#include <math.h>

#define S_DIM 256
#define I_DIM 256
#define CS    256
#define NH    8
#define HD    32
#define M_ROWS 65536
#define MBLOCKS 512
#define QSCALE 0.2550349f   /* log2(e) / sqrt(32) */

// ---------------------------------------------------------------------------
// Scratch (device globals). A-operands plain fp16; B-operands split hi/lo.
// ---------------------------------------------------------------------------
__device__ __align__(16) __half g_x   [M_ROWS * CS];
__device__ __align__(16) __half g_gv  [M_ROWS * CS];
__device__ __align__(16) __half g_q   [M_ROWS * CS];
__device__ __align__(16) __half g_k_hi[M_ROWS * CS];
__device__ __align__(16) __half g_k_lo[M_ROWS * CS];
__device__ __align__(16) __half g_v_hi[M_ROWS * CS];
__device__ __align__(16) __half g_v_lo[M_ROWS * CS];
__device__ __align__(16) __half g_wt_hi[5 * CS * CS];   // [w][k][n]
__device__ __align__(16) __half g_wt_lo[5 * CS * CS];
__device__ float g_g[M_ROWS * CS];

// ---------------------------------------------------------------------------
// Helpers
// ---------------------------------------------------------------------------
__device__ __forceinline__ uint32_t smem_u32(const void* p) {
    uint32_t a;
    asm("{ .reg .u64 t; cvta.to.shared.u64 t, %1; cvt.u32.u64 %0, t; }" : "=r"(a) : "l"(p));
    return a;
}
__device__ __forceinline__ void cpa16(uint32_t dst, const void* src) {
    asm volatile("{ .reg .u64 g; cvta.to.global.u64 g, %1;"
                 "  cp.async.cg.shared.global [%0], [g], 16; }"
                 :: "r"(dst), "l"(src) : "memory");
}
__device__ __forceinline__ void cpa_commit() {
    asm volatile("cp.async.commit_group;" ::: "memory");
}
template <int N>
__device__ __forceinline__ void cpa_wait() {
    asm volatile("cp.async.wait_group %0;" :: "n"(N) : "memory");
}
__device__ __forceinline__ void ldsm4(uint32_t* r, uint32_t addr) {
    asm volatile("ldmatrix.sync.aligned.m8n8.x4.shared.b16 {%0,%1,%2,%3}, [%4];"
                 : "=r"(r[0]), "=r"(r[1]), "=r"(r[2]), "=r"(r[3]) : "r"(addr));
}
__device__ __forceinline__ void ldsm4t(uint32_t* r, uint32_t addr) {
    asm volatile("ldmatrix.sync.aligned.m8n8.x4.trans.shared.b16 {%0,%1,%2,%3}, [%4];"
                 : "=r"(r[0]), "=r"(r[1]), "=r"(r[2]), "=r"(r[3]) : "r"(addr));
}
__device__ __forceinline__ void mma_f16(float* c, const uint32_t* a, const uint32_t* b) {
    asm volatile("mma.sync.aligned.m16n8k16.row.col.f32.f16.f16.f32 "
                 "{%0,%1,%2,%3}, {%4,%5,%6,%7}, {%8,%9}, {%0,%1,%2,%3};"
                 : "+f"(c[0]), "+f"(c[1]), "+f"(c[2]), "+f"(c[3])
                 : "r"(a[0]), "r"(a[1]), "r"(a[2]), "r"(a[3]), "r"(b[0]), "r"(b[1]));
}
__device__ __forceinline__ uint32_t h2pack(float a, float b) {
    __half2 t = __floats2half2_rn(a, b);
    return *reinterpret_cast<uint32_t*>(&t);
}
__device__ __forceinline__ void split2h(float a, float b, uint32_t& hi, uint32_t& lo) {
    __half2 t = __floats2half2_rn(a, b);
    hi = *reinterpret_cast<uint32_t*>(&t);
    __half2 t2 = __floats2half2_rn(a - __low2float(t), b - __high2float(t));
    lo = *reinterpret_cast<uint32_t*>(&t2);
}
__device__ __forceinline__ float ex2f(float x) {
    float r;
    asm("ex2.approx.f32 %0, %1;" : "=f"(r) : "f"(x));
    return r;
}

// ---------------------------------------------------------------------------
// Kernel 1: LayerNorm -> plain fp16
// ---------------------------------------------------------------------------
__global__ void __launch_bounds__(256) ln_kernel(const float* __restrict__ msa,
                                                 const float* __restrict__ gamma,
                                                 const float* __restrict__ beta)
{
    __shared__ float p1[8], p2[8];
    const int tid = threadIdx.x;
    const int r = tid >> 6;
    const int t = tid & 63;
    const int row = blockIdx.x * 4 + r;

    const float4 v = *(const float4*)(msa + (size_t)row * CS + t * 4);
    float s1 = v.x + v.y + v.z + v.w;
    float s2 = v.x * v.x + v.y * v.y + v.z * v.z + v.w * v.w;
    #pragma unroll
    for (int o = 16; o > 0; o >>= 1) {
        s1 += __shfl_xor_sync(0xFFFFFFFFu, s1, o);
        s2 += __shfl_xor_sync(0xFFFFFFFFu, s2, o);
    }
    if ((tid & 31) == 0) { p1[tid >> 5] = s1; p2[tid >> 5] = s2; }
    __syncthreads();
    const float a = p1[2 * r] + p1[2 * r + 1];
    const float b = p2[2 * r] + p2[2 * r + 1];
    const float mu = a * (1.0f / CS);
    const float var = b * (1.0f / CS) - mu * mu;
    const float rstd = rsqrtf(var + 1e-5f);

    const float4 gm = *(const float4*)(gamma + t * 4);
    const float4 bt = *(const float4*)(beta + t * 4);
    const float y0 = (v.x - mu) * rstd * gm.x + bt.x;
    const float y1 = (v.y - mu) * rstd * gm.y + bt.y;
    const float y2 = (v.z - mu) * rstd * gm.z + bt.z;
    const float y3 = (v.w - mu) * rstd * gm.w + bt.w;

    *(uint2*)(g_x + (size_t)row * CS + t * 4) = make_uint2(h2pack(y0, y1), h2pack(y2, y3));
}

// ---------------------------------------------------------------------------
// Kernel 2: weight split to fp16 hi/lo
// ---------------------------------------------------------------------------
__global__ void __launch_bounds__(256) wprep_kernel(const float* __restrict__ Wq,
                                                    const float* __restrict__ Wk,
                                                    const float* __restrict__ Wv,
                                                    const float* __restrict__ Wg,
                                                    const float* __restrict__ Wo)
{
    const int idx = blockIdx.x * 256 + threadIdx.x;
    const int w = idx >> 16;
    const int e = idx & 65535;
    const float* W = (w == 0) ? Wq : (w == 1) ? Wk : (w == 2) ? Wv : (w == 3) ? Wg : Wo;
    const float val = W[e];
    const __half h = __float2half_rn(val);
    g_wt_hi[idx] = h;
    g_wt_lo[idx] = __float2half_rn(val - __half2float(h));
}

// ---------------------------------------------------------------------------
// HMMA GEMM: C[128,128] = A[128,256] @ W[256,128-slice], fp16 A, W split hi/lo.
// 256 threads / 8 warps (2m x 4n), warp tile 64x32, BK=16, 3-stage, 2 CTAs/SM.
// mode: 0 = QSCALE + fp16 single, 1 = fp16 split hi/lo,
//       2 = sigmoid(x+bias) fp32, 3 = x+bias fp32
// ---------------------------------------------------------------------------
#define GB_OFF  6144u
#define GB_TERM 4352u
#define GSTAGE  14848u
#define GEMM_SMEM (3 * 14848)

__device__ __forceinline__ void gemm_load_stage(uint32_t st, int ks, int tid,
                                                int mblk, int nblk,
                                                const __half* __restrict__ aP,
                                                const __half* __restrict__ bH,
                                                const __half* __restrict__ bL)
{
    // A: 128 rows x 32B = 256 chunks, 1 per thread
    const int ar = tid >> 1, ac = tid & 1;
    cpa16(st + (uint32_t)(ar * 48 + ac * 16),
          aP + (size_t)(mblk * 128 + ar) * CS + ks * 16 + ac * 8);
    // B hi/lo: 16 rows x 256B = 256 chunks each, 1 per thread per term
    const int row = tid >> 4, col = tid & 15;
    const uint32_t bdst = st + GB_OFF + (uint32_t)(row * 272 + col * 16);
    const size_t bsrc = (size_t)(ks * 16 + row) * CS + nblk * 128 + col * 8;
    cpa16(bdst, bH + bsrc);
    cpa16(bdst + GB_TERM, bL + bsrc);
}

__device__ __forceinline__ void gemm_body(const __half* __restrict__ aP,
                                          const __half* __restrict__ bH,
                                          const __half* __restrict__ bL,
                                          const float* __restrict__ bias,
                                          float* __restrict__ Cf,
                                          __half* __restrict__ Chi,
                                          __half* __restrict__ Clo,
                                          int mode, int mblk, int nblk)
{
    extern __shared__ unsigned char smem[];
    const uint32_t sb = smem_u32(smem);
    const int tid = threadIdx.x;
    const int lane = tid & 31;
    const int wid = tid >> 5;
    const int wm = wid >> 2;        // 0..1
    const int wn = wid & 3;         // 0..3

    float acc[4][4][4];
    #pragma unroll
    for (int i = 0; i < 4; i++)
        #pragma unroll
        for (int j = 0; j < 4; j++)
            #pragma unroll
            for (int q = 0; q < 4; q++) acc[i][j][q] = 0.f;

    gemm_load_stage(sb,          0, tid, mblk, nblk, aP, bH, bL);
    cpa_commit();
    gemm_load_stage(sb + GSTAGE, 1, tid, mblk, nblk, aP, bH, bL);
    cpa_commit();

    const uint32_t aRowSel = (uint32_t)((wm * 64 + (lane & 15)) * 48 + (lane >> 4) * 16);
    const uint32_t bColSel = (uint32_t)((lane & 15) * 272 + (wn * 32 + (lane >> 4) * 8) * 2);

    for (int ks = 0; ks < 16; ks++) {
        if (ks < 15) cpa_wait<1>(); else cpa_wait<0>();
        __syncthreads();
        if (ks + 2 < 16) {
            gemm_load_stage(sb + (uint32_t)((ks + 2) % 3) * GSTAGE, ks + 2, tid,
                            mblk, nblk, aP, bH, bL);
            cpa_commit();
        }
        const uint32_t st = sb + (uint32_t)(ks % 3) * GSTAGE;

        uint32_t Af[4][4], Bh[4][2], Bl[4][2];
        #pragma unroll
        for (int mf = 0; mf < 4; mf++)
            ldsm4(Af[mf], st + aRowSel + (uint32_t)(mf * 16 * 48));
        const uint32_t bBase = st + GB_OFF + bColSel;
        #pragma unroll
        for (int g = 0; g < 2; g++) {
            uint32_t r[4];
            ldsm4t(r, bBase + (uint32_t)(g * 32));
            Bh[2 * g][0] = r[0]; Bh[2 * g][1] = r[1];
            Bh[2 * g + 1][0] = r[2]; Bh[2 * g + 1][1] = r[3];
            ldsm4t(r, bBase + GB_TERM + (uint32_t)(g * 32));
            Bl[2 * g][0] = r[0]; Bl[2 * g][1] = r[1];
            Bl[2 * g + 1][0] = r[2]; Bl[2 * g + 1][1] = r[3];
        }
        #pragma unroll
        for (int mf = 0; mf < 4; mf++)
            #pragma unroll
            for (int nf = 0; nf < 4; nf++)
                mma_f16(acc[mf][nf], Af[mf], Bh[nf]);
        #pragma unroll
        for (int mf = 0; mf < 4; mf++)
            #pragma unroll
            for (int nf = 0; nf < 4; nf++)
                mma_f16(acc[mf][nf], Af[mf], Bl[nf]);
    }

    // ---- epilogue ----
    const int r0 = mblk * 128 + wm * 64 + (lane >> 2);
    const int c0 = nblk * 128 + wn * 32 + (lane & 3) * 2;
    #pragma unroll
    for (int mf = 0; mf < 4; mf++) {
        #pragma unroll
        for (int nf = 0; nf < 4; nf++) {
            const int n = c0 + nf * 8;
            const int m = r0 + mf * 16;
            float v0 = acc[mf][nf][0], v1 = acc[mf][nf][1];
            float v2 = acc[mf][nf][2], v3 = acc[mf][nf][3];
            if (mode == 0) {
                *(uint32_t*)(Chi + (size_t)m * CS + n)       = h2pack(v0 * QSCALE, v1 * QSCALE);
                *(uint32_t*)(Chi + (size_t)(m + 8) * CS + n) = h2pack(v2 * QSCALE, v3 * QSCALE);
            } else if (mode == 1) {
                uint32_t h0, l0, h1, l1;
                split2h(v0, v1, h0, l0);
                split2h(v2, v3, h1, l1);
                *(uint32_t*)(Chi + (size_t)m * CS + n)       = h0;
                *(uint32_t*)(Clo + (size_t)m * CS + n)       = l0;
                *(uint32_t*)(Chi + (size_t)(m + 8) * CS + n) = h1;
                *(uint32_t*)(Clo + (size_t)(m + 8) * CS + n) = l1;
            } else if (mode == 2) {
                const float b0 = __ldg(bias + n), b1 = __ldg(bias + n + 1);
                v0 = 1.f / (1.f + __expf(-(v0 + b0)));
                v1 = 1.f / (1.f + __expf(-(v1 + b1)));
                v2 = 1.f / (1.f + __expf(-(v2 + b0)));
                v3 = 1.f / (1.f + __expf(-(v3 + b1)));
                *(float2*)(Cf + (size_t)m * CS + n)       = make_float2(v0, v1);
                *(float2*)(Cf + (size_t)(m + 8) * CS + n) = make_float2(v2, v3);
            } else {
                const float b0 = __ldg(bias + n), b1 = __ldg(bias + n + 1);
                *(float2*)(Cf + (size_t)m * CS + n)       = make_float2(v0 + b0, v1 + b1);
                *(float2*)(Cf + (size_t)(m + 8) * CS + n) = make_float2(v2 + b0, v3 + b1);
            }
        }
    }
}

__global__ void __launch_bounds__(256, 2) gemm_proj(const float* __restrict__ bg)
{
    const int w = blockIdx.z;
    const __half* bh = g_wt_hi + (size_t)w * 65536;
    const __half* bl = g_wt_lo + (size_t)w * 65536;
    if (w == 0)
        gemm_body(g_x, bh, bl, nullptr, nullptr, g_q, nullptr, 0, blockIdx.x, blockIdx.y);
    else if (w == 1)
        gemm_body(g_x, bh, bl, nullptr, nullptr, g_k_hi, g_k_lo, 1, blockIdx.x, blockIdx.y);
    else if (w == 2)
        gemm_body(g_x, bh, bl, nullptr, nullptr, g_v_hi, g_v_lo, 1, blockIdx.x, blockIdx.y);
    else
        gemm_body(g_x, bh, bl, bg, g_g, nullptr, nullptr, 2, blockIdx.x, blockIdx.y);
}

__global__ void __launch_bounds__(256, 2) gemm_outp(const float* __restrict__ bo,
                                                    float* __restrict__ out)
{
    gemm_body(g_gv, g_wt_hi + (size_t)4 * 65536, g_wt_lo + (size_t)4 * 65536,
              bo, out, nullptr, nullptr, 3, blockIdx.x, blockIdx.y);
}

// ---------------------------------------------------------------------------
// Kernel 3: tensor-core column attention (round-8 proven config).
// Block = one (i, h). 256 thr = 8 warps, 32 queries/warp, 2 CTAs/SM.
// ---------------------------------------------------------------------------
#define AQ_SZ   20480u
#define AST_OFF 20480u
#define AST_SZ  20480u
#define ATTN_SMEM (20480 + 3 * 20480)

__device__ __forceinline__ void load_kv_stage(uint32_t stbase, int i, int h, int t0, int tid)
{
    #pragma unroll
    for (int j = 0; j < 4; j++) {
        const int u = tid + 256 * j;
        const int arr = u >> 8;             // 0:Kh 1:Kl 2:Vh 3:Vl
        const int rem = u & 255;
        const int row = rem >> 2;
        const int c = rem & 3;
        const __half* base = (arr == 0) ? g_k_hi : (arr == 1) ? g_k_lo
                           : (arr == 2) ? g_v_hi : g_v_lo;
        const __half* src = base + ((size_t)(t0 + row) * I_DIM + i) * CS + h * HD + c * 8;
        cpa16(stbase + (uint32_t)(arr * 5120 + row * 80 + c * 16), src);
    }
}

__global__ void __launch_bounds__(256, 2) attn_kernel()
{
    extern __shared__ unsigned char sm[];
    const uint32_t sb = smem_u32(sm);
    const int i = blockIdx.x;
    const int h = blockIdx.y;
    const int tid = threadIdx.x;
    const int lane = tid & 31;
    const int wq = tid >> 5;

    #pragma unroll
    for (int j = 0; j < 4; j++) {
        const int u = tid + 256 * j;
        const int row = u >> 2, c = u & 3;
        cpa16(sb + (uint32_t)(row * 80 + c * 16),
              g_q + ((size_t)row * I_DIM + i) * CS + h * HD + c * 8);
    }
    cpa_commit();
    load_kv_stage(sb + AST_OFF, i, h, 0, tid);
    cpa_commit();
    load_kv_stage(sb + AST_OFF + AST_SZ, i, h, 64, tid);
    cpa_commit();

    cpa_wait<2>();
    __syncthreads();

    uint32_t qf[2][2][4];
    #pragma unroll
    for (int mf = 0; mf < 2; mf++) {
        const uint32_t qrow = (uint32_t)((wq * 32 + mf * 16 + (lane & 15)) * 80
                                         + (lane >> 4) * 16);
        ldsm4(qf[mf][0], sb + qrow);
        ldsm4(qf[mf][1], sb + qrow + 32u);
    }

    float o[2][4][4];
    #pragma unroll
    for (int mf = 0; mf < 2; mf++)
        #pragma unroll
        for (int nf = 0; nf < 4; nf++)
            #pragma unroll
            for (int q = 0; q < 4; q++) o[mf][nf][q] = 0.f;
    float lsum[2][2] = {{0.f, 0.f}, {0.f, 0.f}};

    const uint32_t kaddr = (uint32_t)((((lane >> 4) * 8) + (lane & 7)) * 80 + ((lane >> 3) & 1) * 16);
    const uint32_t vaddr = (uint32_t)(((((lane >> 3) & 1) * 8) + (lane & 7)) * 80 + (lane >> 4) * 16);

    for (int kt = 0; kt < 4; kt++) {
        if (kt < 3) cpa_wait<1>(); else cpa_wait<0>();
        __syncthreads();
        if (kt + 2 < 4) {
            load_kv_stage(sb + AST_OFF + (uint32_t)((kt + 2) % 3) * AST_SZ, i, h, (kt + 2) * 64, tid);
            cpa_commit();
        }
        const uint32_t st = sb + AST_OFF + (uint32_t)(kt % 3) * AST_SZ;

        #pragma unroll
        for (int ch = 0; ch < 4; ch++) {
            const uint32_t roff = (uint32_t)(ch * 16 * 80);

            float s[2][2][4];
            #pragma unroll
            for (int nt = 0; nt < 2; nt++)
                #pragma unroll
                for (int mf = 0; mf < 2; mf++)
                    #pragma unroll
                    for (int q = 0; q < 4; q++) s[nt][mf][q] = 0.f;

            #pragma unroll
            for (int ks = 0; ks < 2; ks++) {
                uint32_t bh[2][2], bl[2][2], r[4];
                ldsm4(r, st + roff + kaddr + (uint32_t)(ks * 32));
                bh[0][0] = r[0]; bh[0][1] = r[1]; bh[1][0] = r[2]; bh[1][1] = r[3];
                ldsm4(r, st + 5120u + roff + kaddr + (uint32_t)(ks * 32));
                bl[0][0] = r[0]; bl[0][1] = r[1]; bl[1][0] = r[2]; bl[1][1] = r[3];
                #pragma unroll
                for (int nt = 0; nt < 2; nt++)
                    #pragma unroll
                    for (int mf = 0; mf < 2; mf++) {
                        mma_f16(s[nt][mf], qf[mf][ks], bh[nt]);
                        mma_f16(s[nt][mf], qf[mf][ks], bl[nt]);
                    }
            }

            uint32_t vhf[4][2], vlf[4][2];
            #pragma unroll
            for (int np2 = 0; np2 < 2; np2++) {
                uint32_t r[4];
                ldsm4t(r, st + 10240u + roff + vaddr + (uint32_t)(np2 * 32));
                vhf[2 * np2][0] = r[0]; vhf[2 * np2][1] = r[1];
                vhf[2 * np2 + 1][0] = r[2]; vhf[2 * np2 + 1][1] = r[3];
                ldsm4t(r, st + 15360u + roff + vaddr + (uint32_t)(np2 * 32));
                vlf[2 * np2][0] = r[0]; vlf[2 * np2][1] = r[1];
                vlf[2 * np2 + 1][0] = r[2]; vlf[2 * np2 + 1][1] = r[3];
            }

            #pragma unroll
            for (int mf = 0; mf < 2; mf++) {
                float* sa = s[0][mf];
                float* sc = s[1][mf];
                sa[0] = ex2f(sa[0]); sa[1] = ex2f(sa[1]);
                sa[2] = ex2f(sa[2]); sa[3] = ex2f(sa[3]);
                sc[0] = ex2f(sc[0]); sc[1] = ex2f(sc[1]);
                sc[2] = ex2f(sc[2]); sc[3] = ex2f(sc[3]);
                lsum[mf][0] += sa[0] + sa[1] + sc[0] + sc[1];
                lsum[mf][1] += sa[2] + sa[3] + sc[2] + sc[3];
                uint32_t pA[4];
                pA[0] = h2pack(sa[0], sa[1]);
                pA[1] = h2pack(sa[2], sa[3]);
                pA[2] = h2pack(sc[0], sc[1]);
                pA[3] = h2pack(sc[2], sc[3]);
                #pragma unroll
                for (int nf = 0; nf < 4; nf++) {
                    mma_f16(o[mf][nf], pA, vhf[nf]);
                    mma_f16(o[mf][nf], pA, vlf[nf]);
                }
            }
        }
    }

    #pragma unroll
    for (int mf = 0; mf < 2; mf++) {
        float l0 = lsum[mf][0], l1 = lsum[mf][1];
        l0 += __shfl_xor_sync(0xFFFFFFFFu, l0, 1);
        l0 += __shfl_xor_sync(0xFFFFFFFFu, l0, 2);
        l1 += __shfl_xor_sync(0xFFFFFFFFu, l1, 1);
        l1 += __shfl_xor_sync(0xFFFFFFFFu, l1, 2);
        const float inv0 = 1.f / l0;
        const float inv1 = 1.f / l1;

        const int row = wq * 32 + mf * 16 + (lane >> 2);
        const size_t M0 = ((size_t)row * I_DIM + i) * CS + h * HD;
        const size_t M1 = ((size_t)(row + 8) * I_DIM + i) * CS + h * HD;
        #pragma unroll
        for (int nf = 0; nf < 4; nf++) {
            const int col = nf * 8 + (lane & 3) * 2;
            const float2 g0 = *(const float2*)(g_g + M0 + col);
            const float2 g1 = *(const float2*)(g_g + M1 + col);
            *(uint32_t*)(g_gv + M0 + col) =
                h2pack(o[mf][nf][0] * inv0 * g0.x, o[mf][nf][1] * inv0 * g0.y);
            *(uint32_t*)(g_gv + M1 + col) =
                h2pack(o[mf][nf][2] * inv1 * g1.x, o[mf][nf][3] * inv1 * g1.y);
        }
    }
}

// ---------------------------------------------------------------------------
// Launch
// ---------------------------------------------------------------------------
extern "C" void kernel_launch(void* const* d_in, const int* in_sizes, int n_in,
                              void* d_out, int out_size)
{
    const float* msa   = (const float*)d_in[0];
    const float* gamma = (const float*)d_in[1];
    const float* beta  = (const float*)d_in[2];
    const float* Wq    = (const float*)d_in[3];
    const float* Wk    = (const float*)d_in[4];
    const float* Wv    = (const float*)d_in[5];
    const float* Wg    = (const float*)d_in[6];
    const float* bg    = (const float*)d_in[7];
    const float* Wo    = (const float*)d_in[8];
    const float* bo    = (const float*)d_in[9];
    float* out = (float*)d_out;

    cudaFuncSetAttribute(gemm_proj, cudaFuncAttributeMaxDynamicSharedMemorySize, GEMM_SMEM);
    cudaFuncSetAttribute(gemm_outp, cudaFuncAttributeMaxDynamicSharedMemorySize, GEMM_SMEM);
    cudaFuncSetAttribute(attn_kernel, cudaFuncAttributeMaxDynamicSharedMemorySize, ATTN_SMEM);

    ln_kernel<<<M_ROWS / 4, 256>>>(msa, gamma, beta);
    wprep_kernel<<<5 * 65536 / 256, 256>>>(Wq, Wk, Wv, Wg, Wo);

    gemm_proj<<<dim3(MBLOCKS, 2, 4), 256, GEMM_SMEM>>>(bg);

    attn_kernel<<<dim3(I_DIM, NH), 256, ATTN_SMEM>>>();

    gemm_outp<<<dim3(MBLOCKS, 2), 256, GEMM_SMEM>>>(bo, out);
}

// round 10
// speedup vs baseline: 1.4873x; 1.0874x over previous
#include <cuda_runtime.h>
#include <cuda_fp16.h>
#include <cstdint>
#include <math.h>

#define S_DIM 256
#define I_DIM 256
#define CS    256
#define NH    8
#define HD    32
#define M_ROWS 65536
#define MBLOCKS 512
#define QSCALE 0.2550349f   /* log2(e) / sqrt(32) */

// ---------------------------------------------------------------------------
// Scratch (device globals). A-operands plain fp16; K/W split hi/lo; V,G fp16.
// ---------------------------------------------------------------------------
__device__ __align__(16) __half g_x   [M_ROWS * CS];
__device__ __align__(16) __half g_gv  [M_ROWS * CS];
__device__ __align__(16) __half g_q   [M_ROWS * CS];
__device__ __align__(16) __half g_k_hi[M_ROWS * CS];
__device__ __align__(16) __half g_k_lo[M_ROWS * CS];
__device__ __align__(16) __half g_v   [M_ROWS * CS];
__device__ __align__(16) __half g_g   [M_ROWS * CS];
__device__ __align__(16) __half g_wt_hi[5 * CS * CS];   // [w][k][n]
__device__ __align__(16) __half g_wt_lo[5 * CS * CS];

// ---------------------------------------------------------------------------
// Helpers
// ---------------------------------------------------------------------------
__device__ __forceinline__ uint32_t smem_u32(const void* p) {
    uint32_t a;
    asm("{ .reg .u64 t; cvta.to.shared.u64 t, %1; cvt.u32.u64 %0, t; }" : "=r"(a) : "l"(p));
    return a;
}
__device__ __forceinline__ void cpa16(uint32_t dst, const void* src) {
    asm volatile("{ .reg .u64 g; cvta.to.global.u64 g, %1;"
                 "  cp.async.cg.shared.global [%0], [g], 16; }"
                 :: "r"(dst), "l"(src) : "memory");
}
__device__ __forceinline__ void cpa_commit() {
    asm volatile("cp.async.commit_group;" ::: "memory");
}
template <int N>
__device__ __forceinline__ void cpa_wait() {
    asm volatile("cp.async.wait_group %0;" :: "n"(N) : "memory");
}
__device__ __forceinline__ void ldsm4(uint32_t* r, uint32_t addr) {
    asm volatile("ldmatrix.sync.aligned.m8n8.x4.shared.b16 {%0,%1,%2,%3}, [%4];"
                 : "=r"(r[0]), "=r"(r[1]), "=r"(r[2]), "=r"(r[3]) : "r"(addr));
}
__device__ __forceinline__ void ldsm4t(uint32_t* r, uint32_t addr) {
    asm volatile("ldmatrix.sync.aligned.m8n8.x4.trans.shared.b16 {%0,%1,%2,%3}, [%4];"
                 : "=r"(r[0]), "=r"(r[1]), "=r"(r[2]), "=r"(r[3]) : "r"(addr));
}
__device__ __forceinline__ void mma_f16(float* c, const uint32_t* a, const uint32_t* b) {
    asm volatile("mma.sync.aligned.m16n8k16.row.col.f32.f16.f16.f32 "
                 "{%0,%1,%2,%3}, {%4,%5,%6,%7}, {%8,%9}, {%0,%1,%2,%3};"
                 : "+f"(c[0]), "+f"(c[1]), "+f"(c[2]), "+f"(c[3])
                 : "r"(a[0]), "r"(a[1]), "r"(a[2]), "r"(a[3]), "r"(b[0]), "r"(b[1]));
}
__device__ __forceinline__ uint32_t h2pack(float a, float b) {
    __half2 t = __floats2half2_rn(a, b);
    return *reinterpret_cast<uint32_t*>(&t);
}
__device__ __forceinline__ void split2h(float a, float b, uint32_t& hi, uint32_t& lo) {
    __half2 t = __floats2half2_rn(a, b);
    hi = *reinterpret_cast<uint32_t*>(&t);
    __half2 t2 = __floats2half2_rn(a - __low2float(t), b - __high2float(t));
    lo = *reinterpret_cast<uint32_t*>(&t2);
}
__device__ __forceinline__ float ex2f(float x) {
    float r;
    asm("ex2.approx.f32 %0, %1;" : "=f"(r) : "f"(x));
    return r;
}

// ---------------------------------------------------------------------------
// Kernel 1: LayerNorm -> plain fp16
// ---------------------------------------------------------------------------
__global__ void __launch_bounds__(256) ln_kernel(const float* __restrict__ msa,
                                                 const float* __restrict__ gamma,
                                                 const float* __restrict__ beta)
{
    __shared__ float p1[8], p2[8];
    const int tid = threadIdx.x;
    const int r = tid >> 6;
    const int t = tid & 63;
    const int row = blockIdx.x * 4 + r;

    const float4 v = *(const float4*)(msa + (size_t)row * CS + t * 4);
    float s1 = v.x + v.y + v.z + v.w;
    float s2 = v.x * v.x + v.y * v.y + v.z * v.z + v.w * v.w;
    #pragma unroll
    for (int o = 16; o > 0; o >>= 1) {
        s1 += __shfl_xor_sync(0xFFFFFFFFu, s1, o);
        s2 += __shfl_xor_sync(0xFFFFFFFFu, s2, o);
    }
    if ((tid & 31) == 0) { p1[tid >> 5] = s1; p2[tid >> 5] = s2; }
    __syncthreads();
    const float a = p1[2 * r] + p1[2 * r + 1];
    const float b = p2[2 * r] + p2[2 * r + 1];
    const float mu = a * (1.0f / CS);
    const float var = b * (1.0f / CS) - mu * mu;
    const float rstd = rsqrtf(var + 1e-5f);

    const float4 gm = *(const float4*)(gamma + t * 4);
    const float4 bt = *(const float4*)(beta + t * 4);
    const float y0 = (v.x - mu) * rstd * gm.x + bt.x;
    const float y1 = (v.y - mu) * rstd * gm.y + bt.y;
    const float y2 = (v.z - mu) * rstd * gm.z + bt.z;
    const float y3 = (v.w - mu) * rstd * gm.w + bt.w;

    *(uint2*)(g_x + (size_t)row * CS + t * 4) = make_uint2(h2pack(y0, y1), h2pack(y2, y3));
}

// ---------------------------------------------------------------------------
// Kernel 2: weight split to fp16 hi/lo
// ---------------------------------------------------------------------------
__global__ void __launch_bounds__(256) wprep_kernel(const float* __restrict__ Wq,
                                                    const float* __restrict__ Wk,
                                                    const float* __restrict__ Wv,
                                                    const float* __restrict__ Wg,
                                                    const float* __restrict__ Wo)
{
    const int idx = blockIdx.x * 256 + threadIdx.x;
    const int w = idx >> 16;
    const int e = idx & 65535;
    const float* W = (w == 0) ? Wq : (w == 1) ? Wk : (w == 2) ? Wv : (w == 3) ? Wg : Wo;
    const float val = W[e];
    const __half h = __float2half_rn(val);
    g_wt_hi[idx] = h;
    g_wt_lo[idx] = __float2half_rn(val - __half2float(h));
}

// ---------------------------------------------------------------------------
// HMMA GEMM: C[128,128] = A[128,256] @ W[256,128-slice], fp16 A, W split hi/lo.
// 256 threads / 8 warps (2m x 4n), warp tile 64x32, BK=16, 3-stage, 2 CTAs/SM.
// mode: 0 = QSCALE + fp16 single, 1 = fp16 split hi/lo,
//       2 = sigmoid(x+bias) fp16, 3 = x+bias fp32, 4 = plain fp16 single
// ---------------------------------------------------------------------------
#define GB_OFF  6144u
#define GB_TERM 4352u
#define GSTAGE  14848u
#define GEMM_SMEM (3 * 14848)

__device__ __forceinline__ void gemm_load_stage(uint32_t st, int ks, int tid,
                                                int mblk, int nblk,
                                                const __half* __restrict__ aP,
                                                const __half* __restrict__ bH,
                                                const __half* __restrict__ bL)
{
    const int ar = tid >> 1, ac = tid & 1;
    cpa16(st + (uint32_t)(ar * 48 + ac * 16),
          aP + (size_t)(mblk * 128 + ar) * CS + ks * 16 + ac * 8);
    const int row = tid >> 4, col = tid & 15;
    const uint32_t bdst = st + GB_OFF + (uint32_t)(row * 272 + col * 16);
    const size_t bsrc = (size_t)(ks * 16 + row) * CS + nblk * 128 + col * 8;
    cpa16(bdst, bH + bsrc);
    cpa16(bdst + GB_TERM, bL + bsrc);
}

__device__ __forceinline__ void gemm_body(const __half* __restrict__ aP,
                                          const __half* __restrict__ bH,
                                          const __half* __restrict__ bL,
                                          const float* __restrict__ bias,
                                          float* __restrict__ Cf,
                                          __half* __restrict__ Chi,
                                          __half* __restrict__ Clo,
                                          int mode, int mblk, int nblk)
{
    extern __shared__ unsigned char smem[];
    const uint32_t sb = smem_u32(smem);
    const int tid = threadIdx.x;
    const int lane = tid & 31;
    const int wid = tid >> 5;
    const int wm = wid >> 2;
    const int wn = wid & 3;

    float acc[4][4][4];
    #pragma unroll
    for (int i = 0; i < 4; i++)
        #pragma unroll
        for (int j = 0; j < 4; j++)
            #pragma unroll
            for (int q = 0; q < 4; q++) acc[i][j][q] = 0.f;

    gemm_load_stage(sb,          0, tid, mblk, nblk, aP, bH, bL);
    cpa_commit();
    gemm_load_stage(sb + GSTAGE, 1, tid, mblk, nblk, aP, bH, bL);
    cpa_commit();

    const uint32_t aRowSel = (uint32_t)((wm * 64 + (lane & 15)) * 48 + (lane >> 4) * 16);
    const uint32_t bColSel = (uint32_t)((lane & 15) * 272 + (wn * 32 + (lane >> 4) * 8) * 2);

    for (int ks = 0; ks < 16; ks++) {
        if (ks < 15) cpa_wait<1>(); else cpa_wait<0>();
        __syncthreads();
        if (ks + 2 < 16) {
            gemm_load_stage(sb + (uint32_t)((ks + 2) % 3) * GSTAGE, ks + 2, tid,
                            mblk, nblk, aP, bH, bL);
            cpa_commit();
        }
        const uint32_t st = sb + (uint32_t)(ks % 3) * GSTAGE;

        uint32_t Af[4][4], Bh[4][2], Bl[4][2];
        #pragma unroll
        for (int mf = 0; mf < 4; mf++)
            ldsm4(Af[mf], st + aRowSel + (uint32_t)(mf * 16 * 48));
        const uint32_t bBase = st + GB_OFF + bColSel;
        #pragma unroll
        for (int g = 0; g < 2; g++) {
            uint32_t r[4];
            ldsm4t(r, bBase + (uint32_t)(g * 32));
            Bh[2 * g][0] = r[0]; Bh[2 * g][1] = r[1];
            Bh[2 * g + 1][0] = r[2]; Bh[2 * g + 1][1] = r[3];
            ldsm4t(r, bBase + GB_TERM + (uint32_t)(g * 32));
            Bl[2 * g][0] = r[0]; Bl[2 * g][1] = r[1];
            Bl[2 * g + 1][0] = r[2]; Bl[2 * g + 1][1] = r[3];
        }
        #pragma unroll
        for (int mf = 0; mf < 4; mf++)
            #pragma unroll
            for (int nf = 0; nf < 4; nf++)
                mma_f16(acc[mf][nf], Af[mf], Bh[nf]);
        #pragma unroll
        for (int mf = 0; mf < 4; mf++)
            #pragma unroll
            for (int nf = 0; nf < 4; nf++)
                mma_f16(acc[mf][nf], Af[mf], Bl[nf]);
    }

    // ---- epilogue ----
    const int r0 = mblk * 128 + wm * 64 + (lane >> 2);
    const int c0 = nblk * 128 + wn * 32 + (lane & 3) * 2;
    #pragma unroll
    for (int mf = 0; mf < 4; mf++) {
        #pragma unroll
        for (int nf = 0; nf < 4; nf++) {
            const int n = c0 + nf * 8;
            const int m = r0 + mf * 16;
            float v0 = acc[mf][nf][0], v1 = acc[mf][nf][1];
            float v2 = acc[mf][nf][2], v3 = acc[mf][nf][3];
            if (mode == 0) {
                *(uint32_t*)(Chi + (size_t)m * CS + n)       = h2pack(v0 * QSCALE, v1 * QSCALE);
                *(uint32_t*)(Chi + (size_t)(m + 8) * CS + n) = h2pack(v2 * QSCALE, v3 * QSCALE);
            } else if (mode == 4) {
                *(uint32_t*)(Chi + (size_t)m * CS + n)       = h2pack(v0, v1);
                *(uint32_t*)(Chi + (size_t)(m + 8) * CS + n) = h2pack(v2, v3);
            } else if (mode == 1) {
                uint32_t h0, l0, h1, l1;
                split2h(v0, v1, h0, l0);
                split2h(v2, v3, h1, l1);
                *(uint32_t*)(Chi + (size_t)m * CS + n)       = h0;
                *(uint32_t*)(Clo + (size_t)m * CS + n)       = l0;
                *(uint32_t*)(Chi + (size_t)(m + 8) * CS + n) = h1;
                *(uint32_t*)(Clo + (size_t)(m + 8) * CS + n) = l1;
            } else if (mode == 2) {
                const float b0 = __ldg(bias + n), b1 = __ldg(bias + n + 1);
                v0 = 1.f / (1.f + __expf(-(v0 + b0)));
                v1 = 1.f / (1.f + __expf(-(v1 + b1)));
                v2 = 1.f / (1.f + __expf(-(v2 + b0)));
                v3 = 1.f / (1.f + __expf(-(v3 + b1)));
                *(uint32_t*)(Chi + (size_t)m * CS + n)       = h2pack(v0, v1);
                *(uint32_t*)(Chi + (size_t)(m + 8) * CS + n) = h2pack(v2, v3);
            } else {
                const float b0 = __ldg(bias + n), b1 = __ldg(bias + n + 1);
                *(float2*)(Cf + (size_t)m * CS + n)       = make_float2(v0 + b0, v1 + b1);
                *(float2*)(Cf + (size_t)(m + 8) * CS + n) = make_float2(v2 + b0, v3 + b1);
            }
        }
    }
}

__global__ void __launch_bounds__(256, 2) gemm_proj(const float* __restrict__ bg)
{
    const int w = blockIdx.z;
    const __half* bh = g_wt_hi + (size_t)w * 65536;
    const __half* bl = g_wt_lo + (size_t)w * 65536;
    if (w == 0)
        gemm_body(g_x, bh, bl, nullptr, nullptr, g_q, nullptr, 0, blockIdx.x, blockIdx.y);
    else if (w == 1)
        gemm_body(g_x, bh, bl, nullptr, nullptr, g_k_hi, g_k_lo, 1, blockIdx.x, blockIdx.y);
    else if (w == 2)
        gemm_body(g_x, bh, bl, nullptr, nullptr, g_v, nullptr, 4, blockIdx.x, blockIdx.y);
    else
        gemm_body(g_x, bh, bl, bg, nullptr, g_g, nullptr, 2, blockIdx.x, blockIdx.y);
}

__global__ void __launch_bounds__(256, 2) gemm_outp(const float* __restrict__ bo,
                                                    float* __restrict__ out)
{
    gemm_body(g_gv, g_wt_hi + (size_t)4 * 65536, g_wt_lo + (size_t)4 * 65536,
              bo, out, nullptr, nullptr, 3, blockIdx.x, blockIdx.y);
}

// ---------------------------------------------------------------------------
// Kernel 3: tensor-core column attention.
// Block = one (i, h). 256 thr = 8 warps, 32 queries/warp, 2 CTAs/SM.
// K split hi/lo; V single fp16 (PV uses Vh only). Gate fp16.
// Stage = Kh, Kl, V @ 64 rows x 80B = 15360 B.
// ---------------------------------------------------------------------------
#define AQ_SZ   20480u
#define AST_OFF 20480u
#define AST_SZ  15360u
#define ATTN_SMEM (20480 + 3 * 15360)

__device__ __forceinline__ void load_kv_stage(uint32_t stbase, int i, int h, int t0, int tid)
{
    #pragma unroll
    for (int j = 0; j < 3; j++) {
        const int u = tid + 256 * j;
        const int arr = u >> 8;             // 0:Kh 1:Kl 2:V
        const int rem = u & 255;
        const int row = rem >> 2;
        const int c = rem & 3;
        const __half* base = (arr == 0) ? g_k_hi : (arr == 1) ? g_k_lo : g_v;
        const __half* src = base + ((size_t)(t0 + row) * I_DIM + i) * CS + h * HD + c * 8;
        cpa16(stbase + (uint32_t)(arr * 5120 + row * 80 + c * 16), src);
    }
}

__global__ void __launch_bounds__(256, 2) attn_kernel()
{
    extern __shared__ unsigned char sm[];
    const uint32_t sb = smem_u32(sm);
    const int i = blockIdx.x;
    const int h = blockIdx.y;
    const int tid = threadIdx.x;
    const int lane = tid & 31;
    const int wq = tid >> 5;

    #pragma unroll
    for (int j = 0; j < 4; j++) {
        const int u = tid + 256 * j;
        const int row = u >> 2, c = u & 3;
        cpa16(sb + (uint32_t)(row * 80 + c * 16),
              g_q + ((size_t)row * I_DIM + i) * CS + h * HD + c * 8);
    }
    cpa_commit();
    load_kv_stage(sb + AST_OFF, i, h, 0, tid);
    cpa_commit();
    load_kv_stage(sb + AST_OFF + AST_SZ, i, h, 64, tid);
    cpa_commit();

    cpa_wait<2>();
    __syncthreads();

    uint32_t qf[2][2][4];
    #pragma unroll
    for (int mf = 0; mf < 2; mf++) {
        const uint32_t qrow = (uint32_t)((wq * 32 + mf * 16 + (lane & 15)) * 80
                                         + (lane >> 4) * 16);
        ldsm4(qf[mf][0], sb + qrow);
        ldsm4(qf[mf][1], sb + qrow + 32u);
    }

    float o[2][4][4];
    #pragma unroll
    for (int mf = 0; mf < 2; mf++)
        #pragma unroll
        for (int nf = 0; nf < 4; nf++)
            #pragma unroll
            for (int q = 0; q < 4; q++) o[mf][nf][q] = 0.f;
    float lsum[2][2] = {{0.f, 0.f}, {0.f, 0.f}};

    const uint32_t kaddr = (uint32_t)((((lane >> 4) * 8) + (lane & 7)) * 80 + ((lane >> 3) & 1) * 16);
    const uint32_t vaddr = (uint32_t)(((((lane >> 3) & 1) * 8) + (lane & 7)) * 80 + (lane >> 4) * 16);

    for (int kt = 0; kt < 4; kt++) {
        if (kt < 3) cpa_wait<1>(); else cpa_wait<0>();
        __syncthreads();
        if (kt + 2 < 4) {
            load_kv_stage(sb + AST_OFF + (uint32_t)((kt + 2) % 3) * AST_SZ, i, h, (kt + 2) * 64, tid);
            cpa_commit();
        }
        const uint32_t st = sb + AST_OFF + (uint32_t)(kt % 3) * AST_SZ;

        #pragma unroll
        for (int ch = 0; ch < 4; ch++) {
            const uint32_t roff = (uint32_t)(ch * 16 * 80);

            float s[2][2][4];
            #pragma unroll
            for (int nt = 0; nt < 2; nt++)
                #pragma unroll
                for (int mf = 0; mf < 2; mf++)
                    #pragma unroll
                    for (int q = 0; q < 4; q++) s[nt][mf][q] = 0.f;

            #pragma unroll
            for (int ks = 0; ks < 2; ks++) {
                uint32_t bh[2][2], bl[2][2], r[4];
                ldsm4(r, st + roff + kaddr + (uint32_t)(ks * 32));
                bh[0][0] = r[0]; bh[0][1] = r[1]; bh[1][0] = r[2]; bh[1][1] = r[3];
                ldsm4(r, st + 5120u + roff + kaddr + (uint32_t)(ks * 32));
                bl[0][0] = r[0]; bl[0][1] = r[1]; bl[1][0] = r[2]; bl[1][1] = r[3];
                #pragma unroll
                for (int nt = 0; nt < 2; nt++)
                    #pragma unroll
                    for (int mf = 0; mf < 2; mf++) {
                        mma_f16(s[nt][mf], qf[mf][ks], bh[nt]);
                        mma_f16(s[nt][mf], qf[mf][ks], bl[nt]);
                    }
            }

            // V fragments (single fp16) for this 16-key chunk
            uint32_t vhf[4][2];
            #pragma unroll
            for (int np2 = 0; np2 < 2; np2++) {
                uint32_t r[4];
                ldsm4t(r, st + 10240u + roff + vaddr + (uint32_t)(np2 * 32));
                vhf[2 * np2][0] = r[0]; vhf[2 * np2][1] = r[1];
                vhf[2 * np2 + 1][0] = r[2]; vhf[2 * np2 + 1][1] = r[3];
            }

            #pragma unroll
            for (int mf = 0; mf < 2; mf++) {
                float* sa = s[0][mf];
                float* sc = s[1][mf];
                sa[0] = ex2f(sa[0]); sa[1] = ex2f(sa[1]);
                sa[2] = ex2f(sa[2]); sa[3] = ex2f(sa[3]);
                sc[0] = ex2f(sc[0]); sc[1] = ex2f(sc[1]);
                sc[2] = ex2f(sc[2]); sc[3] = ex2f(sc[3]);
                lsum[mf][0] += sa[0] + sa[1] + sc[0] + sc[1];
                lsum[mf][1] += sa[2] + sa[3] + sc[2] + sc[3];
                uint32_t pA[4];
                pA[0] = h2pack(sa[0], sa[1]);
                pA[1] = h2pack(sa[2], sa[3]);
                pA[2] = h2pack(sc[0], sc[1]);
                pA[3] = h2pack(sc[2], sc[3]);
                #pragma unroll
                for (int nf = 0; nf < 4; nf++)
                    mma_f16(o[mf][nf], pA, vhf[nf]);
            }
        }
    }

    // ---- epilogue: quad-reduce lsum, normalize, gate (fp16), fp16 store ----
    #pragma unroll
    for (int mf = 0; mf < 2; mf++) {
        float l0 = lsum[mf][0], l1 = lsum[mf][1];
        l0 += __shfl_xor_sync(0xFFFFFFFFu, l0, 1);
        l0 += __shfl_xor_sync(0xFFFFFFFFu, l0, 2);
        l1 += __shfl_xor_sync(0xFFFFFFFFu, l1, 1);
        l1 += __shfl_xor_sync(0xFFFFFFFFu, l1, 2);
        const float inv0 = 1.f / l0;
        const float inv1 = 1.f / l1;

        const int row = wq * 32 + mf * 16 + (lane >> 2);
        const size_t M0 = ((size_t)row * I_DIM + i) * CS + h * HD;
        const size_t M1 = ((size_t)(row + 8) * I_DIM + i) * CS + h * HD;
        #pragma unroll
        for (int nf = 0; nf < 4; nf++) {
            const int col = nf * 8 + (lane & 3) * 2;
            const float2 g0 = __half22float2(*(const __half2*)(g_g + M0 + col));
            const float2 g1 = __half22float2(*(const __half2*)(g_g + M1 + col));
            *(uint32_t*)(g_gv + M0 + col) =
                h2pack(o[mf][nf][0] * inv0 * g0.x, o[mf][nf][1] * inv0 * g0.y);
            *(uint32_t*)(g_gv + M1 + col) =
                h2pack(o[mf][nf][2] * inv1 * g1.x, o[mf][nf][3] * inv1 * g1.y);
        }
    }
}

// ---------------------------------------------------------------------------
// Launch
// ---------------------------------------------------------------------------
extern "C" void kernel_launch(void* const* d_in, const int* in_sizes, int n_in,
                              void* d_out, int out_size)
{
    const float* msa   = (const float*)d_in[0];
    const float* gamma = (const float*)d_in[1];
    const float* beta  = (const float*)d_in[2];
    const float* Wq    = (const float*)d_in[3];
    const float* Wk    = (const float*)d_in[4];
    const float* Wv    = (const float*)d_in[5];
    const float* Wg    = (const float*)d_in[6];
    const float* bg    = (const float*)d_in[7];
    const float* Wo    = (const float*)d_in[8];
    const float* bo    = (const float*)d_in[9];
    float* out = (float*)d_out;

    cudaFuncSetAttribute(gemm_proj, cudaFuncAttributeMaxDynamicSharedMemorySize, GEMM_SMEM);
    cudaFuncSetAttribute(gemm_outp, cudaFuncAttributeMaxDynamicSharedMemorySize, GEMM_SMEM);
    cudaFuncSetAttribute(attn_kernel, cudaFuncAttributeMaxDynamicSharedMemorySize, ATTN_SMEM);

    ln_kernel<<<M_ROWS / 4, 256>>>(msa, gamma, beta);
    wprep_kernel<<<5 * 65536 / 256, 256>>>(Wq, Wk, Wv, Wg, Wo);

    gemm_proj<<<dim3(MBLOCKS, 2, 4), 256, GEMM_SMEM>>>(bg);

    attn_kernel<<<dim3(I_DIM, NH), 256, ATTN_SMEM>>>();

    gemm_outp<<<dim3(MBLOCKS, 2), 256, GEMM_SMEM>>>(bo, out);
}

// round 11
// speedup vs baseline: 1.6693x; 1.1223x over previous
#include <cuda_runtime.h>
#include <cuda_fp16.h>
#include <cstdint>
#include <math.h>

#define S_DIM 256
#define I_DIM 256
#define CS    256
#define NH    8
#define HD    32
#define M_ROWS 65536
#define MBLOCKS 512
#define QSCALE 0.2550349f   /* log2(e) / sqrt(32) */

// ---------------------------------------------------------------------------
// Scratch (device globals). Q/K/V/G/gv plain fp16; weights split hi/lo.
// ---------------------------------------------------------------------------
__device__ __align__(16) __half g_x   [M_ROWS * CS];
__device__ __align__(16) __half g_gv  [M_ROWS * CS];
__device__ __align__(16) __half g_q   [M_ROWS * CS];
__device__ __align__(16) __half g_k   [M_ROWS * CS];
__device__ __align__(16) __half g_v   [M_ROWS * CS];
__device__ __align__(16) __half g_g   [M_ROWS * CS];
__device__ __align__(16) __half g_wt_hi[5 * CS * CS];   // [w][k][n]
__device__ __align__(16) __half g_wt_lo[5 * CS * CS];

// ---------------------------------------------------------------------------
// Helpers
// ---------------------------------------------------------------------------
__device__ __forceinline__ uint32_t smem_u32(const void* p) {
    uint32_t a;
    asm("{ .reg .u64 t; cvta.to.shared.u64 t, %1; cvt.u32.u64 %0, t; }" : "=r"(a) : "l"(p));
    return a;
}
__device__ __forceinline__ void cpa16(uint32_t dst, const void* src) {
    asm volatile("{ .reg .u64 g; cvta.to.global.u64 g, %1;"
                 "  cp.async.cg.shared.global [%0], [g], 16; }"
                 :: "r"(dst), "l"(src) : "memory");
}
__device__ __forceinline__ void cpa_commit() {
    asm volatile("cp.async.commit_group;" ::: "memory");
}
template <int N>
__device__ __forceinline__ void cpa_wait() {
    asm volatile("cp.async.wait_group %0;" :: "n"(N) : "memory");
}
__device__ __forceinline__ void ldsm4(uint32_t* r, uint32_t addr) {
    asm volatile("ldmatrix.sync.aligned.m8n8.x4.shared.b16 {%0,%1,%2,%3}, [%4];"
                 : "=r"(r[0]), "=r"(r[1]), "=r"(r[2]), "=r"(r[3]) : "r"(addr));
}
__device__ __forceinline__ void ldsm4t(uint32_t* r, uint32_t addr) {
    asm volatile("ldmatrix.sync.aligned.m8n8.x4.trans.shared.b16 {%0,%1,%2,%3}, [%4];"
                 : "=r"(r[0]), "=r"(r[1]), "=r"(r[2]), "=r"(r[3]) : "r"(addr));
}
__device__ __forceinline__ void mma_f16(float* c, const uint32_t* a, const uint32_t* b) {
    asm volatile("mma.sync.aligned.m16n8k16.row.col.f32.f16.f16.f32 "
                 "{%0,%1,%2,%3}, {%4,%5,%6,%7}, {%8,%9}, {%0,%1,%2,%3};"
                 : "+f"(c[0]), "+f"(c[1]), "+f"(c[2]), "+f"(c[3])
                 : "r"(a[0]), "r"(a[1]), "r"(a[2]), "r"(a[3]), "r"(b[0]), "r"(b[1]));
}
__device__ __forceinline__ uint32_t h2pack(float a, float b) {
    __half2 t = __floats2half2_rn(a, b);
    return *reinterpret_cast<uint32_t*>(&t);
}
__device__ __forceinline__ float ex2f(float x) {
    float r;
    asm("ex2.approx.f32 %0, %1;" : "=f"(r) : "f"(x));
    return r;
}

// ---------------------------------------------------------------------------
// Kernel 1: LayerNorm -> plain fp16
// ---------------------------------------------------------------------------
__global__ void __launch_bounds__(256) ln_kernel(const float* __restrict__ msa,
                                                 const float* __restrict__ gamma,
                                                 const float* __restrict__ beta)
{
    __shared__ float p1[8], p2[8];
    const int tid = threadIdx.x;
    const int r = tid >> 6;
    const int t = tid & 63;
    const int row = blockIdx.x * 4 + r;

    const float4 v = *(const float4*)(msa + (size_t)row * CS + t * 4);
    float s1 = v.x + v.y + v.z + v.w;
    float s2 = v.x * v.x + v.y * v.y + v.z * v.z + v.w * v.w;
    #pragma unroll
    for (int o = 16; o > 0; o >>= 1) {
        s1 += __shfl_xor_sync(0xFFFFFFFFu, s1, o);
        s2 += __shfl_xor_sync(0xFFFFFFFFu, s2, o);
    }
    if ((tid & 31) == 0) { p1[tid >> 5] = s1; p2[tid >> 5] = s2; }
    __syncthreads();
    const float a = p1[2 * r] + p1[2 * r + 1];
    const float b = p2[2 * r] + p2[2 * r + 1];
    const float mu = a * (1.0f / CS);
    const float var = b * (1.0f / CS) - mu * mu;
    const float rstd = rsqrtf(var + 1e-5f);

    const float4 gm = *(const float4*)(gamma + t * 4);
    const float4 bt = *(const float4*)(beta + t * 4);
    const float y0 = (v.x - mu) * rstd * gm.x + bt.x;
    const float y1 = (v.y - mu) * rstd * gm.y + bt.y;
    const float y2 = (v.z - mu) * rstd * gm.z + bt.z;
    const float y3 = (v.w - mu) * rstd * gm.w + bt.w;

    *(uint2*)(g_x + (size_t)row * CS + t * 4) = make_uint2(h2pack(y0, y1), h2pack(y2, y3));
}

// ---------------------------------------------------------------------------
// Kernel 2: weight split to fp16 hi/lo
// ---------------------------------------------------------------------------
__global__ void __launch_bounds__(256) wprep_kernel(const float* __restrict__ Wq,
                                                    const float* __restrict__ Wk,
                                                    const float* __restrict__ Wv,
                                                    const float* __restrict__ Wg,
                                                    const float* __restrict__ Wo)
{
    const int idx = blockIdx.x * 256 + threadIdx.x;
    const int w = idx >> 16;
    const int e = idx & 65535;
    const float* W = (w == 0) ? Wq : (w == 1) ? Wk : (w == 2) ? Wv : (w == 3) ? Wg : Wo;
    const float val = W[e];
    const __half h = __float2half_rn(val);
    g_wt_hi[idx] = h;
    g_wt_lo[idx] = __float2half_rn(val - __half2float(h));
}

// ---------------------------------------------------------------------------
// HMMA GEMM: C[128,128] = A[128,256] @ W[256,128-slice], fp16 A.
// TWO=true: W split hi/lo (2 MMA passes); TWO=false: W hi only.
// 256 threads / 8 warps (2m x 4n), warp tile 64x32, BK=16, 3-stage, 2 CTAs/SM.
// mode: 0 = QSCALE + fp16, 4 = plain fp16, 2 = sigmoid(x+bias) fp16,
//       3 = x+bias fp32
// ---------------------------------------------------------------------------
#define GB_OFF  6144u
#define GB_TERM 4352u
#define GSTAGE  14848u
#define GEMM_SMEM (3 * 14848)

template <bool TWO>
__device__ __forceinline__ void gemm_load_stage(uint32_t st, int ks, int tid,
                                                int mblk, int nblk,
                                                const __half* __restrict__ aP,
                                                const __half* __restrict__ bH,
                                                const __half* __restrict__ bL)
{
    const int ar = tid >> 1, ac = tid & 1;
    cpa16(st + (uint32_t)(ar * 48 + ac * 16),
          aP + (size_t)(mblk * 128 + ar) * CS + ks * 16 + ac * 8);
    const int row = tid >> 4, col = tid & 15;
    const uint32_t bdst = st + GB_OFF + (uint32_t)(row * 272 + col * 16);
    const size_t bsrc = (size_t)(ks * 16 + row) * CS + nblk * 128 + col * 8;
    cpa16(bdst, bH + bsrc);
    if (TWO) cpa16(bdst + GB_TERM, bL + bsrc);
}

template <bool TWO>
__device__ __forceinline__ void gemm_body(const __half* __restrict__ aP,
                                          const __half* __restrict__ bH,
                                          const __half* __restrict__ bL,
                                          const float* __restrict__ bias,
                                          float* __restrict__ Cf,
                                          __half* __restrict__ Ch,
                                          int mode, int mblk, int nblk)
{
    extern __shared__ unsigned char smem[];
    const uint32_t sb = smem_u32(smem);
    const int tid = threadIdx.x;
    const int lane = tid & 31;
    const int wid = tid >> 5;
    const int wm = wid >> 2;
    const int wn = wid & 3;

    float acc[4][4][4];
    #pragma unroll
    for (int i = 0; i < 4; i++)
        #pragma unroll
        for (int j = 0; j < 4; j++)
            #pragma unroll
            for (int q = 0; q < 4; q++) acc[i][j][q] = 0.f;

    gemm_load_stage<TWO>(sb,          0, tid, mblk, nblk, aP, bH, bL);
    cpa_commit();
    gemm_load_stage<TWO>(sb + GSTAGE, 1, tid, mblk, nblk, aP, bH, bL);
    cpa_commit();

    const uint32_t aRowSel = (uint32_t)((wm * 64 + (lane & 15)) * 48 + (lane >> 4) * 16);
    const uint32_t bColSel = (uint32_t)((lane & 15) * 272 + (wn * 32 + (lane >> 4) * 8) * 2);

    for (int ks = 0; ks < 16; ks++) {
        if (ks < 15) cpa_wait<1>(); else cpa_wait<0>();
        __syncthreads();
        if (ks + 2 < 16) {
            gemm_load_stage<TWO>(sb + (uint32_t)((ks + 2) % 3) * GSTAGE, ks + 2, tid,
                                 mblk, nblk, aP, bH, bL);
            cpa_commit();
        }
        const uint32_t st = sb + (uint32_t)(ks % 3) * GSTAGE;

        uint32_t Af[4][4], Bh[4][2];
        #pragma unroll
        for (int mf = 0; mf < 4; mf++)
            ldsm4(Af[mf], st + aRowSel + (uint32_t)(mf * 16 * 48));
        const uint32_t bBase = st + GB_OFF + bColSel;
        #pragma unroll
        for (int g = 0; g < 2; g++) {
            uint32_t r[4];
            ldsm4t(r, bBase + (uint32_t)(g * 32));
            Bh[2 * g][0] = r[0]; Bh[2 * g][1] = r[1];
            Bh[2 * g + 1][0] = r[2]; Bh[2 * g + 1][1] = r[3];
        }
        #pragma unroll
        for (int mf = 0; mf < 4; mf++)
            #pragma unroll
            for (int nf = 0; nf < 4; nf++)
                mma_f16(acc[mf][nf], Af[mf], Bh[nf]);

        if (TWO) {
            uint32_t Bl[4][2];
            #pragma unroll
            for (int g = 0; g < 2; g++) {
                uint32_t r[4];
                ldsm4t(r, bBase + GB_TERM + (uint32_t)(g * 32));
                Bl[2 * g][0] = r[0]; Bl[2 * g][1] = r[1];
                Bl[2 * g + 1][0] = r[2]; Bl[2 * g + 1][1] = r[3];
            }
            #pragma unroll
            for (int mf = 0; mf < 4; mf++)
                #pragma unroll
                for (int nf = 0; nf < 4; nf++)
                    mma_f16(acc[mf][nf], Af[mf], Bl[nf]);
        }
    }

    // ---- epilogue ----
    const int r0 = mblk * 128 + wm * 64 + (lane >> 2);
    const int c0 = nblk * 128 + wn * 32 + (lane & 3) * 2;
    #pragma unroll
    for (int mf = 0; mf < 4; mf++) {
        #pragma unroll
        for (int nf = 0; nf < 4; nf++) {
            const int n = c0 + nf * 8;
            const int m = r0 + mf * 16;
            float v0 = acc[mf][nf][0], v1 = acc[mf][nf][1];
            float v2 = acc[mf][nf][2], v3 = acc[mf][nf][3];
            if (mode == 0) {
                *(uint32_t*)(Ch + (size_t)m * CS + n)       = h2pack(v0 * QSCALE, v1 * QSCALE);
                *(uint32_t*)(Ch + (size_t)(m + 8) * CS + n) = h2pack(v2 * QSCALE, v3 * QSCALE);
            } else if (mode == 4) {
                *(uint32_t*)(Ch + (size_t)m * CS + n)       = h2pack(v0, v1);
                *(uint32_t*)(Ch + (size_t)(m + 8) * CS + n) = h2pack(v2, v3);
            } else if (mode == 2) {
                const float b0 = __ldg(bias + n), b1 = __ldg(bias + n + 1);
                v0 = 1.f / (1.f + __expf(-(v0 + b0)));
                v1 = 1.f / (1.f + __expf(-(v1 + b1)));
                v2 = 1.f / (1.f + __expf(-(v2 + b0)));
                v3 = 1.f / (1.f + __expf(-(v3 + b1)));
                *(uint32_t*)(Ch + (size_t)m * CS + n)       = h2pack(v0, v1);
                *(uint32_t*)(Ch + (size_t)(m + 8) * CS + n) = h2pack(v2, v3);
            } else {
                const float b0 = __ldg(bias + n), b1 = __ldg(bias + n + 1);
                *(float2*)(Cf + (size_t)m * CS + n)       = make_float2(v0 + b0, v1 + b1);
                *(float2*)(Cf + (size_t)(m + 8) * CS + n) = make_float2(v2 + b0, v3 + b1);
            }
        }
    }
}

__global__ void __launch_bounds__(256, 2) gemm_proj(const float* __restrict__ bg)
{
    const int w = blockIdx.z;
    const __half* bh = g_wt_hi + (size_t)w * 65536;
    const __half* bl = g_wt_lo + (size_t)w * 65536;
    if (w == 0)
        gemm_body<true >(g_x, bh, bl, nullptr, nullptr, g_q, 0, blockIdx.x, blockIdx.y);
    else if (w == 1)
        gemm_body<true >(g_x, bh, bl, nullptr, nullptr, g_k, 4, blockIdx.x, blockIdx.y);
    else if (w == 2)
        gemm_body<false>(g_x, bh, bl, nullptr, nullptr, g_v, 4, blockIdx.x, blockIdx.y);
    else
        gemm_body<true >(g_x, bh, bl, bg, nullptr, g_g, 2, blockIdx.x, blockIdx.y);
}

__global__ void __launch_bounds__(256, 2) gemm_outp(const float* __restrict__ bo,
                                                    float* __restrict__ out)
{
    gemm_body<true>(g_gv, g_wt_hi + (size_t)4 * 65536, g_wt_lo + (size_t)4 * 65536,
                    bo, out, nullptr, 3, blockIdx.x, blockIdx.y);
}

// ---------------------------------------------------------------------------
// Kernel 3: tensor-core column attention (K and V single fp16).
// Block = one (i, h). 256 thr = 8 warps, 32 queries/warp, 2 CTAs/SM.
// Stage = K, V @ 64 rows x 80B = 10240 B.
// ---------------------------------------------------------------------------
#define AQ_SZ   20480u
#define AST_OFF 20480u
#define AST_SZ  10240u
#define ATTN_SMEM (20480 + 3 * 10240)

__device__ __forceinline__ void load_kv_stage(uint32_t stbase, int i, int h, int t0, int tid)
{
    #pragma unroll
    for (int j = 0; j < 2; j++) {
        const int u = tid + 256 * j;
        const int arr = u >> 8;             // 0:K 1:V
        const int rem = u & 255;
        const int row = rem >> 2;
        const int c = rem & 3;
        const __half* base = (arr == 0) ? g_k : g_v;
        const __half* src = base + ((size_t)(t0 + row) * I_DIM + i) * CS + h * HD + c * 8;
        cpa16(stbase + (uint32_t)(arr * 5120 + row * 80 + c * 16), src);
    }
}

__global__ void __launch_bounds__(256, 2) attn_kernel()
{
    extern __shared__ unsigned char sm[];
    const uint32_t sb = smem_u32(sm);
    const int i = blockIdx.x;
    const int h = blockIdx.y;
    const int tid = threadIdx.x;
    const int lane = tid & 31;
    const int wq = tid >> 5;

    #pragma unroll
    for (int j = 0; j < 4; j++) {
        const int u = tid + 256 * j;
        const int row = u >> 2, c = u & 3;
        cpa16(sb + (uint32_t)(row * 80 + c * 16),
              g_q + ((size_t)row * I_DIM + i) * CS + h * HD + c * 8);
    }
    cpa_commit();
    load_kv_stage(sb + AST_OFF, i, h, 0, tid);
    cpa_commit();
    load_kv_stage(sb + AST_OFF + AST_SZ, i, h, 64, tid);
    cpa_commit();

    cpa_wait<2>();
    __syncthreads();

    uint32_t qf[2][2][4];
    #pragma unroll
    for (int mf = 0; mf < 2; mf++) {
        const uint32_t qrow = (uint32_t)((wq * 32 + mf * 16 + (lane & 15)) * 80
                                         + (lane >> 4) * 16);
        ldsm4(qf[mf][0], sb + qrow);
        ldsm4(qf[mf][1], sb + qrow + 32u);
    }

    float o[2][4][4];
    #pragma unroll
    for (int mf = 0; mf < 2; mf++)
        #pragma unroll
        for (int nf = 0; nf < 4; nf++)
            #pragma unroll
            for (int q = 0; q < 4; q++) o[mf][nf][q] = 0.f;
    float lsum[2][2] = {{0.f, 0.f}, {0.f, 0.f}};

    const uint32_t kaddr = (uint32_t)((((lane >> 4) * 8) + (lane & 7)) * 80 + ((lane >> 3) & 1) * 16);
    const uint32_t vaddr = (uint32_t)(((((lane >> 3) & 1) * 8) + (lane & 7)) * 80 + (lane >> 4) * 16);

    for (int kt = 0; kt < 4; kt++) {
        if (kt < 3) cpa_wait<1>(); else cpa_wait<0>();
        __syncthreads();
        if (kt + 2 < 4) {
            load_kv_stage(sb + AST_OFF + (uint32_t)((kt + 2) % 3) * AST_SZ, i, h, (kt + 2) * 64, tid);
            cpa_commit();
        }
        const uint32_t st = sb + AST_OFF + (uint32_t)(kt % 3) * AST_SZ;

        #pragma unroll
        for (int ch = 0; ch < 4; ch++) {
            const uint32_t roff = (uint32_t)(ch * 16 * 80);

            float s[2][2][4];
            #pragma unroll
            for (int nt = 0; nt < 2; nt++)
                #pragma unroll
                for (int mf = 0; mf < 2; mf++)
                    #pragma unroll
                    for (int q = 0; q < 4; q++) s[nt][mf][q] = 0.f;

            #pragma unroll
            for (int ks = 0; ks < 2; ks++) {
                uint32_t bh[2][2], r[4];
                ldsm4(r, st + roff + kaddr + (uint32_t)(ks * 32));
                bh[0][0] = r[0]; bh[0][1] = r[1]; bh[1][0] = r[2]; bh[1][1] = r[3];
                #pragma unroll
                for (int nt = 0; nt < 2; nt++)
                    #pragma unroll
                    for (int mf = 0; mf < 2; mf++)
                        mma_f16(s[nt][mf], qf[mf][ks], bh[nt]);
            }

            // V fragments (single fp16) for this 16-key chunk
            uint32_t vhf[4][2];
            #pragma unroll
            for (int np2 = 0; np2 < 2; np2++) {
                uint32_t r[4];
                ldsm4t(r, st + 5120u + roff + vaddr + (uint32_t)(np2 * 32));
                vhf[2 * np2][0] = r[0]; vhf[2 * np2][1] = r[1];
                vhf[2 * np2 + 1][0] = r[2]; vhf[2 * np2 + 1][1] = r[3];
            }

            #pragma unroll
            for (int mf = 0; mf < 2; mf++) {
                float* sa = s[0][mf];
                float* sc = s[1][mf];
                sa[0] = ex2f(sa[0]); sa[1] = ex2f(sa[1]);
                sa[2] = ex2f(sa[2]); sa[3] = ex2f(sa[3]);
                sc[0] = ex2f(sc[0]); sc[1] = ex2f(sc[1]);
                sc[2] = ex2f(sc[2]); sc[3] = ex2f(sc[3]);
                lsum[mf][0] += sa[0] + sa[1] + sc[0] + sc[1];
                lsum[mf][1] += sa[2] + sa[3] + sc[2] + sc[3];
                uint32_t pA[4];
                pA[0] = h2pack(sa[0], sa[1]);
                pA[1] = h2pack(sa[2], sa[3]);
                pA[2] = h2pack(sc[0], sc[1]);
                pA[3] = h2pack(sc[2], sc[3]);
                #pragma unroll
                for (int nf = 0; nf < 4; nf++)
                    mma_f16(o[mf][nf], pA, vhf[nf]);
            }
        }
    }

    // ---- epilogue: quad-reduce lsum, normalize, gate (fp16), fp16 store ----
    #pragma unroll
    for (int mf = 0; mf < 2; mf++) {
        float l0 = lsum[mf][0], l1 = lsum[mf][1];
        l0 += __shfl_xor_sync(0xFFFFFFFFu, l0, 1);
        l0 += __shfl_xor_sync(0xFFFFFFFFu, l0, 2);
        l1 += __shfl_xor_sync(0xFFFFFFFFu, l1, 1);
        l1 += __shfl_xor_sync(0xFFFFFFFFu, l1, 2);
        const float inv0 = 1.f / l0;
        const float inv1 = 1.f / l1;

        const int row = wq * 32 + mf * 16 + (lane >> 2);
        const size_t M0 = ((size_t)row * I_DIM + i) * CS + h * HD;
        const size_t M1 = ((size_t)(row + 8) * I_DIM + i) * CS + h * HD;
        #pragma unroll
        for (int nf = 0; nf < 4; nf++) {
            const int col = nf * 8 + (lane & 3) * 2;
            const float2 g0 = __half22float2(*(const __half2*)(g_g + M0 + col));
            const float2 g1 = __half22float2(*(const __half2*)(g_g + M1 + col));
            *(uint32_t*)(g_gv + M0 + col) =
                h2pack(o[mf][nf][0] * inv0 * g0.x, o[mf][nf][1] * inv0 * g0.y);
            *(uint32_t*)(g_gv + M1 + col) =
                h2pack(o[mf][nf][2] * inv1 * g1.x, o[mf][nf][3] * inv1 * g1.y);
        }
    }
}

// ---------------------------------------------------------------------------
// Launch
// ---------------------------------------------------------------------------
extern "C" void kernel_launch(void* const* d_in, const int* in_sizes, int n_in,
                              void* d_out, int out_size)
{
    const float* msa   = (const float*)d_in[0];
    const float* gamma = (const float*)d_in[1];
    const float* beta  = (const float*)d_in[2];
    const float* Wq    = (const float*)d_in[3];
    const float* Wk    = (const float*)d_in[4];
    const float* Wv    = (const float*)d_in[5];
    const float* Wg    = (const float*)d_in[6];
    const float* bg    = (const float*)d_in[7];
    const float* Wo    = (const float*)d_in[8];
    const float* bo    = (const float*)d_in[9];
    float* out = (float*)d_out;

    cudaFuncSetAttribute(gemm_proj, cudaFuncAttributeMaxDynamicSharedMemorySize, GEMM_SMEM);
    cudaFuncSetAttribute(gemm_outp, cudaFuncAttributeMaxDynamicSharedMemorySize, GEMM_SMEM);
    cudaFuncSetAttribute(attn_kernel, cudaFuncAttributeMaxDynamicSharedMemorySize, ATTN_SMEM);

    ln_kernel<<<M_ROWS / 4, 256>>>(msa, gamma, beta);
    wprep_kernel<<<5 * 65536 / 256, 256>>>(Wq, Wk, Wv, Wg, Wo);

    gemm_proj<<<dim3(MBLOCKS, 2, 4), 256, GEMM_SMEM>>>(bg);

    attn_kernel<<<dim3(I_DIM, NH), 256, ATTN_SMEM>>>();

    gemm_outp<<<dim3(MBLOCKS, 2), 256, GEMM_SMEM>>>(bo, out);
}

// round 12
// speedup vs baseline: 1.8902x; 1.1323x over previous
#include <cuda_runtime.h>
#include <cuda_fp16.h>
#include <cstdint>
#include <math.h>

#define S_DIM 256
#define I_DIM 256
#define CS    256
#define NH    8
#define HD    32
#define M_ROWS 65536
#define MBLOCKS 512
#define QSCALE 0.2550349f   /* log2(e) / sqrt(32) */

// ---------------------------------------------------------------------------
// Scratch (device globals). Q/K/V/G/gv plain fp16; weights hi (+lo for Wo).
// ---------------------------------------------------------------------------
__device__ __align__(16) __half g_x   [M_ROWS * CS];
__device__ __align__(16) __half g_gv  [M_ROWS * CS];
__device__ __align__(16) __half g_q   [M_ROWS * CS];
__device__ __align__(16) __half g_k   [M_ROWS * CS];
__device__ __align__(16) __half g_v   [M_ROWS * CS];
__device__ __align__(16) __half g_g   [M_ROWS * CS];
__device__ __align__(16) __half g_wt_hi[5 * CS * CS];   // [w][k][n]
__device__ __align__(16) __half g_wt_lo[5 * CS * CS];

// ---------------------------------------------------------------------------
// Helpers
// ---------------------------------------------------------------------------
__device__ __forceinline__ uint32_t smem_u32(const void* p) {
    uint32_t a;
    asm("{ .reg .u64 t; cvta.to.shared.u64 t, %1; cvt.u32.u64 %0, t; }" : "=r"(a) : "l"(p));
    return a;
}
__device__ __forceinline__ void cpa16(uint32_t dst, const void* src) {
    asm volatile("{ .reg .u64 g; cvta.to.global.u64 g, %1;"
                 "  cp.async.cg.shared.global [%0], [g], 16; }"
                 :: "r"(dst), "l"(src) : "memory");
}
__device__ __forceinline__ void cpa_commit() {
    asm volatile("cp.async.commit_group;" ::: "memory");
}
template <int N>
__device__ __forceinline__ void cpa_wait() {
    asm volatile("cp.async.wait_group %0;" :: "n"(N) : "memory");
}
__device__ __forceinline__ void ldsm4(uint32_t* r, uint32_t addr) {
    asm volatile("ldmatrix.sync.aligned.m8n8.x4.shared.b16 {%0,%1,%2,%3}, [%4];"
                 : "=r"(r[0]), "=r"(r[1]), "=r"(r[2]), "=r"(r[3]) : "r"(addr));
}
__device__ __forceinline__ void ldsm4t(uint32_t* r, uint32_t addr) {
    asm volatile("ldmatrix.sync.aligned.m8n8.x4.trans.shared.b16 {%0,%1,%2,%3}, [%4];"
                 : "=r"(r[0]), "=r"(r[1]), "=r"(r[2]), "=r"(r[3]) : "r"(addr));
}
__device__ __forceinline__ void mma_f16(float* c, const uint32_t* a, const uint32_t* b) {
    asm volatile("mma.sync.aligned.m16n8k16.row.col.f32.f16.f16.f32 "
                 "{%0,%1,%2,%3}, {%4,%5,%6,%7}, {%8,%9}, {%0,%1,%2,%3};"
                 : "+f"(c[0]), "+f"(c[1]), "+f"(c[2]), "+f"(c[3])
                 : "r"(a[0]), "r"(a[1]), "r"(a[2]), "r"(a[3]), "r"(b[0]), "r"(b[1]));
}
__device__ __forceinline__ uint32_t h2pack(float a, float b) {
    __half2 t = __floats2half2_rn(a, b);
    return *reinterpret_cast<uint32_t*>(&t);
}
__device__ __forceinline__ float ex2f(float x) {
    float r;
    asm("ex2.approx.f32 %0, %1;" : "=f"(r) : "f"(x));
    return r;
}

// ---------------------------------------------------------------------------
// Kernel 1: LayerNorm -> plain fp16
// ---------------------------------------------------------------------------
__global__ void __launch_bounds__(256) ln_kernel(const float* __restrict__ msa,
                                                 const float* __restrict__ gamma,
                                                 const float* __restrict__ beta)
{
    __shared__ float p1[8], p2[8];
    const int tid = threadIdx.x;
    const int r = tid >> 6;
    const int t = tid & 63;
    const int row = blockIdx.x * 4 + r;

    const float4 v = *(const float4*)(msa + (size_t)row * CS + t * 4);
    float s1 = v.x + v.y + v.z + v.w;
    float s2 = v.x * v.x + v.y * v.y + v.z * v.z + v.w * v.w;
    #pragma unroll
    for (int o = 16; o > 0; o >>= 1) {
        s1 += __shfl_xor_sync(0xFFFFFFFFu, s1, o);
        s2 += __shfl_xor_sync(0xFFFFFFFFu, s2, o);
    }
    if ((tid & 31) == 0) { p1[tid >> 5] = s1; p2[tid >> 5] = s2; }
    __syncthreads();
    const float a = p1[2 * r] + p1[2 * r + 1];
    const float b = p2[2 * r] + p2[2 * r + 1];
    const float mu = a * (1.0f / CS);
    const float var = b * (1.0f / CS) - mu * mu;
    const float rstd = rsqrtf(var + 1e-5f);

    const float4 gm = *(const float4*)(gamma + t * 4);
    const float4 bt = *(const float4*)(beta + t * 4);
    const float y0 = (v.x - mu) * rstd * gm.x + bt.x;
    const float y1 = (v.y - mu) * rstd * gm.y + bt.y;
    const float y2 = (v.z - mu) * rstd * gm.z + bt.z;
    const float y3 = (v.w - mu) * rstd * gm.w + bt.w;

    *(uint2*)(g_x + (size_t)row * CS + t * 4) = make_uint2(h2pack(y0, y1), h2pack(y2, y3));
}

// ---------------------------------------------------------------------------
// Kernel 2: weight split to fp16 hi/lo
// ---------------------------------------------------------------------------
__global__ void __launch_bounds__(256) wprep_kernel(const float* __restrict__ Wq,
                                                    const float* __restrict__ Wk,
                                                    const float* __restrict__ Wv,
                                                    const float* __restrict__ Wg,
                                                    const float* __restrict__ Wo)
{
    const int idx = blockIdx.x * 256 + threadIdx.x;
    const int w = idx >> 16;
    const int e = idx & 65535;
    const float* W = (w == 0) ? Wq : (w == 1) ? Wk : (w == 2) ? Wv : (w == 3) ? Wg : Wo;
    const float val = W[e];
    const __half h = __float2half_rn(val);
    g_wt_hi[idx] = h;
    g_wt_lo[idx] = __float2half_rn(val - __half2float(h));
}

// ---------------------------------------------------------------------------
// HMMA GEMM: C[128,128] = A[128,256] @ W[256,128-slice], fp16 A.
// TWO=true: W split hi/lo (2 MMA passes); TWO=false: W hi only.
// 256 threads / 8 warps (2m x 4n), warp tile 64x32, BK=16, 3-stage, 2 CTAs/SM.
// mode: 0 = QSCALE + fp16, 4 = plain fp16, 2 = sigmoid(x+bias) fp16,
//       3 = x+bias fp32
// ---------------------------------------------------------------------------
#define GB_OFF  6144u
#define GB_TERM 4352u
#define GSTAGE  14848u
#define GEMM_SMEM (3 * 14848)

template <bool TWO>
__device__ __forceinline__ void gemm_load_stage(uint32_t st, int ks, int tid,
                                                int mblk, int nblk,
                                                const __half* __restrict__ aP,
                                                const __half* __restrict__ bH,
                                                const __half* __restrict__ bL)
{
    const int ar = tid >> 1, ac = tid & 1;
    cpa16(st + (uint32_t)(ar * 48 + ac * 16),
          aP + (size_t)(mblk * 128 + ar) * CS + ks * 16 + ac * 8);
    const int row = tid >> 4, col = tid & 15;
    const uint32_t bdst = st + GB_OFF + (uint32_t)(row * 272 + col * 16);
    const size_t bsrc = (size_t)(ks * 16 + row) * CS + nblk * 128 + col * 8;
    cpa16(bdst, bH + bsrc);
    if (TWO) cpa16(bdst + GB_TERM, bL + bsrc);
}

template <bool TWO>
__device__ __forceinline__ void gemm_body(const __half* __restrict__ aP,
                                          const __half* __restrict__ bH,
                                          const __half* __restrict__ bL,
                                          const float* __restrict__ bias,
                                          float* __restrict__ Cf,
                                          __half* __restrict__ Ch,
                                          int mode, int mblk, int nblk)
{
    extern __shared__ unsigned char smem[];
    const uint32_t sb = smem_u32(smem);
    const int tid = threadIdx.x;
    const int lane = tid & 31;
    const int wid = tid >> 5;
    const int wm = wid >> 2;
    const int wn = wid & 3;

    float acc[4][4][4];
    #pragma unroll
    for (int i = 0; i < 4; i++)
        #pragma unroll
        for (int j = 0; j < 4; j++)
            #pragma unroll
            for (int q = 0; q < 4; q++) acc[i][j][q] = 0.f;

    gemm_load_stage<TWO>(sb,          0, tid, mblk, nblk, aP, bH, bL);
    cpa_commit();
    gemm_load_stage<TWO>(sb + GSTAGE, 1, tid, mblk, nblk, aP, bH, bL);
    cpa_commit();

    const uint32_t aRowSel = (uint32_t)((wm * 64 + (lane & 15)) * 48 + (lane >> 4) * 16);
    const uint32_t bColSel = (uint32_t)((lane & 15) * 272 + (wn * 32 + (lane >> 4) * 8) * 2);

    for (int ks = 0; ks < 16; ks++) {
        if (ks < 15) cpa_wait<1>(); else cpa_wait<0>();
        __syncthreads();
        if (ks + 2 < 16) {
            gemm_load_stage<TWO>(sb + (uint32_t)((ks + 2) % 3) * GSTAGE, ks + 2, tid,
                                 mblk, nblk, aP, bH, bL);
            cpa_commit();
        }
        const uint32_t st = sb + (uint32_t)(ks % 3) * GSTAGE;

        uint32_t Af[4][4], Bh[4][2];
        #pragma unroll
        for (int mf = 0; mf < 4; mf++)
            ldsm4(Af[mf], st + aRowSel + (uint32_t)(mf * 16 * 48));
        const uint32_t bBase = st + GB_OFF + bColSel;
        #pragma unroll
        for (int g = 0; g < 2; g++) {
            uint32_t r[4];
            ldsm4t(r, bBase + (uint32_t)(g * 32));
            Bh[2 * g][0] = r[0]; Bh[2 * g][1] = r[1];
            Bh[2 * g + 1][0] = r[2]; Bh[2 * g + 1][1] = r[3];
        }
        #pragma unroll
        for (int mf = 0; mf < 4; mf++)
            #pragma unroll
            for (int nf = 0; nf < 4; nf++)
                mma_f16(acc[mf][nf], Af[mf], Bh[nf]);

        if (TWO) {
            uint32_t Bl[4][2];
            #pragma unroll
            for (int g = 0; g < 2; g++) {
                uint32_t r[4];
                ldsm4t(r, bBase + GB_TERM + (uint32_t)(g * 32));
                Bl[2 * g][0] = r[0]; Bl[2 * g][1] = r[1];
                Bl[2 * g + 1][0] = r[2]; Bl[2 * g + 1][1] = r[3];
            }
            #pragma unroll
            for (int mf = 0; mf < 4; mf++)
                #pragma unroll
                for (int nf = 0; nf < 4; nf++)
                    mma_f16(acc[mf][nf], Af[mf], Bl[nf]);
        }
    }

    // ---- epilogue ----
    const int r0 = mblk * 128 + wm * 64 + (lane >> 2);
    const int c0 = nblk * 128 + wn * 32 + (lane & 3) * 2;
    #pragma unroll
    for (int mf = 0; mf < 4; mf++) {
        #pragma unroll
        for (int nf = 0; nf < 4; nf++) {
            const int n = c0 + nf * 8;
            const int m = r0 + mf * 16;
            float v0 = acc[mf][nf][0], v1 = acc[mf][nf][1];
            float v2 = acc[mf][nf][2], v3 = acc[mf][nf][3];
            if (mode == 0) {
                *(uint32_t*)(Ch + (size_t)m * CS + n)       = h2pack(v0 * QSCALE, v1 * QSCALE);
                *(uint32_t*)(Ch + (size_t)(m + 8) * CS + n) = h2pack(v2 * QSCALE, v3 * QSCALE);
            } else if (mode == 4) {
                *(uint32_t*)(Ch + (size_t)m * CS + n)       = h2pack(v0, v1);
                *(uint32_t*)(Ch + (size_t)(m + 8) * CS + n) = h2pack(v2, v3);
            } else if (mode == 2) {
                const float b0 = __ldg(bias + n), b1 = __ldg(bias + n + 1);
                v0 = 1.f / (1.f + __expf(-(v0 + b0)));
                v1 = 1.f / (1.f + __expf(-(v1 + b1)));
                v2 = 1.f / (1.f + __expf(-(v2 + b0)));
                v3 = 1.f / (1.f + __expf(-(v3 + b1)));
                *(uint32_t*)(Ch + (size_t)m * CS + n)       = h2pack(v0, v1);
                *(uint32_t*)(Ch + (size_t)(m + 8) * CS + n) = h2pack(v2, v3);
            } else {
                const float b0 = __ldg(bias + n), b1 = __ldg(bias + n + 1);
                *(float2*)(Cf + (size_t)m * CS + n)       = make_float2(v0 + b0, v1 + b1);
                *(float2*)(Cf + (size_t)(m + 8) * CS + n) = make_float2(v2 + b0, v3 + b1);
            }
        }
    }
}

__global__ void __launch_bounds__(256, 2) gemm_proj(const float* __restrict__ bg)
{
    const int w = blockIdx.z;
    const __half* bh = g_wt_hi + (size_t)w * 65536;
    if (w == 0)
        gemm_body<false>(g_x, bh, nullptr, nullptr, nullptr, g_q, 0, blockIdx.x, blockIdx.y);
    else if (w == 1)
        gemm_body<false>(g_x, bh, nullptr, nullptr, nullptr, g_k, 4, blockIdx.x, blockIdx.y);
    else if (w == 2)
        gemm_body<false>(g_x, bh, nullptr, nullptr, nullptr, g_v, 4, blockIdx.x, blockIdx.y);
    else
        gemm_body<false>(g_x, bh, nullptr, bg, nullptr, g_g, 2, blockIdx.x, blockIdx.y);
}

__global__ void __launch_bounds__(256, 2) gemm_outp(const float* __restrict__ bo,
                                                    float* __restrict__ out)
{
    gemm_body<true>(g_gv, g_wt_hi + (size_t)4 * 65536, g_wt_lo + (size_t)4 * 65536,
                    bo, out, nullptr, 3, blockIdx.x, blockIdx.y);
}

// ---------------------------------------------------------------------------
// Kernel 3: tensor-core column attention (K and V single fp16).
// Block = one (i, h). 256 thr = 8 warps, 32 queries/warp, 2 CTAs/SM.
// lsum computed via ones-MMA (P row-sums on tensor pipe; no shuffles).
// Stage = K, V @ 64 rows x 80B = 10240 B.
// ---------------------------------------------------------------------------
#define AQ_SZ   20480u
#define AST_OFF 20480u
#define AST_SZ  10240u
#define ATTN_SMEM (20480 + 3 * 10240)

__device__ __forceinline__ void load_kv_stage(uint32_t stbase, int i, int h, int t0, int tid)
{
    #pragma unroll
    for (int j = 0; j < 2; j++) {
        const int u = tid + 256 * j;
        const int arr = u >> 8;             // 0:K 1:V
        const int rem = u & 255;
        const int row = rem >> 2;
        const int c = rem & 3;
        const __half* base = (arr == 0) ? g_k : g_v;
        const __half* src = base + ((size_t)(t0 + row) * I_DIM + i) * CS + h * HD + c * 8;
        cpa16(stbase + (uint32_t)(arr * 5120 + row * 80 + c * 16), src);
    }
}

__global__ void __launch_bounds__(256, 2) attn_kernel()
{
    extern __shared__ unsigned char sm[];
    const uint32_t sb = smem_u32(sm);
    const int i = blockIdx.x;
    const int h = blockIdx.y;
    const int tid = threadIdx.x;
    const int lane = tid & 31;
    const int wq = tid >> 5;

    #pragma unroll
    for (int j = 0; j < 4; j++) {
        const int u = tid + 256 * j;
        const int row = u >> 2, c = u & 3;
        cpa16(sb + (uint32_t)(row * 80 + c * 16),
              g_q + ((size_t)row * I_DIM + i) * CS + h * HD + c * 8);
    }
    cpa_commit();
    load_kv_stage(sb + AST_OFF, i, h, 0, tid);
    cpa_commit();
    load_kv_stage(sb + AST_OFF + AST_SZ, i, h, 64, tid);
    cpa_commit();

    cpa_wait<2>();
    __syncthreads();

    uint32_t qf[2][2][4];
    #pragma unroll
    for (int mf = 0; mf < 2; mf++) {
        const uint32_t qrow = (uint32_t)((wq * 32 + mf * 16 + (lane & 15)) * 80
                                         + (lane >> 4) * 16);
        ldsm4(qf[mf][0], sb + qrow);
        ldsm4(qf[mf][1], sb + qrow + 32u);
    }

    float o[2][4][4];
    #pragma unroll
    for (int mf = 0; mf < 2; mf++)
        #pragma unroll
        for (int nf = 0; nf < 4; nf++)
            #pragma unroll
            for (int q = 0; q < 4; q++) o[mf][nf][q] = 0.f;
    float lacc[2][4];
    #pragma unroll
    for (int mf = 0; mf < 2; mf++)
        #pragma unroll
        for (int q = 0; q < 4; q++) lacc[mf][q] = 0.f;

    const uint32_t ones[2] = {0x3C003C00u, 0x3C003C00u};   // fp16 1.0 x4

    const uint32_t kaddr = (uint32_t)((((lane >> 4) * 8) + (lane & 7)) * 80 + ((lane >> 3) & 1) * 16);
    const uint32_t vaddr = (uint32_t)(((((lane >> 3) & 1) * 8) + (lane & 7)) * 80 + (lane >> 4) * 16);

    for (int kt = 0; kt < 4; kt++) {
        if (kt < 3) cpa_wait<1>(); else cpa_wait<0>();
        __syncthreads();
        if (kt + 2 < 4) {
            load_kv_stage(sb + AST_OFF + (uint32_t)((kt + 2) % 3) * AST_SZ, i, h, (kt + 2) * 64, tid);
            cpa_commit();
        }
        const uint32_t st = sb + AST_OFF + (uint32_t)(kt % 3) * AST_SZ;

        #pragma unroll
        for (int ch = 0; ch < 4; ch++) {
            const uint32_t roff = (uint32_t)(ch * 16 * 80);

            float s[2][2][4];
            #pragma unroll
            for (int nt = 0; nt < 2; nt++)
                #pragma unroll
                for (int mf = 0; mf < 2; mf++)
                    #pragma unroll
                    for (int q = 0; q < 4; q++) s[nt][mf][q] = 0.f;

            #pragma unroll
            for (int ks = 0; ks < 2; ks++) {
                uint32_t bh[2][2], r[4];
                ldsm4(r, st + roff + kaddr + (uint32_t)(ks * 32));
                bh[0][0] = r[0]; bh[0][1] = r[1]; bh[1][0] = r[2]; bh[1][1] = r[3];
                #pragma unroll
                for (int nt = 0; nt < 2; nt++)
                    #pragma unroll
                    for (int mf = 0; mf < 2; mf++)
                        mma_f16(s[nt][mf], qf[mf][ks], bh[nt]);
            }

            uint32_t vhf[4][2];
            #pragma unroll
            for (int np2 = 0; np2 < 2; np2++) {
                uint32_t r[4];
                ldsm4t(r, st + 5120u + roff + vaddr + (uint32_t)(np2 * 32));
                vhf[2 * np2][0] = r[0]; vhf[2 * np2][1] = r[1];
                vhf[2 * np2 + 1][0] = r[2]; vhf[2 * np2 + 1][1] = r[3];
            }

            #pragma unroll
            for (int mf = 0; mf < 2; mf++) {
                float* sa = s[0][mf];
                float* sc = s[1][mf];
                sa[0] = ex2f(sa[0]); sa[1] = ex2f(sa[1]);
                sa[2] = ex2f(sa[2]); sa[3] = ex2f(sa[3]);
                sc[0] = ex2f(sc[0]); sc[1] = ex2f(sc[1]);
                sc[2] = ex2f(sc[2]); sc[3] = ex2f(sc[3]);
                uint32_t pA[4];
                pA[0] = h2pack(sa[0], sa[1]);
                pA[1] = h2pack(sa[2], sa[3]);
                pA[2] = h2pack(sc[0], sc[1]);
                pA[3] = h2pack(sc[2], sc[3]);
                mma_f16(lacc[mf], pA, ones);
                #pragma unroll
                for (int nf = 0; nf < 4; nf++)
                    mma_f16(o[mf][nf], pA, vhf[nf]);
            }
        }
    }

    // ---- epilogue: lsum from ones-MMA acc (c[0]=row, c[2]=row+8), gate, store
    #pragma unroll
    for (int mf = 0; mf < 2; mf++) {
        const float inv0 = 1.f / lacc[mf][0];
        const float inv1 = 1.f / lacc[mf][2];

        const int row = wq * 32 + mf * 16 + (lane >> 2);
        const size_t M0 = ((size_t)row * I_DIM + i) * CS + h * HD;
        const size_t M1 = ((size_t)(row + 8) * I_DIM + i) * CS + h * HD;
        #pragma unroll
        for (int nf = 0; nf < 4; nf++) {
            const int col = nf * 8 + (lane & 3) * 2;
            const float2 g0 = __half22float2(*(const __half2*)(g_g + M0 + col));
            const float2 g1 = __half22float2(*(const __half2*)(g_g + M1 + col));
            *(uint32_t*)(g_gv + M0 + col) =
                h2pack(o[mf][nf][0] * inv0 * g0.x, o[mf][nf][1] * inv0 * g0.y);
            *(uint32_t*)(g_gv + M1 + col) =
                h2pack(o[mf][nf][2] * inv1 * g1.x, o[mf][nf][3] * inv1 * g1.y);
        }
    }
}

// ---------------------------------------------------------------------------
// Launch
// ---------------------------------------------------------------------------
extern "C" void kernel_launch(void* const* d_in, const int* in_sizes, int n_in,
                              void* d_out, int out_size)
{
    const float* msa   = (const float*)d_in[0];
    const float* gamma = (const float*)d_in[1];
    const float* beta  = (const float*)d_in[2];
    const float* Wq    = (const float*)d_in[3];
    const float* Wk    = (const float*)d_in[4];
    const float* Wv    = (const float*)d_in[5];
    const float* Wg    = (const float*)d_in[6];
    const float* bg    = (const float*)d_in[7];
    const float* Wo    = (const float*)d_in[8];
    const float* bo    = (const float*)d_in[9];
    float* out = (float*)d_out;

    cudaFuncSetAttribute(gemm_proj, cudaFuncAttributeMaxDynamicSharedMemorySize, GEMM_SMEM);
    cudaFuncSetAttribute(gemm_outp, cudaFuncAttributeMaxDynamicSharedMemorySize, GEMM_SMEM);
    cudaFuncSetAttribute(attn_kernel, cudaFuncAttributeMaxDynamicSharedMemorySize, ATTN_SMEM);

    ln_kernel<<<M_ROWS / 4, 256>>>(msa, gamma, beta);
    wprep_kernel<<<5 * 65536 / 256, 256>>>(Wq, Wk, Wv, Wg, Wo);

    gemm_proj<<<dim3(MBLOCKS, 2, 4), 256, GEMM_SMEM>>>(bg);

    attn_kernel<<<dim3(I_DIM, NH), 256, ATTN_SMEM>>>();

    gemm_outp<<<dim3(MBLOCKS, 2), 256, GEMM_SMEM>>>(bo, out);
}

// round 13
// speedup vs baseline: 1.9951x; 1.0555x over previous
#include <cuda_runtime.h>
#include <cuda_fp16.h>
#include <cstdint>
#include <math.h>

#define S_DIM 256
#define I_DIM 256
#define CS    256
#define NH    8
#define HD    32
#define M_ROWS 65536
#define MBLOCKS 512
#define QSCALE 0.2550349f   /* log2(e) / sqrt(32) */

// ---------------------------------------------------------------------------
// Scratch (device globals). All intermediates plain fp16; weights fp16 hi.
// ---------------------------------------------------------------------------
__device__ __align__(16) __half g_x   [M_ROWS * CS];
__device__ __align__(16) __half g_gv  [M_ROWS * CS];
__device__ __align__(16) __half g_q   [M_ROWS * CS];
__device__ __align__(16) __half g_k   [M_ROWS * CS];
__device__ __align__(16) __half g_v   [M_ROWS * CS];
__device__ __align__(16) __half g_g   [M_ROWS * CS];
__device__ __align__(16) __half g_wt  [5 * CS * CS];    // [w][k][n]

// ---------------------------------------------------------------------------
// Helpers
// ---------------------------------------------------------------------------
__device__ __forceinline__ uint32_t smem_u32(const void* p) {
    uint32_t a;
    asm("{ .reg .u64 t; cvta.to.shared.u64 t, %1; cvt.u32.u64 %0, t; }" : "=r"(a) : "l"(p));
    return a;
}
__device__ __forceinline__ void cpa16(uint32_t dst, const void* src) {
    asm volatile("{ .reg .u64 g; cvta.to.global.u64 g, %1;"
                 "  cp.async.cg.shared.global [%0], [g], 16; }"
                 :: "r"(dst), "l"(src) : "memory");
}
__device__ __forceinline__ void cpa_commit() {
    asm volatile("cp.async.commit_group;" ::: "memory");
}
template <int N>
__device__ __forceinline__ void cpa_wait() {
    asm volatile("cp.async.wait_group %0;" :: "n"(N) : "memory");
}
__device__ __forceinline__ void ldsm4(uint32_t* r, uint32_t addr) {
    asm volatile("ldmatrix.sync.aligned.m8n8.x4.shared.b16 {%0,%1,%2,%3}, [%4];"
                 : "=r"(r[0]), "=r"(r[1]), "=r"(r[2]), "=r"(r[3]) : "r"(addr));
}
__device__ __forceinline__ void ldsm4t(uint32_t* r, uint32_t addr) {
    asm volatile("ldmatrix.sync.aligned.m8n8.x4.trans.shared.b16 {%0,%1,%2,%3}, [%4];"
                 : "=r"(r[0]), "=r"(r[1]), "=r"(r[2]), "=r"(r[3]) : "r"(addr));
}
__device__ __forceinline__ void mma_f16(float* c, const uint32_t* a, const uint32_t* b) {
    asm volatile("mma.sync.aligned.m16n8k16.row.col.f32.f16.f16.f32 "
                 "{%0,%1,%2,%3}, {%4,%5,%6,%7}, {%8,%9}, {%0,%1,%2,%3};"
                 : "+f"(c[0]), "+f"(c[1]), "+f"(c[2]), "+f"(c[3])
                 : "r"(a[0]), "r"(a[1]), "r"(a[2]), "r"(a[3]), "r"(b[0]), "r"(b[1]));
}
__device__ __forceinline__ uint32_t h2pack(float a, float b) {
    __half2 t = __floats2half2_rn(a, b);
    return *reinterpret_cast<uint32_t*>(&t);
}
__device__ __forceinline__ float ex2f(float x) {
    float r;
    asm("ex2.approx.f32 %0, %1;" : "=f"(r) : "f"(x));
    return r;
}

// ---------------------------------------------------------------------------
// Kernel 1: LayerNorm -> plain fp16. One warp per row, shuffle-only reduce.
// ---------------------------------------------------------------------------
__global__ void __launch_bounds__(256) ln_kernel(const float* __restrict__ msa,
                                                 const float* __restrict__ gamma,
                                                 const float* __restrict__ beta)
{
    const int lane = threadIdx.x & 31;
    const int row = blockIdx.x * 8 + (threadIdx.x >> 5);
    const float* rp = msa + (size_t)row * CS + lane * 8;

    const float4 v0 = *(const float4*)rp;
    const float4 v1 = *(const float4*)(rp + 4);
    float s1 = v0.x + v0.y + v0.z + v0.w + v1.x + v1.y + v1.z + v1.w;
    float s2 = v0.x * v0.x + v0.y * v0.y + v0.z * v0.z + v0.w * v0.w
             + v1.x * v1.x + v1.y * v1.y + v1.z * v1.z + v1.w * v1.w;
    #pragma unroll
    for (int o = 16; o > 0; o >>= 1) {
        s1 += __shfl_xor_sync(0xFFFFFFFFu, s1, o);
        s2 += __shfl_xor_sync(0xFFFFFFFFu, s2, o);
    }
    const float mu = s1 * (1.0f / CS);
    const float var = s2 * (1.0f / CS) - mu * mu;
    const float rstd = rsqrtf(var + 1e-5f);

    const float4 gm0 = *(const float4*)(gamma + lane * 8);
    const float4 gm1 = *(const float4*)(gamma + lane * 8 + 4);
    const float4 bt0 = *(const float4*)(beta + lane * 8);
    const float4 bt1 = *(const float4*)(beta + lane * 8 + 4);

    uint4 out;
    out.x = h2pack((v0.x - mu) * rstd * gm0.x + bt0.x, (v0.y - mu) * rstd * gm0.y + bt0.y);
    out.y = h2pack((v0.z - mu) * rstd * gm0.z + bt0.z, (v0.w - mu) * rstd * gm0.w + bt0.w);
    out.z = h2pack((v1.x - mu) * rstd * gm1.x + bt1.x, (v1.y - mu) * rstd * gm1.y + bt1.y);
    out.w = h2pack((v1.z - mu) * rstd * gm1.z + bt1.z, (v1.w - mu) * rstd * gm1.w + bt1.w);
    *(uint4*)(g_x + (size_t)row * CS + lane * 8) = out;
}

// ---------------------------------------------------------------------------
// Kernel 2: weight convert to fp16 (single precision level now)
// ---------------------------------------------------------------------------
__global__ void __launch_bounds__(256) wprep_kernel(const float* __restrict__ Wq,
                                                    const float* __restrict__ Wk,
                                                    const float* __restrict__ Wv,
                                                    const float* __restrict__ Wg,
                                                    const float* __restrict__ Wo)
{
    const int idx = blockIdx.x * 256 + threadIdx.x;
    const int w = idx >> 16;
    const int e = idx & 65535;
    const float* W = (w == 0) ? Wq : (w == 1) ? Wk : (w == 2) ? Wv : (w == 3) ? Wg : Wo;
    g_wt[idx] = __float2half_rn(W[e]);
}

// ---------------------------------------------------------------------------
// HMMA GEMM: C[128,128] = A[128,256] @ W[256,128-slice], all fp16 single pass.
// 256 threads / 8 warps (2m x 4n), warp tile 64x32, BK=16, 3-stage, 2 CTAs/SM.
// mode: 0 = QSCALE + fp16, 4 = plain fp16, 2 = sigmoid(x+bias) fp16,
//       3 = x+bias fp32
// ---------------------------------------------------------------------------
#define GB_OFF  6144u
#define GSTAGE  10496u
#define GEMM_SMEM (3 * 10496)

__device__ __forceinline__ void gemm_load_stage(uint32_t st, int ks, int tid,
                                                int mblk, int nblk,
                                                const __half* __restrict__ aP,
                                                const __half* __restrict__ bH)
{
    const int ar = tid >> 1, ac = tid & 1;
    cpa16(st + (uint32_t)(ar * 48 + ac * 16),
          aP + (size_t)(mblk * 128 + ar) * CS + ks * 16 + ac * 8);
    const int row = tid >> 4, col = tid & 15;
    cpa16(st + GB_OFF + (uint32_t)(row * 272 + col * 16),
          bH + (size_t)(ks * 16 + row) * CS + nblk * 128 + col * 8);
}

__device__ __forceinline__ void gemm_body(const __half* __restrict__ aP,
                                          const __half* __restrict__ bH,
                                          const float* __restrict__ bias,
                                          float* __restrict__ Cf,
                                          __half* __restrict__ Ch,
                                          int mode, int mblk, int nblk)
{
    extern __shared__ unsigned char smem[];
    const uint32_t sb = smem_u32(smem);
    const int tid = threadIdx.x;
    const int lane = tid & 31;
    const int wid = tid >> 5;
    const int wm = wid >> 2;
    const int wn = wid & 3;

    float acc[4][4][4];
    #pragma unroll
    for (int i = 0; i < 4; i++)
        #pragma unroll
        for (int j = 0; j < 4; j++)
            #pragma unroll
            for (int q = 0; q < 4; q++) acc[i][j][q] = 0.f;

    gemm_load_stage(sb,          0, tid, mblk, nblk, aP, bH);
    cpa_commit();
    gemm_load_stage(sb + GSTAGE, 1, tid, mblk, nblk, aP, bH);
    cpa_commit();

    const uint32_t aRowSel = (uint32_t)((wm * 64 + (lane & 15)) * 48 + (lane >> 4) * 16);
    const uint32_t bColSel = (uint32_t)((lane & 15) * 272 + (wn * 32 + (lane >> 4) * 8) * 2);

    for (int ks = 0; ks < 16; ks++) {
        if (ks < 15) cpa_wait<1>(); else cpa_wait<0>();
        __syncthreads();
        if (ks + 2 < 16) {
            gemm_load_stage(sb + (uint32_t)((ks + 2) % 3) * GSTAGE, ks + 2, tid,
                            mblk, nblk, aP, bH);
            cpa_commit();
        }
        const uint32_t st = sb + (uint32_t)(ks % 3) * GSTAGE;

        uint32_t Af[4][4], Bh[4][2];
        #pragma unroll
        for (int mf = 0; mf < 4; mf++)
            ldsm4(Af[mf], st + aRowSel + (uint32_t)(mf * 16 * 48));
        const uint32_t bBase = st + GB_OFF + bColSel;
        #pragma unroll
        for (int g = 0; g < 2; g++) {
            uint32_t r[4];
            ldsm4t(r, bBase + (uint32_t)(g * 32));
            Bh[2 * g][0] = r[0]; Bh[2 * g][1] = r[1];
            Bh[2 * g + 1][0] = r[2]; Bh[2 * g + 1][1] = r[3];
        }
        #pragma unroll
        for (int mf = 0; mf < 4; mf++)
            #pragma unroll
            for (int nf = 0; nf < 4; nf++)
                mma_f16(acc[mf][nf], Af[mf], Bh[nf]);
    }

    // ---- epilogue ----
    const int r0 = mblk * 128 + wm * 64 + (lane >> 2);
    const int c0 = nblk * 128 + wn * 32 + (lane & 3) * 2;
    #pragma unroll
    for (int mf = 0; mf < 4; mf++) {
        #pragma unroll
        for (int nf = 0; nf < 4; nf++) {
            const int n = c0 + nf * 8;
            const int m = r0 + mf * 16;
            float v0 = acc[mf][nf][0], v1 = acc[mf][nf][1];
            float v2 = acc[mf][nf][2], v3 = acc[mf][nf][3];
            if (mode == 0) {
                *(uint32_t*)(Ch + (size_t)m * CS + n)       = h2pack(v0 * QSCALE, v1 * QSCALE);
                *(uint32_t*)(Ch + (size_t)(m + 8) * CS + n) = h2pack(v2 * QSCALE, v3 * QSCALE);
            } else if (mode == 4) {
                *(uint32_t*)(Ch + (size_t)m * CS + n)       = h2pack(v0, v1);
                *(uint32_t*)(Ch + (size_t)(m + 8) * CS + n) = h2pack(v2, v3);
            } else if (mode == 2) {
                const float b0 = __ldg(bias + n), b1 = __ldg(bias + n + 1);
                v0 = 1.f / (1.f + __expf(-(v0 + b0)));
                v1 = 1.f / (1.f + __expf(-(v1 + b1)));
                v2 = 1.f / (1.f + __expf(-(v2 + b0)));
                v3 = 1.f / (1.f + __expf(-(v3 + b1)));
                *(uint32_t*)(Ch + (size_t)m * CS + n)       = h2pack(v0, v1);
                *(uint32_t*)(Ch + (size_t)(m + 8) * CS + n) = h2pack(v2, v3);
            } else {
                const float b0 = __ldg(bias + n), b1 = __ldg(bias + n + 1);
                *(float2*)(Cf + (size_t)m * CS + n)       = make_float2(v0 + b0, v1 + b1);
                *(float2*)(Cf + (size_t)(m + 8) * CS + n) = make_float2(v2 + b0, v3 + b1);
            }
        }
    }
}

__global__ void __launch_bounds__(256, 2) gemm_proj(const float* __restrict__ bg)
{
    const int w = blockIdx.z;
    const __half* bh = g_wt + (size_t)w * 65536;
    if (w == 0)
        gemm_body(g_x, bh, nullptr, nullptr, g_q, 0, blockIdx.x, blockIdx.y);
    else if (w == 1)
        gemm_body(g_x, bh, nullptr, nullptr, g_k, 4, blockIdx.x, blockIdx.y);
    else if (w == 2)
        gemm_body(g_x, bh, nullptr, nullptr, g_v, 4, blockIdx.x, blockIdx.y);
    else
        gemm_body(g_x, bh, bg, nullptr, g_g, 2, blockIdx.x, blockIdx.y);
}

__global__ void __launch_bounds__(256, 2) gemm_outp(const float* __restrict__ bo,
                                                    float* __restrict__ out)
{
    gemm_body(g_gv, g_wt + (size_t)4 * 65536, bo, out, nullptr, 3,
              blockIdx.x, blockIdx.y);
}

// ---------------------------------------------------------------------------
// Kernel 3: tensor-core column attention (K and V single fp16).
// Block = one (i, h). 256 thr = 8 warps, 32 queries/warp, 2 CTAs/SM.
// lsum via ones-MMA. Stage = K, V @ 64 rows x 80B = 10240 B.
// ---------------------------------------------------------------------------
#define AQ_SZ   20480u
#define AST_OFF 20480u
#define AST_SZ  10240u
#define ATTN_SMEM (20480 + 3 * 10240)

__device__ __forceinline__ void load_kv_stage(uint32_t stbase, int i, int h, int t0, int tid)
{
    #pragma unroll
    for (int j = 0; j < 2; j++) {
        const int u = tid + 256 * j;
        const int arr = u >> 8;             // 0:K 1:V
        const int rem = u & 255;
        const int row = rem >> 2;
        const int c = rem & 3;
        const __half* base = (arr == 0) ? g_k : g_v;
        const __half* src = base + ((size_t)(t0 + row) * I_DIM + i) * CS + h * HD + c * 8;
        cpa16(stbase + (uint32_t)(arr * 5120 + row * 80 + c * 16), src);
    }
}

__global__ void __launch_bounds__(256, 2) attn_kernel()
{
    extern __shared__ unsigned char sm[];
    const uint32_t sb = smem_u32(sm);
    const int i = blockIdx.x;
    const int h = blockIdx.y;
    const int tid = threadIdx.x;
    const int lane = tid & 31;
    const int wq = tid >> 5;

    #pragma unroll
    for (int j = 0; j < 4; j++) {
        const int u = tid + 256 * j;
        const int row = u >> 2, c = u & 3;
        cpa16(sb + (uint32_t)(row * 80 + c * 16),
              g_q + ((size_t)row * I_DIM + i) * CS + h * HD + c * 8);
    }
    cpa_commit();
    load_kv_stage(sb + AST_OFF, i, h, 0, tid);
    cpa_commit();
    load_kv_stage(sb + AST_OFF + AST_SZ, i, h, 64, tid);
    cpa_commit();

    cpa_wait<2>();
    __syncthreads();

    uint32_t qf[2][2][4];
    #pragma unroll
    for (int mf = 0; mf < 2; mf++) {
        const uint32_t qrow = (uint32_t)((wq * 32 + mf * 16 + (lane & 15)) * 80
                                         + (lane >> 4) * 16);
        ldsm4(qf[mf][0], sb + qrow);
        ldsm4(qf[mf][1], sb + qrow + 32u);
    }

    float o[2][4][4];
    #pragma unroll
    for (int mf = 0; mf < 2; mf++)
        #pragma unroll
        for (int nf = 0; nf < 4; nf++)
            #pragma unroll
            for (int q = 0; q < 4; q++) o[mf][nf][q] = 0.f;
    float lacc[2][4];
    #pragma unroll
    for (int mf = 0; mf < 2; mf++)
        #pragma unroll
        for (int q = 0; q < 4; q++) lacc[mf][q] = 0.f;

    const uint32_t ones[2] = {0x3C003C00u, 0x3C003C00u};

    const uint32_t kaddr = (uint32_t)((((lane >> 4) * 8) + (lane & 7)) * 80 + ((lane >> 3) & 1) * 16);
    const uint32_t vaddr = (uint32_t)(((((lane >> 3) & 1) * 8) + (lane & 7)) * 80 + (lane >> 4) * 16);

    for (int kt = 0; kt < 4; kt++) {
        if (kt < 3) cpa_wait<1>(); else cpa_wait<0>();
        __syncthreads();
        if (kt + 2 < 4) {
            load_kv_stage(sb + AST_OFF + (uint32_t)((kt + 2) % 3) * AST_SZ, i, h, (kt + 2) * 64, tid);
            cpa_commit();
        }
        const uint32_t st = sb + AST_OFF + (uint32_t)(kt % 3) * AST_SZ;

        #pragma unroll
        for (int ch = 0; ch < 4; ch++) {
            const uint32_t roff = (uint32_t)(ch * 16 * 80);

            float s[2][2][4];
            #pragma unroll
            for (int nt = 0; nt < 2; nt++)
                #pragma unroll
                for (int mf = 0; mf < 2; mf++)
                    #pragma unroll
                    for (int q = 0; q < 4; q++) s[nt][mf][q] = 0.f;

            #pragma unroll
            for (int ks = 0; ks < 2; ks++) {
                uint32_t bh[2][2], r[4];
                ldsm4(r, st + roff + kaddr + (uint32_t)(ks * 32));
                bh[0][0] = r[0]; bh[0][1] = r[1]; bh[1][0] = r[2]; bh[1][1] = r[3];
                #pragma unroll
                for (int nt = 0; nt < 2; nt++)
                    #pragma unroll
                    for (int mf = 0; mf < 2; mf++)
                        mma_f16(s[nt][mf], qf[mf][ks], bh[nt]);
            }

            uint32_t vhf[4][2];
            #pragma unroll
            for (int np2 = 0; np2 < 2; np2++) {
                uint32_t r[4];
                ldsm4t(r, st + 5120u + roff + vaddr + (uint32_t)(np2 * 32));
                vhf[2 * np2][0] = r[0]; vhf[2 * np2][1] = r[1];
                vhf[2 * np2 + 1][0] = r[2]; vhf[2 * np2 + 1][1] = r[3];
            }

            #pragma unroll
            for (int mf = 0; mf < 2; mf++) {
                float* sa = s[0][mf];
                float* sc = s[1][mf];
                sa[0] = ex2f(sa[0]); sa[1] = ex2f(sa[1]);
                sa[2] = ex2f(sa[2]); sa[3] = ex2f(sa[3]);
                sc[0] = ex2f(sc[0]); sc[1] = ex2f(sc[1]);
                sc[2] = ex2f(sc[2]); sc[3] = ex2f(sc[3]);
                uint32_t pA[4];
                pA[0] = h2pack(sa[0], sa[1]);
                pA[1] = h2pack(sa[2], sa[3]);
                pA[2] = h2pack(sc[0], sc[1]);
                pA[3] = h2pack(sc[2], sc[3]);
                mma_f16(lacc[mf], pA, ones);
                #pragma unroll
                for (int nf = 0; nf < 4; nf++)
                    mma_f16(o[mf][nf], pA, vhf[nf]);
            }
        }
    }

    // ---- epilogue: lsum from ones-MMA acc, gate, store ----
    #pragma unroll
    for (int mf = 0; mf < 2; mf++) {
        const float inv0 = 1.f / lacc[mf][0];
        const float inv1 = 1.f / lacc[mf][2];

        const int row = wq * 32 + mf * 16 + (lane >> 2);
        const size_t M0 = ((size_t)row * I_DIM + i) * CS + h * HD;
        const size_t M1 = ((size_t)(row + 8) * I_DIM + i) * CS + h * HD;
        #pragma unroll
        for (int nf = 0; nf < 4; nf++) {
            const int col = nf * 8 + (lane & 3) * 2;
            const float2 g0 = __half22float2(*(const __half2*)(g_g + M0 + col));
            const float2 g1 = __half22float2(*(const __half2*)(g_g + M1 + col));
            *(uint32_t*)(g_gv + M0 + col) =
                h2pack(o[mf][nf][0] * inv0 * g0.x, o[mf][nf][1] * inv0 * g0.y);
            *(uint32_t*)(g_gv + M1 + col) =
                h2pack(o[mf][nf][2] * inv1 * g1.x, o[mf][nf][3] * inv1 * g1.y);
        }
    }
}

// ---------------------------------------------------------------------------
// Launch
// ---------------------------------------------------------------------------
extern "C" void kernel_launch(void* const* d_in, const int* in_sizes, int n_in,
                              void* d_out, int out_size)
{
    const float* msa   = (const float*)d_in[0];
    const float* gamma = (const float*)d_in[1];
    const float* beta  = (const float*)d_in[2];
    const float* Wq    = (const float*)d_in[3];
    const float* Wk    = (const float*)d_in[4];
    const float* Wv    = (const float*)d_in[5];
    const float* Wg    = (const float*)d_in[6];
    const float* bg    = (const float*)d_in[7];
    const float* Wo    = (const float*)d_in[8];
    const float* bo    = (const float*)d_in[9];
    float* out = (float*)d_out;

    cudaFuncSetAttribute(gemm_proj, cudaFuncAttributeMaxDynamicSharedMemorySize, GEMM_SMEM);
    cudaFuncSetAttribute(gemm_outp, cudaFuncAttributeMaxDynamicSharedMemorySize, GEMM_SMEM);
    cudaFuncSetAttribute(attn_kernel, cudaFuncAttributeMaxDynamicSharedMemorySize, ATTN_SMEM);

    ln_kernel<<<M_ROWS / 8, 256>>>(msa, gamma, beta);
    wprep_kernel<<<5 * 65536 / 256, 256>>>(Wq, Wk, Wv, Wg, Wo);

    gemm_proj<<<dim3(MBLOCKS, 2, 4), 256, GEMM_SMEM>>>(bg);

    attn_kernel<<<dim3(I_DIM, NH), 256, ATTN_SMEM>>>();

    gemm_outp<<<dim3(MBLOCKS, 2), 256, GEMM_SMEM>>>(bo, out);
}

// round 14
// speedup vs baseline: 2.0589x; 1.0320x over previous
#include <cuda_runtime.h>
#include <cuda_fp16.h>
#include <cstdint>
#include <math.h>

#define S_DIM 256
#define I_DIM 256
#define CS    256
#define NH    8
#define HD    32
#define M_ROWS 65536
#define MBLOCKS 512
#define QSCALE 0.2550349f   /* log2(e) / sqrt(32) */

// ---------------------------------------------------------------------------
// Scratch (device globals). All intermediates plain fp16; weights fp16.
// ---------------------------------------------------------------------------
__device__ __align__(16) __half g_x   [M_ROWS * CS];
__device__ __align__(16) __half g_gv  [M_ROWS * CS];
__device__ __align__(16) __half g_q   [M_ROWS * CS];
__device__ __align__(16) __half g_k   [M_ROWS * CS];
__device__ __align__(16) __half g_v   [M_ROWS * CS];
__device__ __align__(16) __half g_g   [M_ROWS * CS];
__device__ __align__(16) __half g_wt  [5 * CS * CS];    // [w][k][n]

// ---------------------------------------------------------------------------
// Helpers
// ---------------------------------------------------------------------------
__device__ __forceinline__ uint32_t smem_u32(const void* p) {
    uint32_t a;
    asm("{ .reg .u64 t; cvta.to.shared.u64 t, %1; cvt.u32.u64 %0, t; }" : "=r"(a) : "l"(p));
    return a;
}
__device__ __forceinline__ void cpa16(uint32_t dst, const void* src) {
    asm volatile("{ .reg .u64 g; cvta.to.global.u64 g, %1;"
                 "  cp.async.cg.shared.global [%0], [g], 16; }"
                 :: "r"(dst), "l"(src) : "memory");
}
__device__ __forceinline__ void cpa_commit() {
    asm volatile("cp.async.commit_group;" ::: "memory");
}
template <int N>
__device__ __forceinline__ void cpa_wait() {
    asm volatile("cp.async.wait_group %0;" :: "n"(N) : "memory");
}
__device__ __forceinline__ void ldsm4(uint32_t* r, uint32_t addr) {
    asm volatile("ldmatrix.sync.aligned.m8n8.x4.shared.b16 {%0,%1,%2,%3}, [%4];"
                 : "=r"(r[0]), "=r"(r[1]), "=r"(r[2]), "=r"(r[3]) : "r"(addr));
}
__device__ __forceinline__ void ldsm4t(uint32_t* r, uint32_t addr) {
    asm volatile("ldmatrix.sync.aligned.m8n8.x4.trans.shared.b16 {%0,%1,%2,%3}, [%4];"
                 : "=r"(r[0]), "=r"(r[1]), "=r"(r[2]), "=r"(r[3]) : "r"(addr));
}
__device__ __forceinline__ void mma_f16(float* c, const uint32_t* a, const uint32_t* b) {
    asm volatile("mma.sync.aligned.m16n8k16.row.col.f32.f16.f16.f32 "
                 "{%0,%1,%2,%3}, {%4,%5,%6,%7}, {%8,%9}, {%0,%1,%2,%3};"
                 : "+f"(c[0]), "+f"(c[1]), "+f"(c[2]), "+f"(c[3])
                 : "r"(a[0]), "r"(a[1]), "r"(a[2]), "r"(a[3]), "r"(b[0]), "r"(b[1]));
}
__device__ __forceinline__ uint32_t h2pack(float a, float b) {
    __half2 t = __floats2half2_rn(a, b);
    return *reinterpret_cast<uint32_t*>(&t);
}
__device__ __forceinline__ float ex2f(float x) {
    float r;
    asm("ex2.approx.f32 %0, %1;" : "=f"(r) : "f"(x));
    return r;
}

// ---------------------------------------------------------------------------
// Kernel 1: LayerNorm -> plain fp16. One warp per row, shuffle-only reduce.
// ---------------------------------------------------------------------------
__global__ void __launch_bounds__(256) ln_kernel(const float* __restrict__ msa,
                                                 const float* __restrict__ gamma,
                                                 const float* __restrict__ beta)
{
    const int lane = threadIdx.x & 31;
    const int row = blockIdx.x * 8 + (threadIdx.x >> 5);
    const float* rp = msa + (size_t)row * CS + lane * 8;

    const float4 v0 = *(const float4*)rp;
    const float4 v1 = *(const float4*)(rp + 4);
    float s1 = v0.x + v0.y + v0.z + v0.w + v1.x + v1.y + v1.z + v1.w;
    float s2 = v0.x * v0.x + v0.y * v0.y + v0.z * v0.z + v0.w * v0.w
             + v1.x * v1.x + v1.y * v1.y + v1.z * v1.z + v1.w * v1.w;
    #pragma unroll
    for (int o = 16; o > 0; o >>= 1) {
        s1 += __shfl_xor_sync(0xFFFFFFFFu, s1, o);
        s2 += __shfl_xor_sync(0xFFFFFFFFu, s2, o);
    }
    const float mu = s1 * (1.0f / CS);
    const float var = s2 * (1.0f / CS) - mu * mu;
    const float rstd = rsqrtf(var + 1e-5f);

    const float4 gm0 = *(const float4*)(gamma + lane * 8);
    const float4 gm1 = *(const float4*)(gamma + lane * 8 + 4);
    const float4 bt0 = *(const float4*)(beta + lane * 8);
    const float4 bt1 = *(const float4*)(beta + lane * 8 + 4);

    uint4 out;
    out.x = h2pack((v0.x - mu) * rstd * gm0.x + bt0.x, (v0.y - mu) * rstd * gm0.y + bt0.y);
    out.y = h2pack((v0.z - mu) * rstd * gm0.z + bt0.z, (v0.w - mu) * rstd * gm0.w + bt0.w);
    out.z = h2pack((v1.x - mu) * rstd * gm1.x + bt1.x, (v1.y - mu) * rstd * gm1.y + bt1.y);
    out.w = h2pack((v1.z - mu) * rstd * gm1.z + bt1.z, (v1.w - mu) * rstd * gm1.w + bt1.w);
    *(uint4*)(g_x + (size_t)row * CS + lane * 8) = out;
}

// ---------------------------------------------------------------------------
// Kernel 2: weight convert to fp16
// ---------------------------------------------------------------------------
__global__ void __launch_bounds__(256) wprep_kernel(const float* __restrict__ Wq,
                                                    const float* __restrict__ Wk,
                                                    const float* __restrict__ Wv,
                                                    const float* __restrict__ Wg,
                                                    const float* __restrict__ Wo)
{
    const int idx = blockIdx.x * 256 + threadIdx.x;
    const int w = idx >> 16;
    const int e = idx & 65535;
    const float* W = (w == 0) ? Wq : (w == 1) ? Wk : (w == 2) ? Wv : (w == 3) ? Wg : Wo;
    g_wt[idx] = __float2half_rn(W[e]);
}

// ---------------------------------------------------------------------------
// HMMA GEMM: C[128,128] = A[128,256] @ W[256,128-slice], all fp16 single pass.
// 256 threads / 8 warps (2m x 4n), warp tile 64x32, BK=32 (8 iters, half the
// barriers), 3-stage, 2 CTAs/SM.
// smem/stage: A 128 rows x 80B (64B data) = 10240; B 32 rows x 272B = 8704.
// mode: 0 = QSCALE + fp16, 4 = plain fp16, 2 = sigmoid(x+bias) fp16,
//       3 = x+bias fp32
// ---------------------------------------------------------------------------
#define GB_OFF  10240u
#define GSTAGE  18944u
#define GEMM_SMEM (3 * 18944)

__device__ __forceinline__ void gemm_load_stage(uint32_t st, int ks, int tid,
                                                int mblk, int nblk,
                                                const __half* __restrict__ aP,
                                                const __half* __restrict__ bH)
{
    // A: 128 rows x 64B = 512 chunks, 2 per thread
    #pragma unroll
    for (int j = 0; j < 2; j++) {
        const int u = tid + 256 * j;
        const int ar = u >> 2, ac = u & 3;
        cpa16(st + (uint32_t)(ar * 80 + ac * 16),
              aP + (size_t)(mblk * 128 + ar) * CS + ks * 32 + ac * 8);
    }
    // B: 32 rows x 256B = 512 chunks, 2 per thread
    #pragma unroll
    for (int j = 0; j < 2; j++) {
        const int u = tid + 256 * j;
        const int row = u >> 4, col = u & 15;
        cpa16(st + GB_OFF + (uint32_t)(row * 272 + col * 16),
              bH + (size_t)(ks * 32 + row) * CS + nblk * 128 + col * 8);
    }
}

__device__ __forceinline__ void gemm_body(const __half* __restrict__ aP,
                                          const __half* __restrict__ bH,
                                          const float* __restrict__ bias,
                                          float* __restrict__ Cf,
                                          __half* __restrict__ Ch,
                                          int mode, int mblk, int nblk)
{
    extern __shared__ unsigned char smem[];
    const uint32_t sb = smem_u32(smem);
    const int tid = threadIdx.x;
    const int lane = tid & 31;
    const int wid = tid >> 5;
    const int wm = wid >> 2;
    const int wn = wid & 3;

    float acc[4][4][4];
    #pragma unroll
    for (int i = 0; i < 4; i++)
        #pragma unroll
        for (int j = 0; j < 4; j++)
            #pragma unroll
            for (int q = 0; q < 4; q++) acc[i][j][q] = 0.f;

    gemm_load_stage(sb,          0, tid, mblk, nblk, aP, bH);
    cpa_commit();
    gemm_load_stage(sb + GSTAGE, 1, tid, mblk, nblk, aP, bH);
    cpa_commit();

    const uint32_t aRowSel = (uint32_t)((wm * 64 + (lane & 15)) * 80 + (lane >> 4) * 16);
    const uint32_t bColSel = (uint32_t)((wn * 32 + (lane >> 4) * 8) * 2);

    for (int ks = 0; ks < 8; ks++) {
        if (ks < 7) cpa_wait<1>(); else cpa_wait<0>();
        __syncthreads();
        if (ks + 2 < 8) {
            gemm_load_stage(sb + (uint32_t)((ks + 2) % 3) * GSTAGE, ks + 2, tid,
                            mblk, nblk, aP, bH);
            cpa_commit();
        }
        const uint32_t st = sb + (uint32_t)(ks % 3) * GSTAGE;

        #pragma unroll
        for (int kh = 0; kh < 2; kh++) {
            uint32_t Af[4][4], Bh[4][2];
            #pragma unroll
            for (int mf = 0; mf < 4; mf++)
                ldsm4(Af[mf], st + aRowSel + (uint32_t)(mf * 16 * 80 + kh * 32));
            const uint32_t bBase = st + GB_OFF +
                (uint32_t)((kh * 16 + (lane & 15)) * 272) + bColSel;
            #pragma unroll
            for (int g = 0; g < 2; g++) {
                uint32_t r[4];
                ldsm4t(r, bBase + (uint32_t)(g * 32));
                Bh[2 * g][0] = r[0]; Bh[2 * g][1] = r[1];
                Bh[2 * g + 1][0] = r[2]; Bh[2 * g + 1][1] = r[3];
            }
            #pragma unroll
            for (int mf = 0; mf < 4; mf++)
                #pragma unroll
                for (int nf = 0; nf < 4; nf++)
                    mma_f16(acc[mf][nf], Af[mf], Bh[nf]);
        }
    }

    // ---- epilogue ----
    const int r0 = mblk * 128 + wm * 64 + (lane >> 2);
    const int c0 = nblk * 128 + wn * 32 + (lane & 3) * 2;
    #pragma unroll
    for (int mf = 0; mf < 4; mf++) {
        #pragma unroll
        for (int nf = 0; nf < 4; nf++) {
            const int n = c0 + nf * 8;
            const int m = r0 + mf * 16;
            float v0 = acc[mf][nf][0], v1 = acc[mf][nf][1];
            float v2 = acc[mf][nf][2], v3 = acc[mf][nf][3];
            if (mode == 0) {
                *(uint32_t*)(Ch + (size_t)m * CS + n)       = h2pack(v0 * QSCALE, v1 * QSCALE);
                *(uint32_t*)(Ch + (size_t)(m + 8) * CS + n) = h2pack(v2 * QSCALE, v3 * QSCALE);
            } else if (mode == 4) {
                *(uint32_t*)(Ch + (size_t)m * CS + n)       = h2pack(v0, v1);
                *(uint32_t*)(Ch + (size_t)(m + 8) * CS + n) = h2pack(v2, v3);
            } else if (mode == 2) {
                const float b0 = __ldg(bias + n), b1 = __ldg(bias + n + 1);
                v0 = 1.f / (1.f + __expf(-(v0 + b0)));
                v1 = 1.f / (1.f + __expf(-(v1 + b1)));
                v2 = 1.f / (1.f + __expf(-(v2 + b0)));
                v3 = 1.f / (1.f + __expf(-(v3 + b1)));
                *(uint32_t*)(Ch + (size_t)m * CS + n)       = h2pack(v0, v1);
                *(uint32_t*)(Ch + (size_t)(m + 8) * CS + n) = h2pack(v2, v3);
            } else {
                const float b0 = __ldg(bias + n), b1 = __ldg(bias + n + 1);
                *(float2*)(Cf + (size_t)m * CS + n)       = make_float2(v0 + b0, v1 + b1);
                *(float2*)(Cf + (size_t)(m + 8) * CS + n) = make_float2(v2 + b0, v3 + b1);
            }
        }
    }
}

__global__ void __launch_bounds__(256, 2) gemm_proj(const float* __restrict__ bg)
{
    const int w = blockIdx.z;
    const __half* bh = g_wt + (size_t)w * 65536;
    if (w == 0)
        gemm_body(g_x, bh, nullptr, nullptr, g_q, 0, blockIdx.x, blockIdx.y);
    else if (w == 1)
        gemm_body(g_x, bh, nullptr, nullptr, g_k, 4, blockIdx.x, blockIdx.y);
    else if (w == 2)
        gemm_body(g_x, bh, nullptr, nullptr, g_v, 4, blockIdx.x, blockIdx.y);
    else
        gemm_body(g_x, bh, bg, nullptr, g_g, 2, blockIdx.x, blockIdx.y);
}

__global__ void __launch_bounds__(256, 2) gemm_outp(const float* __restrict__ bo,
                                                    float* __restrict__ out)
{
    gemm_body(g_gv, g_wt + (size_t)4 * 65536, bo, out, nullptr, 3,
              blockIdx.x, blockIdx.y);
}

// ---------------------------------------------------------------------------
// Kernel 3: tensor-core column attention (K and V single fp16).
// Grid (h, i): the 8 same-i CTAs are adjacent -> concurrent -> share Q/K/V/G
// L2 lines (each 128B line spans 2 heads' 64B slices; previously refetched).
// Block = one (i, h). 256 thr = 8 warps, 32 queries/warp, 2 CTAs/SM.
// lsum via ones-MMA. Stage = K, V @ 64 rows x 80B = 10240 B.
// ---------------------------------------------------------------------------
#define AQ_SZ   20480u
#define AST_OFF 20480u
#define AST_SZ  10240u
#define ATTN_SMEM (20480 + 3 * 10240)

__device__ __forceinline__ void load_kv_stage(uint32_t stbase, int i, int h, int t0, int tid)
{
    #pragma unroll
    for (int j = 0; j < 2; j++) {
        const int u = tid + 256 * j;
        const int arr = u >> 8;             // 0:K 1:V
        const int rem = u & 255;
        const int row = rem >> 2;
        const int c = rem & 3;
        const __half* base = (arr == 0) ? g_k : g_v;
        const __half* src = base + ((size_t)(t0 + row) * I_DIM + i) * CS + h * HD + c * 8;
        cpa16(stbase + (uint32_t)(arr * 5120 + row * 80 + c * 16), src);
    }
}

__global__ void __launch_bounds__(256, 2) attn_kernel()
{
    extern __shared__ unsigned char sm[];
    const uint32_t sb = smem_u32(sm);
    const int h = blockIdx.x;           // heads fastest -> same-i blocks concurrent
    const int i = blockIdx.y;
    const int tid = threadIdx.x;
    const int lane = tid & 31;
    const int wq = tid >> 5;

    #pragma unroll
    for (int j = 0; j < 4; j++) {
        const int u = tid + 256 * j;
        const int row = u >> 2, c = u & 3;
        cpa16(sb + (uint32_t)(row * 80 + c * 16),
              g_q + ((size_t)row * I_DIM + i) * CS + h * HD + c * 8);
    }
    cpa_commit();
    load_kv_stage(sb + AST_OFF, i, h, 0, tid);
    cpa_commit();
    load_kv_stage(sb + AST_OFF + AST_SZ, i, h, 64, tid);
    cpa_commit();

    cpa_wait<2>();
    __syncthreads();

    uint32_t qf[2][2][4];
    #pragma unroll
    for (int mf = 0; mf < 2; mf++) {
        const uint32_t qrow = (uint32_t)((wq * 32 + mf * 16 + (lane & 15)) * 80
                                         + (lane >> 4) * 16);
        ldsm4(qf[mf][0], sb + qrow);
        ldsm4(qf[mf][1], sb + qrow + 32u);
    }

    float o[2][4][4];
    #pragma unroll
    for (int mf = 0; mf < 2; mf++)
        #pragma unroll
        for (int nf = 0; nf < 4; nf++)
            #pragma unroll
            for (int q = 0; q < 4; q++) o[mf][nf][q] = 0.f;
    float lacc[2][4];
    #pragma unroll
    for (int mf = 0; mf < 2; mf++)
        #pragma unroll
        for (int q = 0; q < 4; q++) lacc[mf][q] = 0.f;

    const uint32_t ones[2] = {0x3C003C00u, 0x3C003C00u};

    const uint32_t kaddr = (uint32_t)((((lane >> 4) * 8) + (lane & 7)) * 80 + ((lane >> 3) & 1) * 16);
    const uint32_t vaddr = (uint32_t)(((((lane >> 3) & 1) * 8) + (lane & 7)) * 80 + (lane >> 4) * 16);

    for (int kt = 0; kt < 4; kt++) {
        if (kt < 3) cpa_wait<1>(); else cpa_wait<0>();
        __syncthreads();
        if (kt + 2 < 4) {
            load_kv_stage(sb + AST_OFF + (uint32_t)((kt + 2) % 3) * AST_SZ, i, h, (kt + 2) * 64, tid);
            cpa_commit();
        }
        const uint32_t st = sb + AST_OFF + (uint32_t)(kt % 3) * AST_SZ;

        #pragma unroll
        for (int ch = 0; ch < 4; ch++) {
            const uint32_t roff = (uint32_t)(ch * 16 * 80);

            float s[2][2][4];
            #pragma unroll
            for (int nt = 0; nt < 2; nt++)
                #pragma unroll
                for (int mf = 0; mf < 2; mf++)
                    #pragma unroll
                    for (int q = 0; q < 4; q++) s[nt][mf][q] = 0.f;

            #pragma unroll
            for (int ks = 0; ks < 2; ks++) {
                uint32_t bh[2][2], r[4];
                ldsm4(r, st + roff + kaddr + (uint32_t)(ks * 32));
                bh[0][0] = r[0]; bh[0][1] = r[1]; bh[1][0] = r[2]; bh[1][1] = r[3];
                #pragma unroll
                for (int nt = 0; nt < 2; nt++)
                    #pragma unroll
                    for (int mf = 0; mf < 2; mf++)
                        mma_f16(s[nt][mf], qf[mf][ks], bh[nt]);
            }

            uint32_t vhf[4][2];
            #pragma unroll
            for (int np2 = 0; np2 < 2; np2++) {
                uint32_t r[4];
                ldsm4t(r, st + 5120u + roff + vaddr + (uint32_t)(np2 * 32));
                vhf[2 * np2][0] = r[0]; vhf[2 * np2][1] = r[1];
                vhf[2 * np2 + 1][0] = r[2]; vhf[2 * np2 + 1][1] = r[3];
            }

            #pragma unroll
            for (int mf = 0; mf < 2; mf++) {
                float* sa = s[0][mf];
                float* sc = s[1][mf];
                sa[0] = ex2f(sa[0]); sa[1] = ex2f(sa[1]);
                sa[2] = ex2f(sa[2]); sa[3] = ex2f(sa[3]);
                sc[0] = ex2f(sc[0]); sc[1] = ex2f(sc[1]);
                sc[2] = ex2f(sc[2]); sc[3] = ex2f(sc[3]);
                uint32_t pA[4];
                pA[0] = h2pack(sa[0], sa[1]);
                pA[1] = h2pack(sa[2], sa[3]);
                pA[2] = h2pack(sc[0], sc[1]);
                pA[3] = h2pack(sc[2], sc[3]);
                mma_f16(lacc[mf], pA, ones);
                #pragma unroll
                for (int nf = 0; nf < 4; nf++)
                    mma_f16(o[mf][nf], pA, vhf[nf]);
            }
        }
    }

    // ---- epilogue: lsum from ones-MMA acc, gate, store ----
    #pragma unroll
    for (int mf = 0; mf < 2; mf++) {
        const float inv0 = 1.f / lacc[mf][0];
        const float inv1 = 1.f / lacc[mf][2];

        const int row = wq * 32 + mf * 16 + (lane >> 2);
        const size_t M0 = ((size_t)row * I_DIM + i) * CS + h * HD;
        const size_t M1 = ((size_t)(row + 8) * I_DIM + i) * CS + h * HD;
        #pragma unroll
        for (int nf = 0; nf < 4; nf++) {
            const int col = nf * 8 + (lane & 3) * 2;
            const float2 g0 = __half22float2(*(const __half2*)(g_g + M0 + col));
            const float2 g1 = __half22float2(*(const __half2*)(g_g + M1 + col));
            *(uint32_t*)(g_gv + M0 + col) =
                h2pack(o[mf][nf][0] * inv0 * g0.x, o[mf][nf][1] * inv0 * g0.y);
            *(uint32_t*)(g_gv + M1 + col) =
                h2pack(o[mf][nf][2] * inv1 * g1.x, o[mf][nf][3] * inv1 * g1.y);
        }
    }
}

// ---------------------------------------------------------------------------
// Launch
// ---------------------------------------------------------------------------
extern "C" void kernel_launch(void* const* d_in, const int* in_sizes, int n_in,
                              void* d_out, int out_size)
{
    const float* msa   = (const float*)d_in[0];
    const float* gamma = (const float*)d_in[1];
    const float* beta  = (const float*)d_in[2];
    const float* Wq    = (const float*)d_in[3];
    const float* Wk    = (const float*)d_in[4];
    const float* Wv    = (const float*)d_in[5];
    const float* Wg    = (const float*)d_in[6];
    const float* bg    = (const float*)d_in[7];
    const float* Wo    = (const float*)d_in[8];
    const float* bo    = (const float*)d_in[9];
    float* out = (float*)d_out;

    cudaFuncSetAttribute(gemm_proj, cudaFuncAttributeMaxDynamicSharedMemorySize, GEMM_SMEM);
    cudaFuncSetAttribute(gemm_outp, cudaFuncAttributeMaxDynamicSharedMemorySize, GEMM_SMEM);
    cudaFuncSetAttribute(attn_kernel, cudaFuncAttributeMaxDynamicSharedMemorySize, ATTN_SMEM);

    ln_kernel<<<M_ROWS / 8, 256>>>(msa, gamma, beta);
    wprep_kernel<<<5 * 65536 / 256, 256>>>(Wq, Wk, Wv, Wg, Wo);

    gemm_proj<<<dim3(MBLOCKS, 2, 4), 256, GEMM_SMEM>>>(bg);

    attn_kernel<<<dim3(NH, I_DIM), 256, ATTN_SMEM>>>();

    gemm_outp<<<dim3(MBLOCKS, 2), 256, GEMM_SMEM>>>(bo, out);
}

// round 15
// speedup vs baseline: 2.1242x; 1.0317x over previous
#include <cuda_runtime.h>
#include <cuda_fp16.h>
#include <cstdint>
#include <math.h>

#define S_DIM 256
#define I_DIM 256
#define CS    256
#define NH    8
#define HD    32
#define M_ROWS 65536
#define MBLOCKS 512
#define QSCALE 0.2550349f   /* log2(e) / sqrt(32) */

// ---------------------------------------------------------------------------
// Scratch (device globals). All intermediates plain fp16; weights fp16.
// ---------------------------------------------------------------------------
__device__ __align__(16) __half g_x   [M_ROWS * CS];
__device__ __align__(16) __half g_gv  [M_ROWS * CS];
__device__ __align__(16) __half g_q   [M_ROWS * CS];
__device__ __align__(16) __half g_k   [M_ROWS * CS];
__device__ __align__(16) __half g_v   [M_ROWS * CS];
__device__ __align__(16) __half g_g   [M_ROWS * CS];
__device__ __align__(16) __half g_wt  [5 * CS * CS];    // [w][k][n]

// ---------------------------------------------------------------------------
// Helpers
// ---------------------------------------------------------------------------
__device__ __forceinline__ uint32_t smem_u32(const void* p) {
    uint32_t a;
    asm("{ .reg .u64 t; cvta.to.shared.u64 t, %1; cvt.u32.u64 %0, t; }" : "=r"(a) : "l"(p));
    return a;
}
__device__ __forceinline__ void cpa16(uint32_t dst, const void* src) {
    asm volatile("{ .reg .u64 g; cvta.to.global.u64 g, %1;"
                 "  cp.async.cg.shared.global [%0], [g], 16; }"
                 :: "r"(dst), "l"(src) : "memory");
}
__device__ __forceinline__ void cpa_commit() {
    asm volatile("cp.async.commit_group;" ::: "memory");
}
template <int N>
__device__ __forceinline__ void cpa_wait() {
    asm volatile("cp.async.wait_group %0;" :: "n"(N) : "memory");
}
__device__ __forceinline__ void ldsm4(uint32_t* r, uint32_t addr) {
    asm volatile("ldmatrix.sync.aligned.m8n8.x4.shared.b16 {%0,%1,%2,%3}, [%4];"
                 : "=r"(r[0]), "=r"(r[1]), "=r"(r[2]), "=r"(r[3]) : "r"(addr));
}
__device__ __forceinline__ void ldsm4t(uint32_t* r, uint32_t addr) {
    asm volatile("ldmatrix.sync.aligned.m8n8.x4.trans.shared.b16 {%0,%1,%2,%3}, [%4];"
                 : "=r"(r[0]), "=r"(r[1]), "=r"(r[2]), "=r"(r[3]) : "r"(addr));
}
__device__ __forceinline__ void mma_f16(float* c, const uint32_t* a, const uint32_t* b) {
    asm volatile("mma.sync.aligned.m16n8k16.row.col.f32.f16.f16.f32 "
                 "{%0,%1,%2,%3}, {%4,%5,%6,%7}, {%8,%9}, {%0,%1,%2,%3};"
                 : "+f"(c[0]), "+f"(c[1]), "+f"(c[2]), "+f"(c[3])
                 : "r"(a[0]), "r"(a[1]), "r"(a[2]), "r"(a[3]), "r"(b[0]), "r"(b[1]));
}
__device__ __forceinline__ uint32_t h2pack(float a, float b) {
    __half2 t = __floats2half2_rn(a, b);
    return *reinterpret_cast<uint32_t*>(&t);
}
__device__ __forceinline__ float ex2f(float x) {
    float r;
    asm("ex2.approx.f32 %0, %1;" : "=f"(r) : "f"(x));
    return r;
}

// ---------------------------------------------------------------------------
// Kernel 1: fused LayerNorm (blocks 0..8191) + weight fp16 convert (rest)
// ---------------------------------------------------------------------------
#define LN_BLOCKS (M_ROWS / 8)
#define WP_BLOCKS (5 * 65536 / 256)

__global__ void __launch_bounds__(256) prep_kernel(const float* __restrict__ msa,
                                                   const float* __restrict__ gamma,
                                                   const float* __restrict__ beta,
                                                   const float* __restrict__ Wq,
                                                   const float* __restrict__ Wk,
                                                   const float* __restrict__ Wv,
                                                   const float* __restrict__ Wg,
                                                   const float* __restrict__ Wo)
{
    if (blockIdx.x >= LN_BLOCKS) {
        const int idx = (blockIdx.x - LN_BLOCKS) * 256 + threadIdx.x;
        const int w = idx >> 16;
        const int e = idx & 65535;
        const float* W = (w == 0) ? Wq : (w == 1) ? Wk : (w == 2) ? Wv : (w == 3) ? Wg : Wo;
        g_wt[idx] = __float2half_rn(W[e]);
        return;
    }
    const int lane = threadIdx.x & 31;
    const int row = blockIdx.x * 8 + (threadIdx.x >> 5);
    const float* rp = msa + (size_t)row * CS + lane * 8;

    const float4 v0 = *(const float4*)rp;
    const float4 v1 = *(const float4*)(rp + 4);
    float s1 = v0.x + v0.y + v0.z + v0.w + v1.x + v1.y + v1.z + v1.w;
    float s2 = v0.x * v0.x + v0.y * v0.y + v0.z * v0.z + v0.w * v0.w
             + v1.x * v1.x + v1.y * v1.y + v1.z * v1.z + v1.w * v1.w;
    #pragma unroll
    for (int o = 16; o > 0; o >>= 1) {
        s1 += __shfl_xor_sync(0xFFFFFFFFu, s1, o);
        s2 += __shfl_xor_sync(0xFFFFFFFFu, s2, o);
    }
    const float mu = s1 * (1.0f / CS);
    const float var = s2 * (1.0f / CS) - mu * mu;
    const float rstd = rsqrtf(var + 1e-5f);

    const float4 gm0 = *(const float4*)(gamma + lane * 8);
    const float4 gm1 = *(const float4*)(gamma + lane * 8 + 4);
    const float4 bt0 = *(const float4*)(beta + lane * 8);
    const float4 bt1 = *(const float4*)(beta + lane * 8 + 4);

    uint4 out;
    out.x = h2pack((v0.x - mu) * rstd * gm0.x + bt0.x, (v0.y - mu) * rstd * gm0.y + bt0.y);
    out.y = h2pack((v0.z - mu) * rstd * gm0.z + bt0.z, (v0.w - mu) * rstd * gm0.w + bt0.w);
    out.z = h2pack((v1.x - mu) * rstd * gm1.x + bt1.x, (v1.y - mu) * rstd * gm1.y + bt1.y);
    out.w = h2pack((v1.z - mu) * rstd * gm1.z + bt1.z, (v1.w - mu) * rstd * gm1.w + bt1.w);
    *(uint4*)(g_x + (size_t)row * CS + lane * 8) = out;
}

// ---------------------------------------------------------------------------
// HMMA GEMM: C[128,128] = A[128,256] @ W[256,128-slice], all fp16 single pass.
// 256 threads / 8 warps (2m x 4n), warp tile 64x32, BK=32 (8 iters),
// 4-stage cp.async, 2 CTAs/SM.
// mode: 0 = QSCALE + fp16, 4 = plain fp16, 2 = sigmoid(x+bias) fp16,
//       3 = x+bias fp32
// ---------------------------------------------------------------------------
#define GB_OFF  10240u
#define GSTAGE  18944u
#define GEMM_SMEM (4 * 18944)

__device__ __forceinline__ void gemm_load_stage(uint32_t st, int ks, int tid,
                                                int mblk, int nblk,
                                                const __half* __restrict__ aP,
                                                const __half* __restrict__ bH)
{
    #pragma unroll
    for (int j = 0; j < 2; j++) {
        const int u = tid + 256 * j;
        const int ar = u >> 2, ac = u & 3;
        cpa16(st + (uint32_t)(ar * 80 + ac * 16),
              aP + (size_t)(mblk * 128 + ar) * CS + ks * 32 + ac * 8);
    }
    #pragma unroll
    for (int j = 0; j < 2; j++) {
        const int u = tid + 256 * j;
        const int row = u >> 4, col = u & 15;
        cpa16(st + GB_OFF + (uint32_t)(row * 272 + col * 16),
              bH + (size_t)(ks * 32 + row) * CS + nblk * 128 + col * 8);
    }
}

__device__ __forceinline__ void gemm_body(const __half* __restrict__ aP,
                                          const __half* __restrict__ bH,
                                          const float* __restrict__ bias,
                                          float* __restrict__ Cf,
                                          __half* __restrict__ Ch,
                                          int mode, int mblk, int nblk)
{
    extern __shared__ unsigned char smem[];
    const uint32_t sb = smem_u32(smem);
    const int tid = threadIdx.x;
    const int lane = tid & 31;
    const int wid = tid >> 5;
    const int wm = wid >> 2;
    const int wn = wid & 3;

    float acc[4][4][4];
    #pragma unroll
    for (int i = 0; i < 4; i++)
        #pragma unroll
        for (int j = 0; j < 4; j++)
            #pragma unroll
            for (int q = 0; q < 4; q++) acc[i][j][q] = 0.f;

    gemm_load_stage(sb,              0, tid, mblk, nblk, aP, bH);
    cpa_commit();
    gemm_load_stage(sb + GSTAGE,     1, tid, mblk, nblk, aP, bH);
    cpa_commit();
    gemm_load_stage(sb + 2 * GSTAGE, 2, tid, mblk, nblk, aP, bH);
    cpa_commit();

    const uint32_t aRowSel = (uint32_t)((wm * 64 + (lane & 15)) * 80 + (lane >> 4) * 16);
    const uint32_t bColSel = (uint32_t)((wn * 32 + (lane >> 4) * 8) * 2);

    for (int ks = 0; ks < 8; ks++) {
        if (ks < 6) cpa_wait<2>(); else if (ks == 6) cpa_wait<1>(); else cpa_wait<0>();
        __syncthreads();
        if (ks + 3 < 8) {
            gemm_load_stage(sb + (uint32_t)((ks + 3) & 3) * GSTAGE, ks + 3, tid,
                            mblk, nblk, aP, bH);
            cpa_commit();
        }
        const uint32_t st = sb + (uint32_t)(ks & 3) * GSTAGE;

        #pragma unroll
        for (int kh = 0; kh < 2; kh++) {
            uint32_t Af[4][4], Bh[4][2];
            #pragma unroll
            for (int mf = 0; mf < 4; mf++)
                ldsm4(Af[mf], st + aRowSel + (uint32_t)(mf * 16 * 80 + kh * 32));
            const uint32_t bBase = st + GB_OFF +
                (uint32_t)((kh * 16 + (lane & 15)) * 272) + bColSel;
            #pragma unroll
            for (int g = 0; g < 2; g++) {
                uint32_t r[4];
                ldsm4t(r, bBase + (uint32_t)(g * 32));
                Bh[2 * g][0] = r[0]; Bh[2 * g][1] = r[1];
                Bh[2 * g + 1][0] = r[2]; Bh[2 * g + 1][1] = r[3];
            }
            #pragma unroll
            for (int mf = 0; mf < 4; mf++)
                #pragma unroll
                for (int nf = 0; nf < 4; nf++)
                    mma_f16(acc[mf][nf], Af[mf], Bh[nf]);
        }
    }

    // ---- epilogue ----
    const int r0 = mblk * 128 + wm * 64 + (lane >> 2);
    const int c0 = nblk * 128 + wn * 32 + (lane & 3) * 2;
    #pragma unroll
    for (int mf = 0; mf < 4; mf++) {
        #pragma unroll
        for (int nf = 0; nf < 4; nf++) {
            const int n = c0 + nf * 8;
            const int m = r0 + mf * 16;
            float v0 = acc[mf][nf][0], v1 = acc[mf][nf][1];
            float v2 = acc[mf][nf][2], v3 = acc[mf][nf][3];
            if (mode == 0) {
                *(uint32_t*)(Ch + (size_t)m * CS + n)       = h2pack(v0 * QSCALE, v1 * QSCALE);
                *(uint32_t*)(Ch + (size_t)(m + 8) * CS + n) = h2pack(v2 * QSCALE, v3 * QSCALE);
            } else if (mode == 4) {
                *(uint32_t*)(Ch + (size_t)m * CS + n)       = h2pack(v0, v1);
                *(uint32_t*)(Ch + (size_t)(m + 8) * CS + n) = h2pack(v2, v3);
            } else if (mode == 2) {
                const float b0 = __ldg(bias + n), b1 = __ldg(bias + n + 1);
                v0 = 1.f / (1.f + __expf(-(v0 + b0)));
                v1 = 1.f / (1.f + __expf(-(v1 + b1)));
                v2 = 1.f / (1.f + __expf(-(v2 + b0)));
                v3 = 1.f / (1.f + __expf(-(v3 + b1)));
                *(uint32_t*)(Ch + (size_t)m * CS + n)       = h2pack(v0, v1);
                *(uint32_t*)(Ch + (size_t)(m + 8) * CS + n) = h2pack(v2, v3);
            } else {
                const float b0 = __ldg(bias + n), b1 = __ldg(bias + n + 1);
                *(float2*)(Cf + (size_t)m * CS + n)       = make_float2(v0 + b0, v1 + b1);
                *(float2*)(Cf + (size_t)(m + 8) * CS + n) = make_float2(v2 + b0, v3 + b1);
            }
        }
    }
}

__global__ void __launch_bounds__(256, 2) gemm_proj(const float* __restrict__ bg)
{
    const int w = blockIdx.z;
    const __half* bh = g_wt + (size_t)w * 65536;
    if (w == 0)
        gemm_body(g_x, bh, nullptr, nullptr, g_q, 0, blockIdx.x, blockIdx.y);
    else if (w == 1)
        gemm_body(g_x, bh, nullptr, nullptr, g_k, 4, blockIdx.x, blockIdx.y);
    else if (w == 2)
        gemm_body(g_x, bh, nullptr, nullptr, g_v, 4, blockIdx.x, blockIdx.y);
    else
        gemm_body(g_x, bh, bg, nullptr, g_g, 2, blockIdx.x, blockIdx.y);
}

__global__ void __launch_bounds__(256, 2) gemm_outp(const float* __restrict__ bo,
                                                    float* __restrict__ out)
{
    gemm_body(g_gv, g_wt + (size_t)4 * 65536, bo, out, nullptr, 3,
              blockIdx.x, blockIdx.y);
}

// ---------------------------------------------------------------------------
// Kernel 3: tensor-core column attention (K and V single fp16).
// Grid (i, h) — round-13 proven order. Block = one (i, h). 256 thr = 8 warps,
// 32 queries/warp, 2 CTAs/SM. lsum via ones-MMA.
// ---------------------------------------------------------------------------
#define AQ_SZ   20480u
#define AST_OFF 20480u
#define AST_SZ  10240u
#define ATTN_SMEM (20480 + 3 * 10240)

__device__ __forceinline__ void load_kv_stage(uint32_t stbase, int i, int h, int t0, int tid)
{
    #pragma unroll
    for (int j = 0; j < 2; j++) {
        const int u = tid + 256 * j;
        const int arr = u >> 8;
        const int rem = u & 255;
        const int row = rem >> 2;
        const int c = rem & 3;
        const __half* base = (arr == 0) ? g_k : g_v;
        const __half* src = base + ((size_t)(t0 + row) * I_DIM + i) * CS + h * HD + c * 8;
        cpa16(stbase + (uint32_t)(arr * 5120 + row * 80 + c * 16), src);
    }
}

__global__ void __launch_bounds__(256, 2) attn_kernel()
{
    extern __shared__ unsigned char sm[];
    const uint32_t sb = smem_u32(sm);
    const int i = blockIdx.x;
    const int h = blockIdx.y;
    const int tid = threadIdx.x;
    const int lane = tid & 31;
    const int wq = tid >> 5;

    #pragma unroll
    for (int j = 0; j < 4; j++) {
        const int u = tid + 256 * j;
        const int row = u >> 2, c = u & 3;
        cpa16(sb + (uint32_t)(row * 80 + c * 16),
              g_q + ((size_t)row * I_DIM + i) * CS + h * HD + c * 8);
    }
    cpa_commit();
    load_kv_stage(sb + AST_OFF, i, h, 0, tid);
    cpa_commit();
    load_kv_stage(sb + AST_OFF + AST_SZ, i, h, 64, tid);
    cpa_commit();

    cpa_wait<2>();
    __syncthreads();

    uint32_t qf[2][2][4];
    #pragma unroll
    for (int mf = 0; mf < 2; mf++) {
        const uint32_t qrow = (uint32_t)((wq * 32 + mf * 16 + (lane & 15)) * 80
                                         + (lane >> 4) * 16);
        ldsm4(qf[mf][0], sb + qrow);
        ldsm4(qf[mf][1], sb + qrow + 32u);
    }

    float o[2][4][4];
    #pragma unroll
    for (int mf = 0; mf < 2; mf++)
        #pragma unroll
        for (int nf = 0; nf < 4; nf++)
            #pragma unroll
            for (int q = 0; q < 4; q++) o[mf][nf][q] = 0.f;
    float lacc[2][4];
    #pragma unroll
    for (int mf = 0; mf < 2; mf++)
        #pragma unroll
        for (int q = 0; q < 4; q++) lacc[mf][q] = 0.f;

    const uint32_t ones[2] = {0x3C003C00u, 0x3C003C00u};

    const uint32_t kaddr = (uint32_t)((((lane >> 4) * 8) + (lane & 7)) * 80 + ((lane >> 3) & 1) * 16);
    const uint32_t vaddr = (uint32_t)(((((lane >> 3) & 1) * 8) + (lane & 7)) * 80 + (lane >> 4) * 16);

    for (int kt = 0; kt < 4; kt++) {
        if (kt < 3) cpa_wait<1>(); else cpa_wait<0>();
        __syncthreads();
        if (kt + 2 < 4) {
            load_kv_stage(sb + AST_OFF + (uint32_t)((kt + 2) % 3) * AST_SZ, i, h, (kt + 2) * 64, tid);
            cpa_commit();
        }
        const uint32_t st = sb + AST_OFF + (uint32_t)(kt % 3) * AST_SZ;

        #pragma unroll
        for (int ch = 0; ch < 4; ch++) {
            const uint32_t roff = (uint32_t)(ch * 16 * 80);

            float s[2][2][4];
            #pragma unroll
            for (int nt = 0; nt < 2; nt++)
                #pragma unroll
                for (int mf = 0; mf < 2; mf++)
                    #pragma unroll
                    for (int q = 0; q < 4; q++) s[nt][mf][q] = 0.f;

            #pragma unroll
            for (int ks = 0; ks < 2; ks++) {
                uint32_t bh[2][2], r[4];
                ldsm4(r, st + roff + kaddr + (uint32_t)(ks * 32));
                bh[0][0] = r[0]; bh[0][1] = r[1]; bh[1][0] = r[2]; bh[1][1] = r[3];
                #pragma unroll
                for (int nt = 0; nt < 2; nt++)
                    #pragma unroll
                    for (int mf = 0; mf < 2; mf++)
                        mma_f16(s[nt][mf], qf[mf][ks], bh[nt]);
            }

            uint32_t vhf[4][2];
            #pragma unroll
            for (int np2 = 0; np2 < 2; np2++) {
                uint32_t r[4];
                ldsm4t(r, st + 5120u + roff + vaddr + (uint32_t)(np2 * 32));
                vhf[2 * np2][0] = r[0]; vhf[2 * np2][1] = r[1];
                vhf[2 * np2 + 1][0] = r[2]; vhf[2 * np2 + 1][1] = r[3];
            }

            #pragma unroll
            for (int mf = 0; mf < 2; mf++) {
                float* sa = s[0][mf];
                float* sc = s[1][mf];
                sa[0] = ex2f(sa[0]); sa[1] = ex2f(sa[1]);
                sa[2] = ex2f(sa[2]); sa[3] = ex2f(sa[3]);
                sc[0] = ex2f(sc[0]); sc[1] = ex2f(sc[1]);
                sc[2] = ex2f(sc[2]); sc[3] = ex2f(sc[3]);
                uint32_t pA[4];
                pA[0] = h2pack(sa[0], sa[1]);
                pA[1] = h2pack(sa[2], sa[3]);
                pA[2] = h2pack(sc[0], sc[1]);
                pA[3] = h2pack(sc[2], sc[3]);
                mma_f16(lacc[mf], pA, ones);
                #pragma unroll
                for (int nf = 0; nf < 4; nf++)
                    mma_f16(o[mf][nf], pA, vhf[nf]);
            }
        }
    }

    // ---- epilogue: lsum from ones-MMA acc, gate, store ----
    #pragma unroll
    for (int mf = 0; mf < 2; mf++) {
        const float inv0 = 1.f / lacc[mf][0];
        const float inv1 = 1.f / lacc[mf][2];

        const int row = wq * 32 + mf * 16 + (lane >> 2);
        const size_t M0 = ((size_t)row * I_DIM + i) * CS + h * HD;
        const size_t M1 = ((size_t)(row + 8) * I_DIM + i) * CS + h * HD;
        #pragma unroll
        for (int nf = 0; nf < 4; nf++) {
            const int col = nf * 8 + (lane & 3) * 2;
            const float2 g0 = __half22float2(*(const __half2*)(g_g + M0 + col));
            const float2 g1 = __half22float2(*(const __half2*)(g_g + M1 + col));
            *(uint32_t*)(g_gv + M0 + col) =
                h2pack(o[mf][nf][0] * inv0 * g0.x, o[mf][nf][1] * inv0 * g0.y);
            *(uint32_t*)(g_gv + M1 + col) =
                h2pack(o[mf][nf][2] * inv1 * g1.x, o[mf][nf][3] * inv1 * g1.y);
        }
    }
}

// ---------------------------------------------------------------------------
// Launch
// ---------------------------------------------------------------------------
extern "C" void kernel_launch(void* const* d_in, const int* in_sizes, int n_in,
                              void* d_out, int out_size)
{
    const float* msa   = (const float*)d_in[0];
    const float* gamma = (const float*)d_in[1];
    const float* beta  = (const float*)d_in[2];
    const float* Wq    = (const float*)d_in[3];
    const float* Wk    = (const float*)d_in[4];
    const float* Wv    = (const float*)d_in[5];
    const float* Wg    = (const float*)d_in[6];
    const float* bg    = (const float*)d_in[7];
    const float* Wo    = (const float*)d_in[8];
    const float* bo    = (const float*)d_in[9];
    float* out = (float*)d_out;

    cudaFuncSetAttribute(gemm_proj, cudaFuncAttributeMaxDynamicSharedMemorySize, GEMM_SMEM);
    cudaFuncSetAttribute(gemm_outp, cudaFuncAttributeMaxDynamicSharedMemorySize, GEMM_SMEM);
    cudaFuncSetAttribute(attn_kernel, cudaFuncAttributeMaxDynamicSharedMemorySize, ATTN_SMEM);

    prep_kernel<<<LN_BLOCKS + WP_BLOCKS, 256>>>(msa, gamma, beta, Wq, Wk, Wv, Wg, Wo);

    gemm_proj<<<dim3(MBLOCKS, 2, 4), 256, GEMM_SMEM>>>(bg);

    attn_kernel<<<dim3(I_DIM, NH), 256, ATTN_SMEM>>>();

    gemm_outp<<<dim3(MBLOCKS, 2), 256, GEMM_SMEM>>>(bo, out);
}